// round 1
// baseline (speedup 1.0000x reference)
#include <cuda_runtime.h>

// Problem constants
#define CB   128          // channels
#define SX   48           // spatial extent per axis
#define SS   110592       // 48^3
#define NB   2            // batch
#define NT   221184       // NB * SS tokens
#define TSEQ 48           // sequence length per axis
#define LD   132          // padded row stride for 48x128 / 64x128 smem tiles
#define WLD  132          // padded row stride for transposed weight tile

// Scratch (allocation-free rule: device globals)
__device__ float g_xe[NT * CB];   // pos-embedded input, channels-last
__device__ float g_y[NT * CB];    // residual + attention accumulator, channels-last

// ---------------------------------------------------------------------------
// prep: xe = 2*x + px + py + pz, transpose (B,C,S) -> (token, C)
// ---------------------------------------------------------------------------
__global__ __launch_bounds__(256) void prep_kernel(
    const float* __restrict__ x,
    const float* __restrict__ px,
    const float* __restrict__ py,
    const float* __restrict__ pz)
{
    __shared__ float tile[64][129];
    int base = blockIdx.x * 64;          // token base (tile never crosses b: SS%64==0)
    int b    = base / SS;
    int sp0  = base % SS;

    for (int e = threadIdx.x; e < 64 * 128; e += 256) {
        int c = e >> 6;
        int s = e & 63;
        int spatial = sp0 + s;
        int zi = spatial % 48;
        int yi = (spatial / 48) % 48;
        int xi = spatial / 2304;
        float v = 2.0f * x[b * CB * SS + c * SS + spatial]
                + px[c * 48 + xi] + py[c * 48 + yi] + pz[c * 48 + zi];
        tile[s][c] = v;
    }
    __syncthreads();
    for (int e = threadIdx.x; e < 64 * 128; e += 256) {
        int s = e >> 7;
        int c = e & 127;
        g_xe[(base + s) * 128 + c] = tile[s][c];
    }
}

// ---------------------------------------------------------------------------
// Shared GEMM helpers (A and W^T both in smem; conflict-free float4 loads)
// ---------------------------------------------------------------------------
__device__ __forceinline__ void stage_w(float* wT, const float* __restrict__ w)
{
    // wT[d][c] = w[c][d], padded rows (WLD)
    for (int e = threadIdx.x; e < 128 * 128; e += 256) {
        int c = e >> 7;
        int d = e & 127;
        wT[d * WLD + c] = w[e];
    }
}

// out[48][128] = A[48][128] @ W^T   (A rows LD, out rows LD, wT rows WLD)
__device__ __forceinline__ void gemm48(float* __restrict__ outp,
                                       const float* __restrict__ A,
                                       const float* __restrict__ wT)
{
    int tx = threadIdx.x & 31;
    int ty = threadIdx.x >> 5;
    int r0 = ty * 6;
    int c0 = tx * 4;
    float acc[6][4];
#pragma unroll
    for (int i = 0; i < 6; i++)
#pragma unroll
        for (int j = 0; j < 4; j++) acc[i][j] = 0.f;

    for (int d = 0; d < 128; d += 4) {
        float4 w0 = *(const float4*)(wT + (d + 0) * WLD + c0);
        float4 w1 = *(const float4*)(wT + (d + 1) * WLD + c0);
        float4 w2 = *(const float4*)(wT + (d + 2) * WLD + c0);
        float4 w3 = *(const float4*)(wT + (d + 3) * WLD + c0);
#pragma unroll
        for (int i = 0; i < 6; i++) {
            float4 a = *(const float4*)(A + (r0 + i) * LD + d);
            acc[i][0] += a.x * w0.x + a.y * w1.x + a.z * w2.x + a.w * w3.x;
            acc[i][1] += a.x * w0.y + a.y * w1.y + a.z * w2.y + a.w * w3.y;
            acc[i][2] += a.x * w0.z + a.y * w1.z + a.z * w2.z + a.w * w3.z;
            acc[i][3] += a.x * w0.w + a.y * w1.w + a.z * w2.w + a.w * w3.w;
        }
    }
#pragma unroll
    for (int i = 0; i < 6; i++)
        *(float4*)(outp + (r0 + i) * LD + c0) =
            make_float4(acc[i][0], acc[i][1], acc[i][2], acc[i][3]);
}

// ---------------------------------------------------------------------------
// Axis attention: one CTA per sequence (4608 per axis)
// ---------------------------------------------------------------------------
__global__ __launch_bounds__(256) void attn_kernel(
    const float* __restrict__ wq,
    const float* __restrict__ wkv,
    const float* __restrict__ wout,
    const float* __restrict__ bout,
    int axis)
{
    extern __shared__ float sm[];
    float* tileX = sm;                    // 48*LD  (kept intact for residual)
    float* q     = tileX + TSEQ * LD;     // 48*LD
    float* kk    = q + TSEQ * LD;         // 48*LD
    float* vv    = kk + TSEQ * LD;        // 48*LD
    float* o     = vv + TSEQ * LD;        // 48*LD
    float* wT    = o + TSEQ * LD;         // 128*WLD
    float* sc    = wT + 128 * WLD;        // 48*48

    int seq = blockIdx.x;
    int b   = seq / 2304;
    int rr  = seq % 2304;
    int o1  = rr / 48, o2 = rr % 48;
    int base, stride;
    if (axis == 0)      { base = b * SS + o1 * 48 + o2;        stride = 2304; }
    else if (axis == 1) { base = b * SS + o1 * 2304 + o2;      stride = 48;   }
    else                { base = b * SS + o1 * 2304 + o2 * 48; stride = 1;    }

    int tid = threadIdx.x;

    // load sequence tile (coalesced: 512B per token row)
    for (int e = tid; e < TSEQ * 128; e += 256) {
        int t = e >> 7, c = e & 127;
        tileX[t * LD + c] = g_xe[(base + t * stride) * 128 + c];
    }
    stage_w(wT, wq);
    __syncthreads();
    gemm48(q, tileX, wT);
    __syncthreads();
    stage_w(wT, wkv);                 // k = first 128 rows of wkv
    __syncthreads();
    gemm48(kk, tileX, wT);
    __syncthreads();
    stage_w(wT, wkv + 128 * 128);     // v = last 128 rows
    __syncthreads();
    gemm48(vv, tileX, wT);
    __syncthreads();

    int lane = tid & 31, warp = tid >> 5;

    for (int h = 0; h < 8; h++) {
        int hb = h * 16;
        // scores: 16x16 thread grid, 3x3 micro-tile, scale = e^-0.5 = 0.25
        {
            int j0 = (tid & 15) * 3;
            int i0 = (tid >> 4) * 3;
            float a00 = 0, a01 = 0, a02 = 0, a10 = 0, a11 = 0, a12 = 0,
                  a20 = 0, a21 = 0, a22 = 0;
#pragma unroll
            for (int d = 0; d < 16; d++) {
                float q0 = q[(i0 + 0) * LD + hb + d];
                float q1 = q[(i0 + 1) * LD + hb + d];
                float q2 = q[(i0 + 2) * LD + hb + d];
                float k0 = kk[(j0 + 0) * LD + hb + d];
                float k1 = kk[(j0 + 1) * LD + hb + d];
                float k2 = kk[(j0 + 2) * LD + hb + d];
                a00 += q0 * k0; a01 += q0 * k1; a02 += q0 * k2;
                a10 += q1 * k0; a11 += q1 * k1; a12 += q1 * k2;
                a20 += q2 * k0; a21 += q2 * k1; a22 += q2 * k2;
            }
            sc[(i0 + 0) * 48 + j0 + 0] = a00 * 0.25f;
            sc[(i0 + 0) * 48 + j0 + 1] = a01 * 0.25f;
            sc[(i0 + 0) * 48 + j0 + 2] = a02 * 0.25f;
            sc[(i0 + 1) * 48 + j0 + 0] = a10 * 0.25f;
            sc[(i0 + 1) * 48 + j0 + 1] = a11 * 0.25f;
            sc[(i0 + 1) * 48 + j0 + 2] = a12 * 0.25f;
            sc[(i0 + 2) * 48 + j0 + 0] = a20 * 0.25f;
            sc[(i0 + 2) * 48 + j0 + 1] = a21 * 0.25f;
            sc[(i0 + 2) * 48 + j0 + 2] = a22 * 0.25f;
        }
        __syncthreads();
        // softmax rows: warp per row group
        for (int i = warp; i < 48; i += 8) {
            float v0 = sc[i * 48 + lane];
            float v1 = (lane < 16) ? sc[i * 48 + 32 + lane] : -1e30f;
            float m = fmaxf(v0, v1);
            for (int off = 16; off; off >>= 1)
                m = fmaxf(m, __shfl_xor_sync(0xffffffffu, m, off));
            float e0 = __expf(v0 - m);
            float e1 = (lane < 16) ? __expf(v1 - m) : 0.f;
            float s = e0 + e1;
            for (int off = 16; off; off >>= 1)
                s += __shfl_xor_sync(0xffffffffu, s, off);
            float inv = 1.f / s;
            sc[i * 48 + lane] = e0 * inv;
            if (lane < 16) sc[i * 48 + 32 + lane] = e1 * inv;
        }
        __syncthreads();
        // AV: thread -> (d = tid&15, rows i0, i0+16, i0+32)
        {
            int d  = tid & 15;
            int i0 = tid >> 4;
            float a0 = 0, a1 = 0, a2 = 0;
            for (int j = 0; j < 48; j++) {
                float vj = vv[j * LD + hb + d];
                a0 += sc[(i0 + 0)  * 48 + j] * vj;
                a1 += sc[(i0 + 16) * 48 + j] * vj;
                a2 += sc[(i0 + 32) * 48 + j] * vj;
            }
            o[(i0 + 0)  * LD + hb + d] = a0;
            o[(i0 + 16) * LD + hb + d] = a1;
            o[(i0 + 32) * LD + hb + d] = a2;
        }
        __syncthreads();
    }

    // output projection: reuse q as scratch (no longer needed)
    stage_w(wT, wout);
    __syncthreads();
    gemm48(q, o, wT);
    __syncthreads();

    // epilogue: bias + residual / accumulate (coalesced: c fast)
    for (int e = tid; e < TSEQ * 128; e += 256) {
        int t = e >> 7, c = e & 127;
        float val = q[t * LD + c] + bout[c];
        int g = (base + t * stride) * 128 + c;
        if (axis == 0) g_y[g] = tileX[t * LD + c] + val;
        else           g_y[g] += val;
    }
}

// ---------------------------------------------------------------------------
// MLP + double LayerNorm, final transpose back to (B,C,X,Y,Z)
// ---------------------------------------------------------------------------
__device__ __forceinline__ void ln_rows64(float* buf,
                                          const float* __restrict__ g,
                                          const float* __restrict__ bb)
{
    int warp = threadIdx.x >> 5, lane = threadIdx.x & 31;
    for (int r = warp; r < 64; r += 8) {
        float vals[4];
        float s = 0.f, s2 = 0.f;
#pragma unroll
        for (int cc = 0; cc < 4; cc++) {
            float v = buf[r * LD + lane + cc * 32];
            vals[cc] = v; s += v; s2 += v * v;
        }
        for (int off = 16; off; off >>= 1) {
            s  += __shfl_xor_sync(0xffffffffu, s,  off);
            s2 += __shfl_xor_sync(0xffffffffu, s2, off);
        }
        float m   = s * (1.f / 128.f);
        float var = s2 * (1.f / 128.f) - m * m;
        float inv = rsqrtf(var + 1e-5f);
#pragma unroll
        for (int cc = 0; cc < 4; cc++) {
            int c = lane + cc * 32;
            buf[r * LD + c] = (vals[cc] - m) * inv * g[c] + bb[c];
        }
    }
}

// h[64][128] = relu(A @ W^T + bias)
__device__ __forceinline__ void gemm64_relu(float* __restrict__ outp,
                                            const float* __restrict__ A,
                                            const float* __restrict__ wT,
                                            const float* __restrict__ bias)
{
    int tx = threadIdx.x & 31, ty = threadIdx.x >> 5;
    int r0 = ty * 8, c0 = tx * 4;
    float acc[8][4];
#pragma unroll
    for (int i = 0; i < 8; i++)
#pragma unroll
        for (int j = 0; j < 4; j++) acc[i][j] = 0.f;

    for (int d = 0; d < 128; d += 4) {
        float4 w0 = *(const float4*)(wT + (d + 0) * WLD + c0);
        float4 w1 = *(const float4*)(wT + (d + 1) * WLD + c0);
        float4 w2 = *(const float4*)(wT + (d + 2) * WLD + c0);
        float4 w3 = *(const float4*)(wT + (d + 3) * WLD + c0);
#pragma unroll
        for (int i = 0; i < 8; i++) {
            float4 a = *(const float4*)(A + (r0 + i) * LD + d);
            acc[i][0] += a.x * w0.x + a.y * w1.x + a.z * w2.x + a.w * w3.x;
            acc[i][1] += a.x * w0.y + a.y * w1.y + a.z * w2.y + a.w * w3.y;
            acc[i][2] += a.x * w0.z + a.y * w1.z + a.z * w2.z + a.w * w3.z;
            acc[i][3] += a.x * w0.w + a.y * w1.w + a.z * w2.w + a.w * w3.w;
        }
    }
#pragma unroll
    for (int i = 0; i < 8; i++)
#pragma unroll
        for (int j = 0; j < 4; j++) {
            float v = acc[i][j] + bias[c0 + j];
            outp[(r0 + i) * LD + c0 + j] = fmaxf(v, 0.f);
        }
}

// res[64][128] += A @ W^T + bias   (res also holds the residual)
__device__ __forceinline__ void gemm64_res(float* __restrict__ res,
                                           const float* __restrict__ A,
                                           const float* __restrict__ wT,
                                           const float* __restrict__ bias)
{
    int tx = threadIdx.x & 31, ty = threadIdx.x >> 5;
    int r0 = ty * 8, c0 = tx * 4;
    float acc[8][4];
#pragma unroll
    for (int i = 0; i < 8; i++)
#pragma unroll
        for (int j = 0; j < 4; j++) acc[i][j] = 0.f;

    for (int d = 0; d < 128; d += 4) {
        float4 w0 = *(const float4*)(wT + (d + 0) * WLD + c0);
        float4 w1 = *(const float4*)(wT + (d + 1) * WLD + c0);
        float4 w2 = *(const float4*)(wT + (d + 2) * WLD + c0);
        float4 w3 = *(const float4*)(wT + (d + 3) * WLD + c0);
#pragma unroll
        for (int i = 0; i < 8; i++) {
            float4 a = *(const float4*)(A + (r0 + i) * LD + d);
            acc[i][0] += a.x * w0.x + a.y * w1.x + a.z * w2.x + a.w * w3.x;
            acc[i][1] += a.x * w0.y + a.y * w1.y + a.z * w2.y + a.w * w3.y;
            acc[i][2] += a.x * w0.z + a.y * w1.z + a.z * w2.z + a.w * w3.z;
            acc[i][3] += a.x * w0.w + a.y * w1.w + a.z * w2.w + a.w * w3.w;
        }
    }
#pragma unroll
    for (int i = 0; i < 8; i++)
#pragma unroll
        for (int j = 0; j < 4; j++) {
            int idx = (r0 + i) * LD + c0 + j;
            res[idx] = acc[i][j] + bias[c0 + j] + res[idx];
        }
}

__global__ __launch_bounds__(256) void mlp_kernel(
    const float* __restrict__ ln_g, const float* __restrict__ ln_b,
    const float* __restrict__ w1,   const float* __restrict__ b1,
    const float* __restrict__ w2,   const float* __restrict__ b2,
    float* __restrict__ out)
{
    extern __shared__ float sm[];
    float* xln = sm;                  // 64*LD
    float* h   = xln + 64 * LD;       // 64*LD
    float* wT  = h + 64 * LD;         // 128*WLD

    int base = blockIdx.x * 64;
    int tid  = threadIdx.x;

    for (int e = tid; e < 64 * 128; e += 256) {
        int t = e >> 7, c = e & 127;
        xln[t * LD + c] = g_y[(base + t) * 128 + c];
    }
    __syncthreads();
    ln_rows64(xln, ln_g, ln_b);           // first LN (in place)
    stage_w(wT, w1);
    __syncthreads();
    gemm64_relu(h, xln, wT, b1);
    __syncthreads();
    stage_w(wT, w2);
    __syncthreads();
    gemm64_res(xln, h, wT, b2);           // xln = h@w2^T + b2 + res
    __syncthreads();
    ln_rows64(xln, ln_g, ln_b);           // second LN (same weights)
    __syncthreads();

    // write transposed output (B,C,X,Y,Z), coalesced over spatial
    int b   = base / SS;
    int sp0 = base % SS;
    for (int e = tid; e < 64 * 128; e += 256) {
        int c = e >> 6;
        int s = e & 63;
        out[b * CB * SS + c * SS + sp0 + s] = xln[s * LD + c];
    }
}

// ---------------------------------------------------------------------------
// launch
// ---------------------------------------------------------------------------
extern "C" void kernel_launch(void* const* d_in, const int* in_sizes, int n_in,
                              void* d_out, int out_size)
{
    (void)in_sizes; (void)n_in; (void)out_size;
    const float* x    = (const float*)d_in[0];
    const float* px   = (const float*)d_in[1];
    const float* py   = (const float*)d_in[2];
    const float* pz   = (const float*)d_in[3];
    const float* ln_g = (const float*)d_in[16];
    const float* ln_b = (const float*)d_in[17];
    const float* w1   = (const float*)d_in[18];
    const float* b1   = (const float*)d_in[19];
    const float* w2   = (const float*)d_in[20];
    const float* b2   = (const float*)d_in[21];

    const int ATTN_SMEM = (5 * TSEQ * LD + 128 * WLD + 48 * 48) * (int)sizeof(float); // 203520
    const int MLP_SMEM  = (2 * 64 * LD + 128 * WLD) * (int)sizeof(float);             // 135168

    // Sticky attributes; set on the (non-captured) correctness call, ignore errors later.
    cudaFuncSetAttribute((const void*)attn_kernel,
                         cudaFuncAttributeMaxDynamicSharedMemorySize, ATTN_SMEM);
    cudaFuncSetAttribute((const void*)mlp_kernel,
                         cudaFuncAttributeMaxDynamicSharedMemorySize, MLP_SMEM);

    prep_kernel<<<NT / 64, 256>>>(x, px, py, pz);

    for (int axis = 0; axis < 3; axis++) {
        const float* wq   = (const float*)d_in[4 + 4 * axis];
        const float* wkv  = (const float*)d_in[5 + 4 * axis];
        const float* wout = (const float*)d_in[6 + 4 * axis];
        const float* bout = (const float*)d_in[7 + 4 * axis];
        attn_kernel<<<4608, 256, ATTN_SMEM>>>(wq, wkv, wout, bout, axis);
    }

    mlp_kernel<<<NT / 64, 256, MLP_SMEM>>>(ln_g, ln_b, w1, b1, w2, b2, (float*)d_out);
}

// round 2
// speedup vs baseline: 1.0480x; 1.0480x over previous
#include <cuda_runtime.h>

// Problem constants
#define CB   128          // channels
#define SX   48           // spatial extent per axis
#define SS   110592       // 48^3
#define NB   2            // batch
#define NT   221184       // NB * SS tokens
#define TSEQ 48           // sequence length per axis
#define LD   132          // padded row stride for 48x128 / 64x128 smem tiles
#define WLD  132          // padded row stride for transposed weight tile

// Scratch (allocation-free rule: device globals)
__device__ float g_xe[NT * CB];   // pos-embedded input, channels-last
__device__ float g_y[NT * CB];    // residual + attention accumulator, channels-last

// ---------------------------------------------------------------------------
// prep: xe = 2*x + px + py + pz, transpose (B,C,S) -> (token, C)
// ---------------------------------------------------------------------------
__global__ __launch_bounds__(256) void prep_kernel(
    const float* __restrict__ x,
    const float* __restrict__ px,
    const float* __restrict__ py,
    const float* __restrict__ pz)
{
    __shared__ float tile[64][129];
    int base = blockIdx.x * 64;          // token base (tile never crosses b: SS%64==0)
    int b    = base / SS;
    int sp0  = base % SS;

    for (int e = threadIdx.x; e < 64 * 128; e += 256) {
        int c = e >> 6;
        int s = e & 63;
        int spatial = sp0 + s;
        int zi = spatial % 48;
        int yi = (spatial / 48) % 48;
        int xi = spatial / 2304;
        float v = 2.0f * x[b * CB * SS + c * SS + spatial]
                + px[c * 48 + xi] + py[c * 48 + yi] + pz[c * 48 + zi];
        tile[s][c] = v;
    }
    __syncthreads();
    for (int e = threadIdx.x; e < 64 * 128; e += 256) {
        int s = e >> 7;
        int c = e & 127;
        g_xe[(base + s) * 128 + c] = tile[s][c];
    }
}

// ---------------------------------------------------------------------------
// Shared GEMM helpers (A and W^T both in smem; conflict-free float4 loads)
// ---------------------------------------------------------------------------
__device__ __forceinline__ void stage_w(float* wT, const float* __restrict__ w)
{
    // wT[d][c] = w[c][d], padded rows (WLD)
    for (int e = threadIdx.x; e < 128 * 128; e += 256) {
        int c = e >> 7;
        int d = e & 127;
        wT[d * WLD + c] = w[e];
    }
}

// out[48][128] = A[48][128] @ W^T   (A rows LD, out rows LD, wT rows WLD)
__device__ __forceinline__ void gemm48(float* __restrict__ outp,
                                       const float* __restrict__ A,
                                       const float* __restrict__ wT)
{
    int tx = threadIdx.x & 31;
    int ty = threadIdx.x >> 5;
    int r0 = ty * 6;
    int c0 = tx * 4;
    float acc[6][4];
#pragma unroll
    for (int i = 0; i < 6; i++)
#pragma unroll
        for (int j = 0; j < 4; j++) acc[i][j] = 0.f;

    for (int d = 0; d < 128; d += 4) {
        float4 w0 = *(const float4*)(wT + (d + 0) * WLD + c0);
        float4 w1 = *(const float4*)(wT + (d + 1) * WLD + c0);
        float4 w2 = *(const float4*)(wT + (d + 2) * WLD + c0);
        float4 w3 = *(const float4*)(wT + (d + 3) * WLD + c0);
#pragma unroll
        for (int i = 0; i < 6; i++) {
            float4 a = *(const float4*)(A + (r0 + i) * LD + d);
            acc[i][0] += a.x * w0.x + a.y * w1.x + a.z * w2.x + a.w * w3.x;
            acc[i][1] += a.x * w0.y + a.y * w1.y + a.z * w2.y + a.w * w3.y;
            acc[i][2] += a.x * w0.z + a.y * w1.z + a.z * w2.z + a.w * w3.z;
            acc[i][3] += a.x * w0.w + a.y * w1.w + a.z * w2.w + a.w * w3.w;
        }
    }
#pragma unroll
    for (int i = 0; i < 6; i++)
        *(float4*)(outp + (r0 + i) * LD + c0) =
            make_float4(acc[i][0], acc[i][1], acc[i][2], acc[i][3]);
}

// ---------------------------------------------------------------------------
// Axis attention: one CTA per sequence (4608 per axis)
// ---------------------------------------------------------------------------
__global__ __launch_bounds__(256) void attn_kernel(
    const float* __restrict__ wq,
    const float* __restrict__ wkv,
    const float* __restrict__ wout,
    const float* __restrict__ bout,
    int axis)
{
    extern __shared__ float sm[];
    float* tileX = sm;                    // 48*LD  (kept intact for residual)
    float* q     = tileX + TSEQ * LD;     // 48*LD
    float* kk    = q + TSEQ * LD;         // 48*LD
    float* vv    = kk + TSEQ * LD;        // 48*LD
    float* o     = vv + TSEQ * LD;        // 48*LD
    float* wT    = o + TSEQ * LD;         // 128*WLD
    float* sc    = wT + 128 * WLD;        // 48*48

    int seq = blockIdx.x;
    int b   = seq / 2304;
    int rr  = seq % 2304;
    int o1  = rr / 48, o2 = rr % 48;
    int base, stride;
    if (axis == 0)      { base = b * SS + o1 * 48 + o2;        stride = 2304; }
    else if (axis == 1) { base = b * SS + o1 * 2304 + o2;      stride = 48;   }
    else                { base = b * SS + o1 * 2304 + o2 * 48; stride = 1;    }

    int tid = threadIdx.x;

    // load sequence tile (coalesced: 512B per token row)
    for (int e = tid; e < TSEQ * 128; e += 256) {
        int t = e >> 7, c = e & 127;
        tileX[t * LD + c] = g_xe[(base + t * stride) * 128 + c];
    }
    stage_w(wT, wq);
    __syncthreads();
    gemm48(q, tileX, wT);
    __syncthreads();
    stage_w(wT, wkv);                 // k = first 128 rows of wkv
    __syncthreads();
    gemm48(kk, tileX, wT);
    __syncthreads();
    stage_w(wT, wkv + 128 * 128);     // v = last 128 rows
    __syncthreads();
    gemm48(vv, tileX, wT);
    __syncthreads();

    int lane = tid & 31, warp = tid >> 5;

    for (int h = 0; h < 8; h++) {
        int hb = h * 16;
        // scores: 16x16 thread grid, 3x3 micro-tile, scale = e^-0.5 = 0.25
        {
            int j0 = (tid & 15) * 3;
            int i0 = (tid >> 4) * 3;
            float a00 = 0, a01 = 0, a02 = 0, a10 = 0, a11 = 0, a12 = 0,
                  a20 = 0, a21 = 0, a22 = 0;
#pragma unroll
            for (int d = 0; d < 16; d++) {
                float q0 = q[(i0 + 0) * LD + hb + d];
                float q1 = q[(i0 + 1) * LD + hb + d];
                float q2 = q[(i0 + 2) * LD + hb + d];
                float k0 = kk[(j0 + 0) * LD + hb + d];
                float k1 = kk[(j0 + 1) * LD + hb + d];
                float k2 = kk[(j0 + 2) * LD + hb + d];
                a00 += q0 * k0; a01 += q0 * k1; a02 += q0 * k2;
                a10 += q1 * k0; a11 += q1 * k1; a12 += q1 * k2;
                a20 += q2 * k0; a21 += q2 * k1; a22 += q2 * k2;
            }
            sc[(i0 + 0) * 48 + j0 + 0] = a00 * 0.25f;
            sc[(i0 + 0) * 48 + j0 + 1] = a01 * 0.25f;
            sc[(i0 + 0) * 48 + j0 + 2] = a02 * 0.25f;
            sc[(i0 + 1) * 48 + j0 + 0] = a10 * 0.25f;
            sc[(i0 + 1) * 48 + j0 + 1] = a11 * 0.25f;
            sc[(i0 + 1) * 48 + j0 + 2] = a12 * 0.25f;
            sc[(i0 + 2) * 48 + j0 + 0] = a20 * 0.25f;
            sc[(i0 + 2) * 48 + j0 + 1] = a21 * 0.25f;
            sc[(i0 + 2) * 48 + j0 + 2] = a22 * 0.25f;
        }
        __syncthreads();
        // softmax rows: warp per row group
        for (int i = warp; i < 48; i += 8) {
            float v0 = sc[i * 48 + lane];
            float v1 = (lane < 16) ? sc[i * 48 + 32 + lane] : -1e30f;
            float m = fmaxf(v0, v1);
            for (int off = 16; off; off >>= 1)
                m = fmaxf(m, __shfl_xor_sync(0xffffffffu, m, off));
            float e0 = __expf(v0 - m);
            float e1 = (lane < 16) ? __expf(v1 - m) : 0.f;
            float s = e0 + e1;
            for (int off = 16; off; off >>= 1)
                s += __shfl_xor_sync(0xffffffffu, s, off);
            float inv = 1.f / s;
            sc[i * 48 + lane] = e0 * inv;
            if (lane < 16) sc[i * 48 + 32 + lane] = e1 * inv;
        }
        __syncthreads();
        // AV: thread -> (d = tid&15, rows i0, i0+16, i0+32)
        {
            int d  = tid & 15;
            int i0 = tid >> 4;
            float a0 = 0, a1 = 0, a2 = 0;
            for (int j = 0; j < 48; j++) {
                float vj = vv[j * LD + hb + d];
                a0 += sc[(i0 + 0)  * 48 + j] * vj;
                a1 += sc[(i0 + 16) * 48 + j] * vj;
                a2 += sc[(i0 + 32) * 48 + j] * vj;
            }
            o[(i0 + 0)  * LD + hb + d] = a0;
            o[(i0 + 16) * LD + hb + d] = a1;
            o[(i0 + 32) * LD + hb + d] = a2;
        }
        __syncthreads();
    }

    // output projection: reuse q as scratch (no longer needed)
    stage_w(wT, wout);
    __syncthreads();
    gemm48(q, o, wT);
    __syncthreads();

    // epilogue: bias + residual / accumulate (coalesced: c fast)
    for (int e = tid; e < TSEQ * 128; e += 256) {
        int t = e >> 7, c = e & 127;
        float val = q[t * LD + c] + bout[c];
        int g = (base + t * stride) * 128 + c;
        if (axis == 0) g_y[g] = tileX[t * LD + c] + val;
        else           g_y[g] += val;
    }
}

// ---------------------------------------------------------------------------
// MLP + double LayerNorm, final transpose back to (B,C,X,Y,Z)
// ---------------------------------------------------------------------------
__device__ __forceinline__ void ln_rows64(float* buf,
                                          const float* __restrict__ g,
                                          const float* __restrict__ bb)
{
    int warp = threadIdx.x >> 5, lane = threadIdx.x & 31;
    for (int r = warp; r < 64; r += 8) {
        float vals[4];
        float s = 0.f, s2 = 0.f;
#pragma unroll
        for (int cc = 0; cc < 4; cc++) {
            float v = buf[r * LD + lane + cc * 32];
            vals[cc] = v; s += v; s2 += v * v;
        }
        for (int off = 16; off; off >>= 1) {
            s  += __shfl_xor_sync(0xffffffffu, s,  off);
            s2 += __shfl_xor_sync(0xffffffffu, s2, off);
        }
        float m   = s * (1.f / 128.f);
        float var = s2 * (1.f / 128.f) - m * m;
        float inv = rsqrtf(var + 1e-5f);
#pragma unroll
        for (int cc = 0; cc < 4; cc++) {
            int c = lane + cc * 32;
            buf[r * LD + c] = (vals[cc] - m) * inv * g[c] + bb[c];
        }
    }
}

// h[64][128] = relu(A @ W^T + bias)
__device__ __forceinline__ void gemm64_relu(float* __restrict__ outp,
                                            const float* __restrict__ A,
                                            const float* __restrict__ wT,
                                            const float* __restrict__ bias)
{
    int tx = threadIdx.x & 31, ty = threadIdx.x >> 5;
    int r0 = ty * 8, c0 = tx * 4;
    float acc[8][4];
#pragma unroll
    for (int i = 0; i < 8; i++)
#pragma unroll
        for (int j = 0; j < 4; j++) acc[i][j] = 0.f;

    for (int d = 0; d < 128; d += 4) {
        float4 w0 = *(const float4*)(wT + (d + 0) * WLD + c0);
        float4 w1 = *(const float4*)(wT + (d + 1) * WLD + c0);
        float4 w2 = *(const float4*)(wT + (d + 2) * WLD + c0);
        float4 w3 = *(const float4*)(wT + (d + 3) * WLD + c0);
#pragma unroll
        for (int i = 0; i < 8; i++) {
            float4 a = *(const float4*)(A + (r0 + i) * LD + d);
            acc[i][0] += a.x * w0.x + a.y * w1.x + a.z * w2.x + a.w * w3.x;
            acc[i][1] += a.x * w0.y + a.y * w1.y + a.z * w2.y + a.w * w3.y;
            acc[i][2] += a.x * w0.z + a.y * w1.z + a.z * w2.z + a.w * w3.z;
            acc[i][3] += a.x * w0.w + a.y * w1.w + a.z * w2.w + a.w * w3.w;
        }
    }
#pragma unroll
    for (int i = 0; i < 8; i++)
#pragma unroll
        for (int j = 0; j < 4; j++) {
            float v = acc[i][j] + bias[c0 + j];
            outp[(r0 + i) * LD + c0 + j] = fmaxf(v, 0.f);
        }
}

// res[64][128] += A @ W^T + bias   (res also holds the residual)
__device__ __forceinline__ void gemm64_res(float* __restrict__ res,
                                           const float* __restrict__ A,
                                           const float* __restrict__ wT,
                                           const float* __restrict__ bias)
{
    int tx = threadIdx.x & 31, ty = threadIdx.x >> 5;
    int r0 = ty * 8, c0 = tx * 4;
    float acc[8][4];
#pragma unroll
    for (int i = 0; i < 8; i++)
#pragma unroll
        for (int j = 0; j < 4; j++) acc[i][j] = 0.f;

    for (int d = 0; d < 128; d += 4) {
        float4 w0 = *(const float4*)(wT + (d + 0) * WLD + c0);
        float4 w1 = *(const float4*)(wT + (d + 1) * WLD + c0);
        float4 w2 = *(const float4*)(wT + (d + 2) * WLD + c0);
        float4 w3 = *(const float4*)(wT + (d + 3) * WLD + c0);
#pragma unroll
        for (int i = 0; i < 8; i++) {
            float4 a = *(const float4*)(A + (r0 + i) * LD + d);
            acc[i][0] += a.x * w0.x + a.y * w1.x + a.z * w2.x + a.w * w3.x;
            acc[i][1] += a.x * w0.y + a.y * w1.y + a.z * w2.y + a.w * w3.y;
            acc[i][2] += a.x * w0.z + a.y * w1.z + a.z * w2.z + a.w * w3.z;
            acc[i][3] += a.x * w0.w + a.y * w1.w + a.z * w2.w + a.w * w3.w;
        }
    }
#pragma unroll
    for (int i = 0; i < 8; i++)
#pragma unroll
        for (int j = 0; j < 4; j++) {
            int idx = (r0 + i) * LD + c0 + j;
            res[idx] = acc[i][j] + bias[c0 + j] + res[idx];
        }
}

__global__ __launch_bounds__(256) void mlp_kernel(
    const float* __restrict__ ln_g, const float* __restrict__ ln_b,
    const float* __restrict__ w1,   const float* __restrict__ b1,
    const float* __restrict__ w2,   const float* __restrict__ b2,
    float* __restrict__ out)
{
    extern __shared__ float sm[];
    float* xln = sm;                  // 64*LD
    float* h   = xln + 64 * LD;       // 64*LD
    float* wT  = h + 64 * LD;         // 128*WLD

    int base = blockIdx.x * 64;
    int tid  = threadIdx.x;

    for (int e = tid; e < 64 * 128; e += 256) {
        int t = e >> 7, c = e & 127;
        xln[t * LD + c] = g_y[(base + t) * 128 + c];
    }
    __syncthreads();
    ln_rows64(xln, ln_g, ln_b);           // first LN (in place)
    stage_w(wT, w1);
    __syncthreads();
    gemm64_relu(h, xln, wT, b1);
    __syncthreads();
    stage_w(wT, w2);
    __syncthreads();
    gemm64_res(xln, h, wT, b2);           // xln = h@w2^T + b2 + res
    __syncthreads();
    ln_rows64(xln, ln_g, ln_b);           // second LN (same weights)
    __syncthreads();

    // write transposed output (B,C,X,Y,Z), coalesced over spatial
    int b   = base / SS;
    int sp0 = base % SS;
    for (int e = tid; e < 64 * 128; e += 256) {
        int c = e >> 6;
        int s = e & 63;
        out[b * CB * SS + c * SS + sp0 + s] = xln[s * LD + c];
    }
}

// ---------------------------------------------------------------------------
// launch
// ---------------------------------------------------------------------------
extern "C" void kernel_launch(void* const* d_in, const int* in_sizes, int n_in,
                              void* d_out, int out_size)
{
    (void)in_sizes; (void)n_in; (void)out_size;
    const float* x    = (const float*)d_in[0];
    const float* px   = (const float*)d_in[1];
    const float* py   = (const float*)d_in[2];
    const float* pz   = (const float*)d_in[3];
    const float* ln_g = (const float*)d_in[16];
    const float* ln_b = (const float*)d_in[17];
    const float* w1   = (const float*)d_in[18];
    const float* b1   = (const float*)d_in[19];
    const float* w2   = (const float*)d_in[20];
    const float* b2   = (const float*)d_in[21];

    const int ATTN_SMEM = (5 * TSEQ * LD + 128 * WLD + 48 * 48) * (int)sizeof(float); // 203520
    const int MLP_SMEM  = (2 * 64 * LD + 128 * WLD) * (int)sizeof(float);             // 135168

    // Sticky attributes; set on the (non-captured) correctness call, ignore errors later.
    cudaFuncSetAttribute((const void*)attn_kernel,
                         cudaFuncAttributeMaxDynamicSharedMemorySize, ATTN_SMEM);
    cudaFuncSetAttribute((const void*)mlp_kernel,
                         cudaFuncAttributeMaxDynamicSharedMemorySize, MLP_SMEM);

    prep_kernel<<<NT / 64, 256>>>(x, px, py, pz);

    for (int axis = 0; axis < 3; axis++) {
        const float* wq   = (const float*)d_in[4 + 4 * axis];
        const float* wkv  = (const float*)d_in[5 + 4 * axis];
        const float* wout = (const float*)d_in[6 + 4 * axis];
        const float* bout = (const float*)d_in[7 + 4 * axis];
        attn_kernel<<<4608, 256, ATTN_SMEM>>>(wq, wkv, wout, bout, axis);
    }

    mlp_kernel<<<NT / 64, 256, MLP_SMEM>>>(ln_g, ln_b, w1, b1, w2, b2, (float*)d_out);
}

// round 3
// speedup vs baseline: 4.7683x; 4.5500x over previous
#include <cuda_runtime.h>

// Problem constants
#define CB   128
#define SS   110592          // 48^3
#define NB   2
#define NT   221184          // NB*SS tokens
#define QKVW 1152            // 3 axes * (q,k,v) * 128

// Scratch (device globals; no allocation allowed)
__device__ float g_xe [NT * 128];        // pos-embedded input, channels-last (residual 1)
__device__ float g_qkv[NT * QKVW];       // q/k/v for all 3 axes
__device__ float g_o  [NT * 384];        // attention outputs, 3 axes concat
__device__ float g_ln [NT * 128];        // LN1 output (residual 2)
__device__ float g_h  [NT * 128];        // MLP hidden

// ---------------------------------------------------------------------------
// helpers
// ---------------------------------------------------------------------------
__device__ __forceinline__ unsigned f2tf(float x) {
    unsigned u; asm("cvt.rna.tf32.f32 %0, %1;" : "=r"(u) : "f"(x)); return u;
}
__device__ __forceinline__ float tf32r(float x) {
    return __uint_as_float(f2tf(x));
}
__device__ __forceinline__ void cpa16(void* dst, const void* src) {
    unsigned d = (unsigned)__cvta_generic_to_shared(dst);
    asm volatile("cp.async.cg.shared.global [%0], [%1], 16;" :: "r"(d), "l"(src));
}
#define CP_COMMIT() asm volatile("cp.async.commit_group;")
#define CP_WAIT1()  asm volatile("cp.async.wait_group 1;")
#define CP_WAIT0()  asm volatile("cp.async.wait_group 0;")

#define MMA8(d, a, b) \
    asm volatile("mma.sync.aligned.m16n8k8.row.col.f32.tf32.tf32.f32 " \
        "{%0,%1,%2,%3}, {%4,%5,%6,%7}, {%8,%9}, {%0,%1,%2,%3};" \
        : "+f"((d)[0]), "+f"((d)[1]), "+f"((d)[2]), "+f"((d)[3]) \
        : "r"((a)[0]), "r"((a)[1]), "r"((a)[2]), "r"((a)[3]), \
          "r"((b)[0]), "r"((b)[1]))

// ---------------------------------------------------------------------------
// prep: xe = 2*x + px + py + pz, transpose (B,C,S) -> (token, C)
// ---------------------------------------------------------------------------
__global__ __launch_bounds__(256) void prep_kernel(
    const float* __restrict__ x,  const float* __restrict__ px,
    const float* __restrict__ py, const float* __restrict__ pz)
{
    __shared__ float tile[64][129];
    int base = blockIdx.x * 64;
    int b    = base / SS;
    int sp0  = base % SS;

    for (int e = threadIdx.x; e < 64 * 128; e += 256) {
        int c = e >> 6;
        int s = e & 63;
        int spatial = sp0 + s;
        int zi = spatial % 48;
        int yi = (spatial / 48) % 48;
        int xi = spatial / 2304;
        tile[s][c] = 2.0f * x[b * CB * SS + c * SS + spatial]
                   + px[c * 48 + xi] + py[c * 48 + yi] + pz[c * 48 + zi];
    }
    __syncthreads();
    for (int e = threadIdx.x; e < 64 * 128; e += 256) {
        int s = e >> 7;
        int c = e & 127;
        g_xe[(size_t)(base + s) * 128 + c] = tile[s][c];
    }
}

// ---------------------------------------------------------------------------
// Generic tf32 GEMM: C[M x 128-strip] = A[M x K] @ B^T, fused epilogues.
// CTA tile 128x128, 8 warps (4x2), warp tile 32x64, k-chunks of 32, cp.async
// double buffered. mode: 0=qkv store, 1=outproj(+bias3+res+LN1 -> g_ln),
// 2=mlp1(relu -> g_h), 3=mlp2(+bias+res+LN2 -> transposed d_out)
// ---------------------------------------------------------------------------
struct GP {
    const float* Bseg0; const float* Bseg1; const float* Bseg2;
    const float* wq0; const float* wkv0;
    const float* wq1; const float* wkv1;
    const float* wq2; const float* wkv2;
    const float* bias0; const float* bias1; const float* bias2;
    const float* lng; const float* lnb;
    float* out;            // d_out for mode 3
    int mode;
};

#define GEMM_SMEM (4 * 4608 * 4)   // 2 A bufs + 2 B bufs, each 128x36 floats

__global__ __launch_bounds__(256, 2) void gemm_kernel(GP p)
{
    extern __shared__ float sm[];
    float* As = sm;
    float* Bs = sm + 2 * 4608;

    int tid  = threadIdx.x;
    int w    = tid >> 5, lane = tid & 31;
    int mw   = w & 3,  nw = w >> 2;
    int g    = lane >> 2, t = lane & 3;
    long m0  = (long)blockIdx.x * 128;

    const float* Aptr; int lda, NC;
    const float* Bseg[3] = {p.Bseg0, p.Bseg1, p.Bseg2};
    if (p.mode == 0) {
        Aptr = g_xe; lda = 128; NC = 4;
        int s = blockIdx.y, a = s / 3, r = s % 3;
        const float* wqs[3]  = {p.wq0, p.wq1, p.wq2};
        const float* wkvs[3] = {p.wkv0, p.wkv1, p.wkv2};
        Bseg[0] = (r == 0) ? wqs[a] : wkvs[a] + (size_t)(r - 1) * 16384;
    } else if (p.mode == 1) { Aptr = g_o;  lda = 384; NC = 12; }
    else if   (p.mode == 2) { Aptr = g_ln; lda = 128; NC = 4;  }
    else                    { Aptr = g_h;  lda = 128; NC = 4;  }

    // ---- staging ----
#define STAGE(c, buf) do {                                                    \
        int k0_ = (c) * 32;                                                   \
        const float* Bp_ = Bseg[k0_ >> 7] + (k0_ & 127);                      \
        _Pragma("unroll")                                                     \
        for (int i_ = 0; i_ < 4; i_++) {                                      \
            int idx_ = tid + 256 * i_;                                        \
            int row_ = idx_ >> 3, sg_ = idx_ & 7;                             \
            cpa16(As + (buf) * 4608 + row_ * 36 + sg_ * 4,                    \
                  Aptr + (m0 + row_) * lda + k0_ + sg_ * 4);                  \
            cpa16(Bs + (buf) * 4608 + row_ * 36 + sg_ * 4,                    \
                  Bp_ + (size_t)row_ * 128 + sg_ * 4);                        \
        }                                                                     \
    } while (0)

    float acc[2][8][4];
#pragma unroll
    for (int mt = 0; mt < 2; mt++)
#pragma unroll
        for (int nt = 0; nt < 8; nt++)
#pragma unroll
            for (int i = 0; i < 4; i++) acc[mt][nt][i] = 0.f;

    STAGE(0, 0); CP_COMMIT();

    for (int c = 0; c < NC; c++) {
        if (c + 1 < NC) { STAGE(c + 1, (c + 1) & 1); CP_COMMIT(); CP_WAIT1(); }
        else            { CP_WAIT0(); }
        __syncthreads();
        const float* Ac = As + (c & 1) * 4608 + (mw * 32) * 36;
        const float* Bc = Bs + (c & 1) * 4608 + (nw * 64) * 36;
#pragma unroll
        for (int kk = 0; kk < 32; kk += 8) {
            unsigned a[2][4];
#pragma unroll
            for (int mt = 0; mt < 2; mt++) {
                int ab = (mt * 16 + g) * 36 + kk + t;
                a[mt][0] = f2tf(Ac[ab]);
                a[mt][1] = f2tf(Ac[ab + 8 * 36]);
                a[mt][2] = f2tf(Ac[ab + 4]);
                a[mt][3] = f2tf(Ac[ab + 8 * 36 + 4]);
            }
#pragma unroll
            for (int nt = 0; nt < 8; nt++) {
                int bb = (nt * 8 + g) * 36 + kk + t;
                unsigned b[2];
                b[0] = f2tf(Bc[bb]);
                b[1] = f2tf(Bc[bb + 4]);
                MMA8(acc[0][nt], a[0], b);
                MMA8(acc[1][nt], a[1], b);
            }
        }
        __syncthreads();
    }

    // ---- epilogues ----
    if (p.mode == 0) {
        size_t ocol = (size_t)blockIdx.y * 128;
#pragma unroll
        for (int mt = 0; mt < 2; mt++)
#pragma unroll
            for (int nt = 0; nt < 8; nt++) {
                size_t tok = m0 + mw * 32 + mt * 16 + g;
                int cc = nw * 64 + nt * 8 + t * 2;
                *(float2*)(g_qkv + tok * QKVW + ocol + cc) =
                    make_float2(acc[mt][nt][0], acc[mt][nt][1]);
                *(float2*)(g_qkv + (tok + 8) * QKVW + ocol + cc) =
                    make_float2(acc[mt][nt][2], acc[mt][nt][3]);
            }
        return;
    }
    if (p.mode == 2) {
#pragma unroll
        for (int mt = 0; mt < 2; mt++)
#pragma unroll
            for (int nt = 0; nt < 8; nt++) {
                size_t tok = m0 + mw * 32 + mt * 16 + g;
                int cc = nw * 64 + nt * 8 + t * 2;
                float b0 = p.bias0[cc], b1 = p.bias0[cc + 1];
                *(float2*)(g_h + tok * 128 + cc) =
                    make_float2(fmaxf(acc[mt][nt][0] + b0, 0.f),
                                fmaxf(acc[mt][nt][1] + b1, 0.f));
                *(float2*)(g_h + (tok + 8) * 128 + cc) =
                    make_float2(fmaxf(acc[mt][nt][2] + b0, 0.f),
                                fmaxf(acc[mt][nt][3] + b1, 0.f));
            }
        return;
    }

    // mode 1 / 3: write to Ct (union over A/B buffers), LN rows, store
    const int CS = (p.mode == 3) ? 133 : 132;
    float* Ct = sm;
#pragma unroll
    for (int mt = 0; mt < 2; mt++)
#pragma unroll
        for (int nt = 0; nt < 8; nt++) {
            int rl = mw * 32 + mt * 16 + g;
            int cc = nw * 64 + nt * 8 + t * 2;
            size_t tok = m0 + rl;
            float b0, b1;
            if (p.mode == 1) {
                b0 = p.bias0[cc] + p.bias1[cc] + p.bias2[cc];
                b1 = p.bias0[cc + 1] + p.bias1[cc + 1] + p.bias2[cc + 1];
            } else {
                b0 = p.bias0[cc]; b1 = p.bias0[cc + 1];
            }
            const float* res = (p.mode == 1) ? g_xe : g_ln;
            Ct[rl * CS + cc]           = acc[mt][nt][0] + b0 + res[tok * 128 + cc];
            Ct[rl * CS + cc + 1]       = acc[mt][nt][1] + b1 + res[tok * 128 + cc + 1];
            Ct[(rl + 8) * CS + cc]     = acc[mt][nt][2] + b0 + res[(tok + 8) * 128 + cc];
            Ct[(rl + 8) * CS + cc + 1] = acc[mt][nt][3] + b1 + res[(tok + 8) * 128 + cc + 1];
        }
    __syncthreads();

    // LN per row: warp per row
    for (int r = w; r < 128; r += 8) {
        float v[4], s = 0.f, s2 = 0.f;
#pragma unroll
        for (int k = 0; k < 4; k++) {
            v[k] = Ct[r * CS + lane + 32 * k];
            s += v[k]; s2 += v[k] * v[k];
        }
        for (int off = 16; off; off >>= 1) {
            s  += __shfl_xor_sync(0xffffffffu, s,  off);
            s2 += __shfl_xor_sync(0xffffffffu, s2, off);
        }
        float m   = s * (1.f / 128.f);
        float var = s2 * (1.f / 128.f) - m * m;
        float inv = rsqrtf(var + 1e-5f);
#pragma unroll
        for (int k = 0; k < 4; k++) {
            int cc = lane + 32 * k;
            float y = (v[k] - m) * inv * p.lng[cc] + p.lnb[cc];
            if (p.mode == 1) g_ln[(m0 + r) * 128 + cc] = y;
            else             Ct[r * CS + cc] = y;
        }
    }
    if (p.mode == 3) {
        __syncthreads();
        int  bi  = (int)(m0 / SS);
        long sp0 = m0 % SS;
        float* outp = p.out + (size_t)bi * CB * SS + sp0;
        for (int e = tid; e < 128 * 128; e += 256) {
            int cc = e >> 7, ss = e & 127;
            outp[(size_t)cc * SS + ss] = Ct[ss * 133 + cc];
        }
    }
#undef STAGE
}

// ---------------------------------------------------------------------------
// attention: grid (4608, 3 axes); 8 warps, warp = head; scores & AV on mma,
// softmax fully in registers (quad-local rows).
// per-head smem: Q[48][28], K[48][28] (union with P[48][49]), V[48][24]
// ---------------------------------------------------------------------------
#define HSZ 3840
#define ATTN_SMEM (8 * HSZ * 4)

__global__ __launch_bounds__(256) void attn_kernel()
{
    extern __shared__ float sm[];
    int tid = threadIdx.x, w = tid >> 5, lane = tid & 31;
    int g = lane >> 2, t = lane & 3;
    int h = w;

    int axis = blockIdx.y, seq = blockIdx.x;
    int b = seq / 2304, rr = seq % 2304;
    int o1 = rr / 48, o2 = rr % 48;
    long base; int stride;
    if (axis == 0)      { base = (long)b * SS + o1 * 48 + o2;        stride = 2304; }
    else if (axis == 1) { base = (long)b * SS + o1 * 2304 + o2;      stride = 48;   }
    else                { base = (long)b * SS + o1 * 2304 + o2 * 48; stride = 1;    }

    float* hb = sm + w * HSZ;
    float* Qs = hb;
    float* Ks = hb + 1344;
    float* Ps = hb;            // union over Q+K (used after scores)
    float* Vs = hb + 2688;

    // stage q,k,v for this head (tf32-rounded; q pre-scaled by 0.25 = e^-0.5)
#pragma unroll
    for (int i = 0; i < 6; i++) {
        int idx = lane + 32 * i;
        int tok = idx >> 2, sg = idx & 3;
        size_t ga = (size_t)(base + (long)tok * stride) * QKVW
                  + (size_t)axis * 384 + h * 16 + sg * 4;
        float4 qv = *(const float4*)(g_qkv + ga);
        float4 kv = *(const float4*)(g_qkv + ga + 128);
        float4 vv = *(const float4*)(g_qkv + ga + 256);
        float4 qo = make_float4(tf32r(qv.x * 0.25f), tf32r(qv.y * 0.25f),
                                tf32r(qv.z * 0.25f), tf32r(qv.w * 0.25f));
        float4 ko = make_float4(tf32r(kv.x), tf32r(kv.y), tf32r(kv.z), tf32r(kv.w));
        float4 vo = make_float4(tf32r(vv.x), tf32r(vv.y), tf32r(vv.z), tf32r(vv.w));
        *(float4*)(Qs + tok * 28 + sg * 4) = qo;
        *(float4*)(Ks + tok * 28 + sg * 4) = ko;
        *(float4*)(Vs + tok * 24 + sg * 4) = vo;
    }
    __syncwarp();

    // scores S = Q @ K^T : M=48, N=48, K=16
    float s[3][6][4];
#pragma unroll
    for (int mt = 0; mt < 3; mt++)
#pragma unroll
        for (int nt = 0; nt < 6; nt++)
#pragma unroll
            for (int i = 0; i < 4; i++) s[mt][nt][i] = 0.f;

#pragma unroll
    for (int kt = 0; kt < 2; kt++) {
        unsigned a[3][4];
#pragma unroll
        for (int mt = 0; mt < 3; mt++) {
            int ab = (mt * 16 + g) * 28 + kt * 8 + t;
            a[mt][0] = __float_as_uint(Qs[ab]);
            a[mt][1] = __float_as_uint(Qs[ab + 8 * 28]);
            a[mt][2] = __float_as_uint(Qs[ab + 4]);
            a[mt][3] = __float_as_uint(Qs[ab + 8 * 28 + 4]);
        }
#pragma unroll
        for (int nt = 0; nt < 6; nt++) {
            int bb = (nt * 8 + g) * 28 + kt * 8 + t;
            unsigned bf[2];
            bf[0] = __float_as_uint(Ks[bb]);
            bf[1] = __float_as_uint(Ks[bb + 4]);
            MMA8(s[0][nt], a[0], bf);
            MMA8(s[1][nt], a[1], bf);
            MMA8(s[2][nt], a[2], bf);
        }
    }

    // softmax: row (mt,hi) lives on the 4 lanes of a quad (t dim)
#pragma unroll
    for (int mt = 0; mt < 3; mt++)
#pragma unroll
        for (int hi = 0; hi < 2; hi++) {
            float mx = -1e30f;
#pragma unroll
            for (int nt = 0; nt < 6; nt++) {
                mx = fmaxf(mx, s[mt][nt][hi * 2]);
                mx = fmaxf(mx, s[mt][nt][hi * 2 + 1]);
            }
            mx = fmaxf(mx, __shfl_xor_sync(0xffffffffu, mx, 1));
            mx = fmaxf(mx, __shfl_xor_sync(0xffffffffu, mx, 2));
            float sum = 0.f;
#pragma unroll
            for (int nt = 0; nt < 6; nt++) {
#pragma unroll
                for (int lo = 0; lo < 2; lo++) {
                    float e = __expf(s[mt][nt][hi * 2 + lo] - mx);
                    s[mt][nt][hi * 2 + lo] = e;
                    sum += e;
                }
            }
            sum += __shfl_xor_sync(0xffffffffu, sum, 1);
            sum += __shfl_xor_sync(0xffffffffu, sum, 2);
            float inv = 1.f / sum;
#pragma unroll
            for (int nt = 0; nt < 6; nt++) {
                s[mt][nt][hi * 2]     *= inv;
                s[mt][nt][hi * 2 + 1] *= inv;
            }
        }

    // store P (tf32-rounded) into union buffer
#pragma unroll
    for (int mt = 0; mt < 3; mt++)
#pragma unroll
        for (int hi = 0; hi < 2; hi++)
#pragma unroll
            for (int nt = 0; nt < 6; nt++) {
                int r = mt * 16 + hi * 8 + g;
                int c = nt * 8 + 2 * t;
                Ps[r * 49 + c]     = tf32r(s[mt][nt][hi * 2]);
                Ps[r * 49 + c + 1] = tf32r(s[mt][nt][hi * 2 + 1]);
            }
    __syncwarp();

    // O = P @ V : M=48, N=16, K=48
    float o[3][2][4];
#pragma unroll
    for (int mt = 0; mt < 3; mt++)
#pragma unroll
        for (int nt = 0; nt < 2; nt++)
#pragma unroll
            for (int i = 0; i < 4; i++) o[mt][nt][i] = 0.f;

#pragma unroll
    for (int kt = 0; kt < 6; kt++) {
        unsigned a[3][4];
#pragma unroll
        for (int mt = 0; mt < 3; mt++) {
            int ab = (mt * 16 + g) * 49 + kt * 8 + t;
            a[mt][0] = __float_as_uint(Ps[ab]);
            a[mt][1] = __float_as_uint(Ps[ab + 8 * 49]);
            a[mt][2] = __float_as_uint(Ps[ab + 4]);
            a[mt][3] = __float_as_uint(Ps[ab + 8 * 49 + 4]);
        }
#pragma unroll
        for (int nt = 0; nt < 2; nt++) {
            int bb = (kt * 8 + t) * 24 + nt * 8 + g;
            unsigned bf[2];
            bf[0] = __float_as_uint(Vs[bb]);
            bf[1] = __float_as_uint(Vs[bb + 4 * 24]);
            MMA8(o[0][nt], a[0], bf);
            MMA8(o[1][nt], a[1], bf);
            MMA8(o[2][nt], a[2], bf);
        }
    }

    // store O to g_o[token][axis*128 + h*16 + e]
#pragma unroll
    for (int mt = 0; mt < 3; mt++)
#pragma unroll
        for (int nt = 0; nt < 2; nt++) {
            long tok = base + (long)(mt * 16 + g) * stride;
            size_t ob = (size_t)tok * 384 + (size_t)axis * 128 + h * 16 + nt * 8 + 2 * t;
            *(float2*)(g_o + ob) = make_float2(o[mt][nt][0], o[mt][nt][1]);
            *(float2*)(g_o + ob + (size_t)8 * stride * 384) =
                make_float2(o[mt][nt][2], o[mt][nt][3]);
        }
}

// ---------------------------------------------------------------------------
// launch
// ---------------------------------------------------------------------------
extern "C" void kernel_launch(void* const* d_in, const int* in_sizes, int n_in,
                              void* d_out, int out_size)
{
    (void)in_sizes; (void)n_in; (void)out_size;
    const float* x    = (const float*)d_in[0];
    const float* px   = (const float*)d_in[1];
    const float* py   = (const float*)d_in[2];
    const float* pz   = (const float*)d_in[3];
    const float* ln_g = (const float*)d_in[16];
    const float* ln_b = (const float*)d_in[17];
    const float* w1   = (const float*)d_in[18];
    const float* b1   = (const float*)d_in[19];
    const float* w2   = (const float*)d_in[20];
    const float* b2   = (const float*)d_in[21];

    cudaFuncSetAttribute((const void*)gemm_kernel,
                         cudaFuncAttributeMaxDynamicSharedMemorySize, GEMM_SMEM);
    cudaFuncSetAttribute((const void*)attn_kernel,
                         cudaFuncAttributeMaxDynamicSharedMemorySize, ATTN_SMEM);

    prep_kernel<<<NT / 64, 256>>>(x, px, py, pz);

    GP q = {};
    q.mode = 0;
    q.wq0 = (const float*)d_in[4];  q.wkv0 = (const float*)d_in[5];
    q.wq1 = (const float*)d_in[8];  q.wkv1 = (const float*)d_in[9];
    q.wq2 = (const float*)d_in[12]; q.wkv2 = (const float*)d_in[13];
    gemm_kernel<<<dim3(NT / 128, 9), 256, GEMM_SMEM>>>(q);

    attn_kernel<<<dim3(4608, 3), 256, ATTN_SMEM>>>();

    GP op = {};
    op.mode = 1;
    op.Bseg0 = (const float*)d_in[6];
    op.Bseg1 = (const float*)d_in[10];
    op.Bseg2 = (const float*)d_in[14];
    op.bias0 = (const float*)d_in[7];
    op.bias1 = (const float*)d_in[11];
    op.bias2 = (const float*)d_in[15];
    op.lng = ln_g; op.lnb = ln_b;
    gemm_kernel<<<NT / 128, 256, GEMM_SMEM>>>(op);

    GP m1 = {};
    m1.mode = 2;
    m1.Bseg0 = w1; m1.Bseg1 = w1; m1.Bseg2 = w1;
    m1.bias0 = b1;
    gemm_kernel<<<NT / 128, 256, GEMM_SMEM>>>(m1);

    GP m2 = {};
    m2.mode = 3;
    m2.Bseg0 = w2; m2.Bseg1 = w2; m2.Bseg2 = w2;
    m2.bias0 = b2;
    m2.lng = ln_g; m2.lnb = ln_b;
    m2.out = (float*)d_out;
    gemm_kernel<<<NT / 128, 256, GEMM_SMEM>>>(m2);
}

// round 4
// speedup vs baseline: 8.6042x; 1.8044x over previous
#include <cuda_runtime.h>
#include <cuda_fp16.h>

// Problem constants
#define SS   110592          // 48^3
#define NT   221184          // NB*SS tokens
#define QKVW 1152            // 3 axes * (q,k,v) * 128

// Scratch (device globals; no allocation allowed) — all intermediates fp16
__device__ __half g_xe [NT * 128];            // pos-embedded input (residual 1)
__device__ __half g_qkv[(size_t)NT * QKVW];   // q/k/v, 3 axes
__device__ __half g_o  [(size_t)NT * 384];    // attention outputs, 3 axes
__device__ __half g_ln [NT * 128];            // LN1 output (residual 2)
__device__ __half g_h  [NT * 128];            // MLP hidden
// fp16 weights: [0,147456) qkv strips (9 x 128x128), [147456,196608) wout_cat
// (128 rows x 384), [196608,212992) w1, [212992,229376) w2
__device__ __half g_wh [229376];

// ---------------------------------------------------------------------------
// helpers
// ---------------------------------------------------------------------------
__device__ __forceinline__ void cpa16_s(unsigned d, const void* s) {
    asm volatile("cp.async.cg.shared.global [%0], [%1], 16;" :: "r"(d), "l"(s));
}
#define CP_COMMIT() asm volatile("cp.async.commit_group;")
#define CP_WAIT1()  asm volatile("cp.async.wait_group 1;")
#define CP_WAIT0()  asm volatile("cp.async.wait_group 0;")

#define LDSM4(r, addr) \
    asm volatile("ldmatrix.sync.aligned.m8n8.x4.shared.b16 {%0,%1,%2,%3}, [%4];" \
        : "=r"((r)[0]), "=r"((r)[1]), "=r"((r)[2]), "=r"((r)[3]) : "r"(addr))

#define MMA16(d, a, b0, b1) \
    asm volatile("mma.sync.aligned.m16n8k16.row.col.f32.f16.f16.f32 " \
        "{%0,%1,%2,%3}, {%4,%5,%6,%7}, {%8,%9}, {%0,%1,%2,%3};" \
        : "+f"((d)[0]), "+f"((d)[1]), "+f"((d)[2]), "+f"((d)[3]) \
        : "r"((a)[0]), "r"((a)[1]), "r"((a)[2]), "r"((a)[3]), \
          "r"(b0), "r"(b1))

__device__ __forceinline__ unsigned h2u(float x, float y) {
    __half2 h = __floats2half2_rn(x, y);
    return *(unsigned*)&h;
}

// ---------------------------------------------------------------------------
// weight convert: fp32 -> fp16 buffer, one-time layout
// ---------------------------------------------------------------------------
struct WP {
    const float* wq[3]; const float* wkv[3]; const float* wout[3];
    const float* w1; const float* w2;
};
__global__ __launch_bounds__(256) void wconv_kernel(WP p)
{
    int idx = blockIdx.x * 256 + threadIdx.x;
    if (idx >= 229376) return;
    float v;
    if (idx < 147456) {
        int strip = idx >> 14, rem = idx & 16383;
        int a = strip / 3, r = strip - a * 3;
        v = (r == 0) ? p.wq[a][rem] : p.wkv[a][(r - 1) * 16384 + rem];
    } else if (idx < 196608) {
        int rem = idx - 147456;
        int n = rem / 384, k = rem - n * 384;
        v = p.wout[k >> 7][n * 128 + (k & 127)];
    } else if (idx < 212992) v = p.w1[idx - 196608];
    else                     v = p.w2[idx - 212992];
    g_wh[idx] = __float2half(v);
}

// ---------------------------------------------------------------------------
// prep: xe = 2*x + px + py + pz, transpose (B,C,S) -> (token, C), fp16
// ---------------------------------------------------------------------------
__global__ __launch_bounds__(256) void prep_kernel(
    const float* __restrict__ x,  const float* __restrict__ px,
    const float* __restrict__ py, const float* __restrict__ pz)
{
    __shared__ float tile[64][129];
    int base = blockIdx.x * 64;
    int b    = base / SS;
    int sp0  = base % SS;

    for (int e = threadIdx.x; e < 64 * 128; e += 256) {
        int c = e >> 6;
        int s = e & 63;
        int spatial = sp0 + s;
        int zi = spatial % 48;
        int yi = (spatial / 48) % 48;
        int xi = spatial / 2304;
        tile[s][c] = 2.0f * x[(size_t)b * 128 * SS + (size_t)c * SS + spatial]
                   + px[c * 48 + xi] + py[c * 48 + yi] + pz[c * 48 + zi];
    }
    __syncthreads();
    for (int e = threadIdx.x; e < 64 * 128; e += 256) {
        int s = e >> 7;
        int c = e & 127;
        g_xe[(size_t)(base + s) * 128 + c] = __float2half(tile[s][c]);
    }
}

// ---------------------------------------------------------------------------
// fp16 GEMM: C[Mx128] = A[MxK] @ B^T, ldmatrix + m16n8k16, fused epilogues.
// modes: 0=qkv (blockIdx.x=strip, blockIdx.y=mtile), 1=outproj+res+LN1,
// 2=mlp1 relu, 3=mlp2+res+LN2+transposed fp32 store
// ---------------------------------------------------------------------------
struct GP {
    const float *bias0, *bias1, *bias2, *lng, *lnb;
    float* out;
    int mode;
};

#define GEMM_SMEM 68096

__global__ __launch_bounds__(256, 2) void gemm_kernel(GP p)
{
    extern __shared__ __align__(16) char smc[];
    unsigned sA = (unsigned)__cvta_generic_to_shared(smc);
    unsigned sB = sA + 32768;

    int tid = threadIdx.x, w = tid >> 5, lane = tid & 31;
    int mw = w & 3, nw = w >> 2;
    int g = lane >> 2, t = lane & 3;

    long m0; const __half* Ap; const __half* Bp;
    int lda, ldb, NC;
    if (p.mode == 0) {
        m0 = (long)blockIdx.y * 128;
        Ap = g_xe; lda = 128;
        Bp = g_wh + (size_t)blockIdx.x * 16384; ldb = 128; NC = 2;
    } else if (p.mode == 1) {
        m0 = (long)blockIdx.x * 128;
        Ap = g_o; lda = 384;
        Bp = g_wh + 147456; ldb = 384; NC = 6;
    } else if (p.mode == 2) {
        m0 = (long)blockIdx.x * 128;
        Ap = g_ln; lda = 128;
        Bp = g_wh + 196608; ldb = 128; NC = 2;
    } else {
        m0 = (long)blockIdx.x * 128;
        Ap = g_h; lda = 128;
        Bp = g_wh + 212992; ldb = 128; NC = 2;
    }

#define STAGE(c, buf) do {                                                    \
        int k0_ = (c) * 64;                                                   \
        _Pragma("unroll")                                                     \
        for (int i_ = 0; i_ < 4; i_++) {                                      \
            int idx_ = tid + 256 * i_;                                        \
            int row_ = idx_ >> 3, seg_ = idx_ & 7;                            \
            unsigned dcol_ = (unsigned)((seg_ * 16) ^ ((row_ & 7) << 4));     \
            cpa16_s(sA + (buf) * 16384 + row_ * 128 + dcol_,                  \
                    Ap + (m0 + row_) * (size_t)lda + k0_ + seg_ * 8);         \
            cpa16_s(sB + (buf) * 16384 + row_ * 128 + dcol_,                  \
                    Bp + (size_t)row_ * ldb + k0_ + seg_ * 8);                \
        }                                                                     \
    } while (0)

    float acc[2][8][4];
#pragma unroll
    for (int mt = 0; mt < 2; mt++)
#pragma unroll
        for (int nt = 0; nt < 8; nt++)
#pragma unroll
            for (int i = 0; i < 4; i++) acc[mt][nt][i] = 0.f;

    STAGE(0, 0); CP_COMMIT();

    int rowA  = mw * 32 + (lane & 15);
    int rowB0 = nw * 64 + ((lane & 16) >> 1) + (lane & 7);
    unsigned hiA = (unsigned)((lane >> 4) << 4);
    unsigned hiB = (unsigned)(((lane >> 3) & 1) << 4);
    unsigned xA = (unsigned)((rowA & 7) << 4);
    unsigned xB = (unsigned)((rowB0 & 7) << 4);

    for (int c = 0; c < NC; c++) {
        if (c + 1 < NC) { STAGE(c + 1, (c + 1) & 1); CP_COMMIT(); CP_WAIT1(); }
        else            { CP_WAIT0(); }
        __syncthreads();
        unsigned baseA = sA + (c & 1) * 16384;
        unsigned baseB = sB + (c & 1) * 16384;
#pragma unroll
        for (int kt = 0; kt < 4; kt++) {
            unsigned a[2][4];
#pragma unroll
            for (int mt = 0; mt < 2; mt++) {
                unsigned adr = baseA + (rowA + mt * 16) * 128
                             + (((unsigned)(kt * 32) + hiA) ^ xA);
                LDSM4(a[mt], adr);
            }
#pragma unroll
            for (int np = 0; np < 4; np++) {
                unsigned adr = baseB + (rowB0 + np * 16) * 128
                             + (((unsigned)(kt * 32) + hiB) ^ xB);
                unsigned b[4];
                LDSM4(b, adr);
                MMA16(acc[0][2 * np],     a[0], b[0], b[1]);
                MMA16(acc[1][2 * np],     a[1], b[0], b[1]);
                MMA16(acc[0][2 * np + 1], a[0], b[2], b[3]);
                MMA16(acc[1][2 * np + 1], a[1], b[2], b[3]);
            }
        }
        __syncthreads();
    }
#undef STAGE

    // ---- epilogues ----
    if (p.mode == 0) {
        size_t ocol = (size_t)blockIdx.x * 128;
#pragma unroll
        for (int mt = 0; mt < 2; mt++)
#pragma unroll
            for (int nt = 0; nt < 8; nt++) {
                size_t tok = m0 + mw * 32 + mt * 16 + g;
                int cc = nw * 64 + nt * 8 + 2 * t;
                *(__half2*)(g_qkv + tok * QKVW + ocol + cc) =
                    __floats2half2_rn(acc[mt][nt][0], acc[mt][nt][1]);
                *(__half2*)(g_qkv + (tok + 8) * QKVW + ocol + cc) =
                    __floats2half2_rn(acc[mt][nt][2], acc[mt][nt][3]);
            }
        return;
    }
    if (p.mode == 2) {
#pragma unroll
        for (int mt = 0; mt < 2; mt++)
#pragma unroll
            for (int nt = 0; nt < 8; nt++) {
                size_t tok = m0 + mw * 32 + mt * 16 + g;
                int cc = nw * 64 + nt * 8 + 2 * t;
                float b0 = p.bias0[cc], b1 = p.bias0[cc + 1];
                *(__half2*)(g_h + tok * 128 + cc) =
                    __floats2half2_rn(fmaxf(acc[mt][nt][0] + b0, 0.f),
                                      fmaxf(acc[mt][nt][1] + b1, 0.f));
                *(__half2*)(g_h + (tok + 8) * 128 + cc) =
                    __floats2half2_rn(fmaxf(acc[mt][nt][2] + b0, 0.f),
                                      fmaxf(acc[mt][nt][3] + b1, 0.f));
            }
        return;
    }

    // modes 1/3: residual add in fp32 Ct (reuses smem), LN rows, store
    const int CS = (p.mode == 3) ? 133 : 132;
    float* Ct = (float*)smc;
    const __half* res = (p.mode == 1) ? g_xe : g_ln;
#pragma unroll
    for (int mt = 0; mt < 2; mt++)
#pragma unroll
        for (int nt = 0; nt < 8; nt++) {
            int rl = mw * 32 + mt * 16 + g;
            int cc = nw * 64 + nt * 8 + 2 * t;
            size_t tok = m0 + rl;
            float b0, b1;
            if (p.mode == 1) {
                b0 = p.bias0[cc] + p.bias1[cc] + p.bias2[cc];
                b1 = p.bias0[cc + 1] + p.bias1[cc + 1] + p.bias2[cc + 1];
            } else {
                b0 = p.bias0[cc]; b1 = p.bias0[cc + 1];
            }
            Ct[rl * CS + cc]     = acc[mt][nt][0] + b0 + __half2float(res[tok * 128 + cc]);
            Ct[rl * CS + cc + 1] = acc[mt][nt][1] + b1 + __half2float(res[tok * 128 + cc + 1]);
            Ct[(rl + 8) * CS + cc]     = acc[mt][nt][2] + b0 + __half2float(res[(tok + 8) * 128 + cc]);
            Ct[(rl + 8) * CS + cc + 1] = acc[mt][nt][3] + b1 + __half2float(res[(tok + 8) * 128 + cc + 1]);
        }
    __syncthreads();

    for (int r = w; r < 128; r += 8) {
        float v[4], s = 0.f, s2 = 0.f;
#pragma unroll
        for (int k = 0; k < 4; k++) {
            v[k] = Ct[r * CS + lane + 32 * k];
            s += v[k]; s2 += v[k] * v[k];
        }
        for (int off = 16; off; off >>= 1) {
            s  += __shfl_xor_sync(0xffffffffu, s,  off);
            s2 += __shfl_xor_sync(0xffffffffu, s2, off);
        }
        float m   = s * (1.f / 128.f);
        float var = s2 * (1.f / 128.f) - m * m;
        float inv = rsqrtf(var + 1e-5f);
#pragma unroll
        for (int k = 0; k < 4; k++) {
            int cc = lane + 32 * k;
            float y = (v[k] - m) * inv * p.lng[cc] + p.lnb[cc];
            if (p.mode == 1) g_ln[(m0 + r) * 128 + cc] = __float2half(y);
            else             Ct[r * CS + cc] = y;
        }
    }
    if (p.mode == 3) {
        __syncthreads();
        int  bi  = (int)(m0 / SS);
        long sp0 = m0 % SS;
        float* outp = p.out + (size_t)bi * 128 * SS + sp0;
        for (int e = tid; e < 128 * 128; e += 256) {
            int cc = e >> 7, ss = e & 127;
            outp[(size_t)cc * SS + ss] = Ct[ss * 133 + cc];
        }
    }
}

// ---------------------------------------------------------------------------
// attention: grid (4608, 3); warp = head; fp16 mma for QK^T and P@V,
// P kept in registers (S-acc fragments repacked as A-fragments).
// per-head smem (halves): Qs 48x24, Ks 48x24, Vt 16x56 = 3200
// ---------------------------------------------------------------------------
#define ATTN_SMEM 51200

__global__ __launch_bounds__(256) void attn_kernel()
{
    extern __shared__ __align__(16) __half smh[];
    int tid = threadIdx.x, w = tid >> 5, lane = tid & 31;
    int g = lane >> 2, t = lane & 3, h = w;

    int axis = blockIdx.y, seq = blockIdx.x;
    int b = seq / 2304, rr = seq % 2304;
    int o1 = rr / 48, o2 = rr % 48;
    long base; int stride;
    if (axis == 0)      { base = (long)b * SS + o1 * 48 + o2;        stride = 2304; }
    else if (axis == 1) { base = (long)b * SS + o1 * 2304 + o2;      stride = 48;   }
    else                { base = (long)b * SS + o1 * 2304 + o2 * 48; stride = 1;    }

    __half* Qs = smh + w * 3200;
    __half* Ks = Qs + 1152;
    __half* Vt = Qs + 2304;

    for (int tok = lane; tok < 48; tok += 32) {
        const __half* gp = g_qkv + (size_t)(base + (long)tok * stride) * QKVW
                         + axis * 384 + h * 16;
        uint4 q0 = *(const uint4*)gp;         uint4 q1 = *(const uint4*)(gp + 8);
        uint4 k0 = *(const uint4*)(gp + 128); uint4 k1 = *(const uint4*)(gp + 136);
        uint4 v0 = *(const uint4*)(gp + 256); uint4 v1 = *(const uint4*)(gp + 264);
        *(uint4*)(Qs + tok * 24)     = q0;  *(uint4*)(Qs + tok * 24 + 8) = q1;
        *(uint4*)(Ks + tok * 24)     = k0;  *(uint4*)(Ks + tok * 24 + 8) = k1;
        __half vb[16];
        *(uint4*)vb = v0; *(uint4*)(vb + 8) = v1;
#pragma unroll
        for (int e = 0; e < 16; e++) Vt[e * 56 + tok] = vb[e];
    }
    __syncwarp();

    // scores S = Q @ K^T : M=48, N=48, K=16 (one k-tile)
    float s[3][6][4];
#pragma unroll
    for (int mt = 0; mt < 3; mt++)
#pragma unroll
        for (int nt = 0; nt < 6; nt++)
#pragma unroll
            for (int i = 0; i < 4; i++) s[mt][nt][i] = 0.f;

    {
        unsigned a[3][4];
#pragma unroll
        for (int mt = 0; mt < 3; mt++) {
            const __half* qb = Qs + (mt * 16 + g) * 24 + 2 * t;
            a[mt][0] = *(const unsigned*)qb;
            a[mt][1] = *(const unsigned*)(qb + 8 * 24);
            a[mt][2] = *(const unsigned*)(qb + 8);
            a[mt][3] = *(const unsigned*)(qb + 8 * 24 + 8);
        }
#pragma unroll
        for (int nt = 0; nt < 6; nt++) {
            const __half* kb = Ks + (nt * 8 + g) * 24 + 2 * t;
            unsigned b0 = *(const unsigned*)kb;
            unsigned b1 = *(const unsigned*)(kb + 8);
            MMA16(s[0][nt], a[0], b0, b1);
            MMA16(s[1][nt], a[1], b0, b1);
            MMA16(s[2][nt], a[2], b0, b1);
        }
    }

    // softmax over j (scale 0.25 = e^-0.5); row (mt,hi) lives on a lane-quad
#pragma unroll
    for (int mt = 0; mt < 3; mt++)
#pragma unroll
        for (int hi = 0; hi < 2; hi++) {
            float mx = -1e30f;
#pragma unroll
            for (int nt = 0; nt < 6; nt++) {
                s[mt][nt][hi * 2]     *= 0.25f;
                s[mt][nt][hi * 2 + 1] *= 0.25f;
                mx = fmaxf(mx, fmaxf(s[mt][nt][hi * 2], s[mt][nt][hi * 2 + 1]));
            }
            mx = fmaxf(mx, __shfl_xor_sync(0xffffffffu, mx, 1));
            mx = fmaxf(mx, __shfl_xor_sync(0xffffffffu, mx, 2));
            float sum = 0.f;
#pragma unroll
            for (int nt = 0; nt < 6; nt++)
#pragma unroll
                for (int lo = 0; lo < 2; lo++) {
                    float e = __expf(s[mt][nt][hi * 2 + lo] - mx);
                    s[mt][nt][hi * 2 + lo] = e;
                    sum += e;
                }
            sum += __shfl_xor_sync(0xffffffffu, sum, 1);
            sum += __shfl_xor_sync(0xffffffffu, sum, 2);
            float inv = 1.f / sum;
#pragma unroll
            for (int nt = 0; nt < 6; nt++) {
                s[mt][nt][hi * 2]     *= inv;
                s[mt][nt][hi * 2 + 1] *= inv;
            }
        }

    // O = P @ V : M=48, N=16, K=48; P fragments repacked from S accumulators
    float o[3][2][4];
#pragma unroll
    for (int mt = 0; mt < 3; mt++)
#pragma unroll
        for (int nt = 0; nt < 2; nt++)
#pragma unroll
            for (int i = 0; i < 4; i++) o[mt][nt][i] = 0.f;

#pragma unroll
    for (int kt = 0; kt < 3; kt++) {
        unsigned pa[3][4];
#pragma unroll
        for (int mt = 0; mt < 3; mt++) {
            pa[mt][0] = h2u(s[mt][2 * kt][0],     s[mt][2 * kt][1]);
            pa[mt][1] = h2u(s[mt][2 * kt][2],     s[mt][2 * kt][3]);
            pa[mt][2] = h2u(s[mt][2 * kt + 1][0], s[mt][2 * kt + 1][1]);
            pa[mt][3] = h2u(s[mt][2 * kt + 1][2], s[mt][2 * kt + 1][3]);
        }
#pragma unroll
        for (int nt = 0; nt < 2; nt++) {
            const __half* vb = Vt + (nt * 8 + g) * 56 + kt * 16 + 2 * t;
            unsigned b0 = *(const unsigned*)vb;
            unsigned b1 = *(const unsigned*)(vb + 8);
            MMA16(o[0][nt], pa[0], b0, b1);
            MMA16(o[1][nt], pa[1], b0, b1);
            MMA16(o[2][nt], pa[2], b0, b1);
        }
    }

#pragma unroll
    for (int mt = 0; mt < 3; mt++)
#pragma unroll
        for (int nt = 0; nt < 2; nt++) {
            long tok = base + (long)(mt * 16 + g) * stride;
            size_t ob = (size_t)tok * 384 + (size_t)axis * 128 + h * 16 + nt * 8 + 2 * t;
            *(__half2*)(g_o + ob) = __floats2half2_rn(o[mt][nt][0], o[mt][nt][1]);
            *(__half2*)(g_o + ob + (size_t)(8 * stride) * 384) =
                __floats2half2_rn(o[mt][nt][2], o[mt][nt][3]);
        }
}

// ---------------------------------------------------------------------------
// launch
// ---------------------------------------------------------------------------
extern "C" void kernel_launch(void* const* d_in, const int* in_sizes, int n_in,
                              void* d_out, int out_size)
{
    (void)in_sizes; (void)n_in; (void)out_size;
    const float* x    = (const float*)d_in[0];
    const float* px   = (const float*)d_in[1];
    const float* py   = (const float*)d_in[2];
    const float* pz   = (const float*)d_in[3];
    const float* ln_g = (const float*)d_in[16];
    const float* ln_b = (const float*)d_in[17];
    const float* b1   = (const float*)d_in[19];
    const float* b2   = (const float*)d_in[21];

    cudaFuncSetAttribute((const void*)gemm_kernel,
                         cudaFuncAttributeMaxDynamicSharedMemorySize, GEMM_SMEM);
    cudaFuncSetAttribute((const void*)attn_kernel,
                         cudaFuncAttributeMaxDynamicSharedMemorySize, ATTN_SMEM);

    WP wp;
    for (int a = 0; a < 3; a++) {
        wp.wq[a]   = (const float*)d_in[4 + 4 * a];
        wp.wkv[a]  = (const float*)d_in[5 + 4 * a];
        wp.wout[a] = (const float*)d_in[6 + 4 * a];
    }
    wp.w1 = (const float*)d_in[18];
    wp.w2 = (const float*)d_in[20];
    wconv_kernel<<<896, 256>>>(wp);

    prep_kernel<<<NT / 64, 256>>>(x, px, py, pz);

    GP q = {}; q.mode = 0;
    gemm_kernel<<<dim3(9, NT / 128), 256, GEMM_SMEM>>>(q);

    attn_kernel<<<dim3(4608, 3), 256, ATTN_SMEM>>>();

    GP op = {}; op.mode = 1;
    op.bias0 = (const float*)d_in[7];
    op.bias1 = (const float*)d_in[11];
    op.bias2 = (const float*)d_in[15];
    op.lng = ln_g; op.lnb = ln_b;
    gemm_kernel<<<NT / 128, 256, GEMM_SMEM>>>(op);

    GP m1 = {}; m1.mode = 2; m1.bias0 = b1;
    gemm_kernel<<<NT / 128, 256, GEMM_SMEM>>>(m1);

    GP m2 = {}; m2.mode = 3; m2.bias0 = b2;
    m2.lng = ln_g; m2.lnb = ln_b; m2.out = (float*)d_out;
    gemm_kernel<<<NT / 128, 256, GEMM_SMEM>>>(m2);
}

// round 5
// speedup vs baseline: 9.2060x; 1.0699x over previous
#include <cuda_runtime.h>
#include <cuda_fp16.h>

// Problem constants
#define SS   110592          // 48^3
#define NT   221184          // NB*SS tokens
#define QKVW 1152            // 3 axes * (q,k,v) * 128

// Scratch (device globals; no allocation allowed) — all intermediates fp16
__device__ __half g_xe [NT * 128];            // pos-embedded input (residual 1)
__device__ __half g_qkv[(size_t)NT * QKVW];   // q/k/v, 3 axes
__device__ __half g_o  [(size_t)NT * 384];    // attention outputs, 3 axes
__device__ __half g_ln [NT * 128];            // LN1 output (residual 2)
__device__ __half g_h  [NT * 128];            // MLP hidden
// fp16 weights: [0,147456) qkv strips (9 x 128x128), [147456,196608) wout_cat
// (128 rows x 384), [196608,212992) w1, [212992,229376) w2
__device__ __half g_wh [229376];

// ---------------------------------------------------------------------------
// helpers
// ---------------------------------------------------------------------------
__device__ __forceinline__ void cpa16_s(unsigned d, const void* s) {
    asm volatile("cp.async.cg.shared.global [%0], [%1], 16;" :: "r"(d), "l"(s));
}
#define CP_COMMIT() asm volatile("cp.async.commit_group;")
#define CP_WAIT1()  asm volatile("cp.async.wait_group 1;")
#define CP_WAIT0()  asm volatile("cp.async.wait_group 0;")

#define LDSM4(r, addr) \
    asm volatile("ldmatrix.sync.aligned.m8n8.x4.shared.b16 {%0,%1,%2,%3}, [%4];" \
        : "=r"((r)[0]), "=r"((r)[1]), "=r"((r)[2]), "=r"((r)[3]) : "r"(addr))

#define LDSM4T(r, addr) \
    asm volatile("ldmatrix.sync.aligned.m8n8.x4.trans.shared.b16 {%0,%1,%2,%3}, [%4];" \
        : "=r"((r)[0]), "=r"((r)[1]), "=r"((r)[2]), "=r"((r)[3]) : "r"(addr))

#define MMA16(d, a, b0, b1) \
    asm volatile("mma.sync.aligned.m16n8k16.row.col.f32.f16.f16.f32 " \
        "{%0,%1,%2,%3}, {%4,%5,%6,%7}, {%8,%9}, {%0,%1,%2,%3};" \
        : "+f"((d)[0]), "+f"((d)[1]), "+f"((d)[2]), "+f"((d)[3]) \
        : "r"((a)[0]), "r"((a)[1]), "r"((a)[2]), "r"((a)[3]), \
          "r"(b0), "r"(b1))

__device__ __forceinline__ unsigned h2u(float x, float y) {
    __half2 h = __floats2half2_rn(x, y);
    return *(unsigned*)&h;
}

// ---------------------------------------------------------------------------
// weight convert: fp32 -> fp16 buffer, one-time layout
// ---------------------------------------------------------------------------
struct WP {
    const float* wq[3]; const float* wkv[3]; const float* wout[3];
    const float* w1; const float* w2;
};
__global__ __launch_bounds__(256) void wconv_kernel(WP p)
{
    int idx = blockIdx.x * 256 + threadIdx.x;
    if (idx >= 229376) return;
    float v;
    if (idx < 147456) {
        int strip = idx >> 14, rem = idx & 16383;
        int a = strip / 3, r = strip - a * 3;
        v = (r == 0) ? p.wq[a][rem] : p.wkv[a][(r - 1) * 16384 + rem];
    } else if (idx < 196608) {
        int rem = idx - 147456;
        int n = rem / 384, k = rem - n * 384;
        v = p.wout[k >> 7][n * 128 + (k & 127)];
    } else if (idx < 212992) v = p.w1[idx - 196608];
    else                     v = p.w2[idx - 212992];
    g_wh[idx] = __float2half(v);
}

// ---------------------------------------------------------------------------
// prep: xe = 2*x + px + py + pz, transpose (B,C,S) -> (token, C), fp16
// ---------------------------------------------------------------------------
__global__ __launch_bounds__(256) void prep_kernel(
    const float* __restrict__ x,  const float* __restrict__ px,
    const float* __restrict__ py, const float* __restrict__ pz)
{
    __shared__ float tile[64][129];
    int base = blockIdx.x * 64;
    int b    = base / SS;
    int sp0  = base % SS;

    for (int e = threadIdx.x; e < 64 * 128; e += 256) {
        int c = e >> 6;
        int s = e & 63;
        int spatial = sp0 + s;
        int zi = spatial % 48;
        int yi = (spatial / 48) % 48;
        int xi = spatial / 2304;
        tile[s][c] = 2.0f * x[(size_t)b * 128 * SS + (size_t)c * SS + spatial]
                   + px[c * 48 + xi] + py[c * 48 + yi] + pz[c * 48 + zi];
    }
    __syncthreads();
    for (int e = threadIdx.x; e < 64 * 128; e += 256) {
        int s = e >> 7;
        int c = e & 127;
        g_xe[(size_t)(base + s) * 128 + c] = __float2half(tile[s][c]);
    }
}

// ---------------------------------------------------------------------------
// fp16 GEMM: C[Mx128] = A[MxK] @ B^T, ldmatrix + m16n8k16, fused epilogues.
// modes: 0=qkv (blockIdx.x=strip, blockIdx.y=mtile), 1=outproj+res+LN1,
// 2=mlp1 relu, 3=mlp2+res+LN2+transposed fp32 store
// ---------------------------------------------------------------------------
struct GP {
    const float *bias0, *bias1, *bias2, *lng, *lnb;
    float* out;
    int mode;
};

#define GEMM_SMEM 68096

__global__ __launch_bounds__(256, 2) void gemm_kernel(GP p)
{
    extern __shared__ __align__(16) char smc[];
    unsigned sA = (unsigned)__cvta_generic_to_shared(smc);
    unsigned sB = sA + 32768;

    int tid = threadIdx.x, w = tid >> 5, lane = tid & 31;
    int mw = w & 3, nw = w >> 2;
    int g = lane >> 2, t = lane & 3;

    long m0; const __half* Ap; const __half* Bp;
    int lda, ldb, NC;
    if (p.mode == 0) {
        m0 = (long)blockIdx.y * 128;
        Ap = g_xe; lda = 128;
        Bp = g_wh + (size_t)blockIdx.x * 16384; ldb = 128; NC = 2;
    } else if (p.mode == 1) {
        m0 = (long)blockIdx.x * 128;
        Ap = g_o; lda = 384;
        Bp = g_wh + 147456; ldb = 384; NC = 6;
    } else if (p.mode == 2) {
        m0 = (long)blockIdx.x * 128;
        Ap = g_ln; lda = 128;
        Bp = g_wh + 196608; ldb = 128; NC = 2;
    } else {
        m0 = (long)blockIdx.x * 128;
        Ap = g_h; lda = 128;
        Bp = g_wh + 212992; ldb = 128; NC = 2;
    }

#define STAGE(c, buf) do {                                                    \
        int k0_ = (c) * 64;                                                   \
        _Pragma("unroll")                                                     \
        for (int i_ = 0; i_ < 4; i_++) {                                      \
            int idx_ = tid + 256 * i_;                                        \
            int row_ = idx_ >> 3, seg_ = idx_ & 7;                            \
            unsigned dcol_ = (unsigned)((seg_ * 16) ^ ((row_ & 7) << 4));     \
            cpa16_s(sA + (buf) * 16384 + row_ * 128 + dcol_,                  \
                    Ap + (m0 + row_) * (size_t)lda + k0_ + seg_ * 8);         \
            cpa16_s(sB + (buf) * 16384 + row_ * 128 + dcol_,                  \
                    Bp + (size_t)row_ * ldb + k0_ + seg_ * 8);                \
        }                                                                     \
    } while (0)

    float acc[2][8][4];
#pragma unroll
    for (int mt = 0; mt < 2; mt++)
#pragma unroll
        for (int nt = 0; nt < 8; nt++)
#pragma unroll
            for (int i = 0; i < 4; i++) acc[mt][nt][i] = 0.f;

    STAGE(0, 0); CP_COMMIT();

    int rowA  = mw * 32 + (lane & 15);
    int rowB0 = nw * 64 + ((lane & 16) >> 1) + (lane & 7);
    unsigned hiA = (unsigned)((lane >> 4) << 4);
    unsigned hiB = (unsigned)(((lane >> 3) & 1) << 4);
    unsigned xA = (unsigned)((rowA & 7) << 4);
    unsigned xB = (unsigned)((rowB0 & 7) << 4);

    for (int c = 0; c < NC; c++) {
        if (c + 1 < NC) { STAGE(c + 1, (c + 1) & 1); CP_COMMIT(); CP_WAIT1(); }
        else            { CP_WAIT0(); }
        __syncthreads();
        unsigned baseA = sA + (c & 1) * 16384;
        unsigned baseB = sB + (c & 1) * 16384;
#pragma unroll
        for (int kt = 0; kt < 4; kt++) {
            unsigned a[2][4];
#pragma unroll
            for (int mt = 0; mt < 2; mt++) {
                unsigned adr = baseA + (rowA + mt * 16) * 128
                             + (((unsigned)(kt * 32) + hiA) ^ xA);
                LDSM4(a[mt], adr);
            }
#pragma unroll
            for (int np = 0; np < 4; np++) {
                unsigned adr = baseB + (rowB0 + np * 16) * 128
                             + (((unsigned)(kt * 32) + hiB) ^ xB);
                unsigned b[4];
                LDSM4(b, adr);
                MMA16(acc[0][2 * np],     a[0], b[0], b[1]);
                MMA16(acc[1][2 * np],     a[1], b[0], b[1]);
                MMA16(acc[0][2 * np + 1], a[0], b[2], b[3]);
                MMA16(acc[1][2 * np + 1], a[1], b[2], b[3]);
            }
        }
        __syncthreads();
    }
#undef STAGE

    // ---- epilogues ----
    if (p.mode == 0) {
        size_t ocol = (size_t)blockIdx.x * 128;
#pragma unroll
        for (int mt = 0; mt < 2; mt++)
#pragma unroll
            for (int nt = 0; nt < 8; nt++) {
                size_t tok = m0 + mw * 32 + mt * 16 + g;
                int cc = nw * 64 + nt * 8 + 2 * t;
                *(__half2*)(g_qkv + tok * QKVW + ocol + cc) =
                    __floats2half2_rn(acc[mt][nt][0], acc[mt][nt][1]);
                *(__half2*)(g_qkv + (tok + 8) * QKVW + ocol + cc) =
                    __floats2half2_rn(acc[mt][nt][2], acc[mt][nt][3]);
            }
        return;
    }
    if (p.mode == 2) {
#pragma unroll
        for (int mt = 0; mt < 2; mt++)
#pragma unroll
            for (int nt = 0; nt < 8; nt++) {
                size_t tok = m0 + mw * 32 + mt * 16 + g;
                int cc = nw * 64 + nt * 8 + 2 * t;
                float b0 = p.bias0[cc], b1 = p.bias0[cc + 1];
                *(__half2*)(g_h + tok * 128 + cc) =
                    __floats2half2_rn(fmaxf(acc[mt][nt][0] + b0, 0.f),
                                      fmaxf(acc[mt][nt][1] + b1, 0.f));
                *(__half2*)(g_h + (tok + 8) * 128 + cc) =
                    __floats2half2_rn(fmaxf(acc[mt][nt][2] + b0, 0.f),
                                      fmaxf(acc[mt][nt][3] + b1, 0.f));
            }
        return;
    }

    // modes 1/3: residual add in fp32 Ct (reuses smem), LN rows, store
    const int CS = (p.mode == 3) ? 133 : 132;
    float* Ct = (float*)smc;
    const __half* res = (p.mode == 1) ? g_xe : g_ln;
#pragma unroll
    for (int mt = 0; mt < 2; mt++)
#pragma unroll
        for (int nt = 0; nt < 8; nt++) {
            int rl = mw * 32 + mt * 16 + g;
            int cc = nw * 64 + nt * 8 + 2 * t;
            size_t tok = m0 + rl;
            float b0, b1;
            if (p.mode == 1) {
                b0 = p.bias0[cc] + p.bias1[cc] + p.bias2[cc];
                b1 = p.bias0[cc + 1] + p.bias1[cc + 1] + p.bias2[cc + 1];
            } else {
                b0 = p.bias0[cc]; b1 = p.bias0[cc + 1];
            }
            Ct[rl * CS + cc]     = acc[mt][nt][0] + b0 + __half2float(res[tok * 128 + cc]);
            Ct[rl * CS + cc + 1] = acc[mt][nt][1] + b1 + __half2float(res[tok * 128 + cc + 1]);
            Ct[(rl + 8) * CS + cc]     = acc[mt][nt][2] + b0 + __half2float(res[(tok + 8) * 128 + cc]);
            Ct[(rl + 8) * CS + cc + 1] = acc[mt][nt][3] + b1 + __half2float(res[(tok + 8) * 128 + cc + 1]);
        }
    __syncthreads();

    for (int r = w; r < 128; r += 8) {
        float v[4], s = 0.f, s2 = 0.f;
#pragma unroll
        for (int k = 0; k < 4; k++) {
            v[k] = Ct[r * CS + lane + 32 * k];
            s += v[k]; s2 += v[k] * v[k];
        }
        for (int off = 16; off; off >>= 1) {
            s  += __shfl_xor_sync(0xffffffffu, s,  off);
            s2 += __shfl_xor_sync(0xffffffffu, s2, off);
        }
        float m   = s * (1.f / 128.f);
        float var = s2 * (1.f / 128.f) - m * m;
        float inv = rsqrtf(var + 1e-5f);
#pragma unroll
        for (int k = 0; k < 4; k++) {
            int cc = lane + 32 * k;
            float y = (v[k] - m) * inv * p.lng[cc] + p.lnb[cc];
            if (p.mode == 1) g_ln[(m0 + r) * 128 + cc] = __float2half(y);
            else             Ct[r * CS + cc] = y;
        }
    }
    if (p.mode == 3) {
        __syncthreads();
        int  bi  = (int)(m0 / SS);
        long sp0 = m0 % SS;
        float* outp = p.out + (size_t)bi * 128 * SS + sp0;
        for (int e = tid; e < 128 * 128; e += 256) {
            int cc = e >> 7, ss = e & 127;
            outp[(size_t)cc * SS + ss] = Ct[ss * 133 + cc];
        }
    }
}

// ---------------------------------------------------------------------------
// attention v2: grid (4608, 3); warp = head.
// CTA-cooperative coalesced staging of q/k/v (768B per token row), ldmatrix
// fragments (trans for V), register softmax, smem-staged coalesced O write.
// smem layout (halves): kind k in {q,k,v} at k*9344, head h at +h*1168,
// token row stride 24 (48B => conflict-free ldmatrix). O tile aliases q/k.
// ---------------------------------------------------------------------------
#define ATTN_SMEM 56064

__global__ __launch_bounds__(256, 2) void attn_kernel()
{
    extern __shared__ __align__(16) __half smh[];
    unsigned sbase = (unsigned)__cvta_generic_to_shared(smh);
    int tid = threadIdx.x, w = tid >> 5, lane = tid & 31;
    int g = lane >> 2, t = lane & 3, h = w;

    int axis = blockIdx.y, seq = blockIdx.x;
    int b = seq / 2304, rr = seq % 2304;
    int o1 = rr / 48, o2 = rr % 48;
    long base; int stride;
    if (axis == 0)      { base = (long)b * SS + o1 * 48 + o2;        stride = 2304; }
    else if (axis == 1) { base = (long)b * SS + o1 * 2304 + o2;      stride = 48;   }
    else                { base = (long)b * SS + o1 * 2304 + o2 * 48; stride = 1;    }

    // ---- cooperative staging: 48 rows x 48 chunks of 16B ----
#pragma unroll
    for (int it = 0; it < 9; it++) {
        int idx  = tid + it * 256;
        int row  = idx / 48;
        int c    = idx - row * 48;
        int kind = c >> 4;
        int hh   = (c >> 1) & 7;
        int lo   = c & 1;
        unsigned dst = sbase + (unsigned)(kind * 9344 + hh * 1168 + row * 24 + lo * 8) * 2;
        const __half* src = g_qkv + (size_t)(base + (long)row * stride) * QKVW
                          + axis * 384 + c * 8;
        cpa16_s(dst, src);
    }
    CP_COMMIT(); CP_WAIT0();
    __syncthreads();

    unsigned Qb = sbase + (unsigned)(h * 1168) * 2;
    unsigned Kb = Qb + 9344u * 2;
    unsigned Vb = Qb + 18688u * 2;

    // ---- scores S = Q @ K^T : M=48, N=48, K=16 ----
    float s[3][6][4];
#pragma unroll
    for (int mt = 0; mt < 3; mt++)
#pragma unroll
        for (int nt = 0; nt < 6; nt++)
#pragma unroll
            for (int i = 0; i < 4; i++) s[mt][nt][i] = 0.f;

    {
        unsigned a[3][4];
#pragma unroll
        for (int mt = 0; mt < 3; mt++)
            LDSM4(a[mt], Qb + (unsigned)((mt * 16 + (lane & 15)) * 24
                                         + ((lane >> 4) << 3)) * 2);
#pragma unroll
        for (int nt2 = 0; nt2 < 3; nt2++) {
            unsigned bb[4];
            LDSM4(bb, Kb + (unsigned)((nt2 * 16 + ((lane & 16) >> 1) + (lane & 7)) * 24
                                      + (((lane >> 3) & 1) << 3)) * 2);
#pragma unroll
            for (int mt = 0; mt < 3; mt++) {
                MMA16(s[mt][2 * nt2],     a[mt], bb[0], bb[1]);
                MMA16(s[mt][2 * nt2 + 1], a[mt], bb[2], bb[3]);
            }
        }
    }

    // ---- softmax over j (scale 0.25 = e^-0.5); rows live on lane quads ----
#pragma unroll
    for (int mt = 0; mt < 3; mt++)
#pragma unroll
        for (int hi = 0; hi < 2; hi++) {
            float mx = -1e30f;
#pragma unroll
            for (int nt = 0; nt < 6; nt++) {
                s[mt][nt][hi * 2]     *= 0.25f;
                s[mt][nt][hi * 2 + 1] *= 0.25f;
                mx = fmaxf(mx, fmaxf(s[mt][nt][hi * 2], s[mt][nt][hi * 2 + 1]));
            }
            mx = fmaxf(mx, __shfl_xor_sync(0xffffffffu, mx, 1));
            mx = fmaxf(mx, __shfl_xor_sync(0xffffffffu, mx, 2));
            float sum = 0.f;
#pragma unroll
            for (int nt = 0; nt < 6; nt++)
#pragma unroll
                for (int lo = 0; lo < 2; lo++) {
                    float e = __expf(s[mt][nt][hi * 2 + lo] - mx);
                    s[mt][nt][hi * 2 + lo] = e;
                    sum += e;
                }
            sum += __shfl_xor_sync(0xffffffffu, sum, 1);
            sum += __shfl_xor_sync(0xffffffffu, sum, 2);
            float inv = 1.f / sum;
#pragma unroll
            for (int nt = 0; nt < 6; nt++) {
                s[mt][nt][hi * 2]     *= inv;
                s[mt][nt][hi * 2 + 1] *= inv;
            }
        }

    // ---- O = P @ V : M=48, N=16, K=48; V B-frags via ldmatrix.trans ----
    float o[3][2][4];
#pragma unroll
    for (int mt = 0; mt < 3; mt++)
#pragma unroll
        for (int nt = 0; nt < 2; nt++)
#pragma unroll
            for (int i = 0; i < 4; i++) o[mt][nt][i] = 0.f;

#pragma unroll
    for (int kt = 0; kt < 3; kt++) {
        unsigned vb[4];
        LDSM4T(vb, Vb + (unsigned)((kt * 16 + (lane & 15)) * 24
                                   + ((lane >> 4) << 3)) * 2);
        unsigned pa[3][4];
#pragma unroll
        for (int mt = 0; mt < 3; mt++) {
            pa[mt][0] = h2u(s[mt][2 * kt][0],     s[mt][2 * kt][1]);
            pa[mt][1] = h2u(s[mt][2 * kt][2],     s[mt][2 * kt][3]);
            pa[mt][2] = h2u(s[mt][2 * kt + 1][0], s[mt][2 * kt + 1][1]);
            pa[mt][3] = h2u(s[mt][2 * kt + 1][2], s[mt][2 * kt + 1][3]);
        }
#pragma unroll
        for (int mt = 0; mt < 3; mt++) {
            MMA16(o[mt][0], pa[mt], vb[0], vb[1]);
            MMA16(o[mt][1], pa[mt], vb[2], vb[3]);
        }
    }

    // ---- stage O in smem (aliases q/k regions), then coalesced store ----
    __syncthreads();
#pragma unroll
    for (int mt = 0; mt < 3; mt++)
#pragma unroll
        for (int nt = 0; nt < 2; nt++) {
            int col = h * 16 + nt * 8 + 2 * t;
            int r0 = mt * 16 + g;
            *(__half2*)(smh + r0 * 136 + col) =
                __floats2half2_rn(o[mt][nt][0], o[mt][nt][1]);
            *(__half2*)(smh + (r0 + 8) * 136 + col) =
                __floats2half2_rn(o[mt][nt][2], o[mt][nt][3]);
        }
    __syncthreads();

#pragma unroll
    for (int it = 0; it < 3; it++) {
        int idx = tid + it * 256;
        int row = idx >> 4, c = idx & 15;
        *(uint4*)(g_o + (size_t)(base + (long)row * stride) * 384
                  + axis * 128 + c * 8) = *(const uint4*)(smh + row * 136 + c * 8);
    }
}

// ---------------------------------------------------------------------------
// launch
// ---------------------------------------------------------------------------
extern "C" void kernel_launch(void* const* d_in, const int* in_sizes, int n_in,
                              void* d_out, int out_size)
{
    (void)in_sizes; (void)n_in; (void)out_size;
    const float* x    = (const float*)d_in[0];
    const float* px   = (const float*)d_in[1];
    const float* py   = (const float*)d_in[2];
    const float* pz   = (const float*)d_in[3];
    const float* ln_g = (const float*)d_in[16];
    const float* ln_b = (const float*)d_in[17];
    const float* b1   = (const float*)d_in[19];
    const float* b2   = (const float*)d_in[21];

    cudaFuncSetAttribute((const void*)gemm_kernel,
                         cudaFuncAttributeMaxDynamicSharedMemorySize, GEMM_SMEM);
    cudaFuncSetAttribute((const void*)attn_kernel,
                         cudaFuncAttributeMaxDynamicSharedMemorySize, ATTN_SMEM);

    WP wp;
    for (int a = 0; a < 3; a++) {
        wp.wq[a]   = (const float*)d_in[4 + 4 * a];
        wp.wkv[a]  = (const float*)d_in[5 + 4 * a];
        wp.wout[a] = (const float*)d_in[6 + 4 * a];
    }
    wp.w1 = (const float*)d_in[18];
    wp.w2 = (const float*)d_in[20];
    wconv_kernel<<<896, 256>>>(wp);

    prep_kernel<<<NT / 64, 256>>>(x, px, py, pz);

    GP q = {}; q.mode = 0;
    gemm_kernel<<<dim3(9, NT / 128), 256, GEMM_SMEM>>>(q);

    attn_kernel<<<dim3(4608, 3), 256, ATTN_SMEM>>>();

    GP op = {}; op.mode = 1;
    op.bias0 = (const float*)d_in[7];
    op.bias1 = (const float*)d_in[11];
    op.bias2 = (const float*)d_in[15];
    op.lng = ln_g; op.lnb = ln_b;
    gemm_kernel<<<NT / 128, 256, GEMM_SMEM>>>(op);

    GP m1 = {}; m1.mode = 2; m1.bias0 = b1;
    gemm_kernel<<<NT / 128, 256, GEMM_SMEM>>>(m1);

    GP m2 = {}; m2.mode = 3; m2.bias0 = b2;
    m2.lng = ln_g; m2.lnb = ln_b; m2.out = (float*)d_out;
    gemm_kernel<<<NT / 128, 256, GEMM_SMEM>>>(m2);
}

// round 6
// speedup vs baseline: 9.5065x; 1.0326x over previous
#include <cuda_runtime.h>
#include <cuda_fp16.h>

// Problem constants
#define SS   110592          // 48^3
#define NT   221184          // NB*SS tokens
#define QKVW 1152            // 3 axes * (q,k,v) * 128

// Scratch (device globals; no allocation allowed) — all intermediates fp16
__device__ __half g_xe [NT * 128];            // pos-embedded input (residual 1)
__device__ __half g_qkv[(size_t)NT * QKVW];   // q/k/v, 3 axes
__device__ __half g_o  [(size_t)NT * 384];    // attention outputs, 3 axes
__device__ __half g_ln [NT * 128];            // LN1 output (residual 2)
__device__ __half g_h  [NT * 128];            // MLP hidden
// fp16 weights: [0,147456) qkv strips (9 x 128x128), [147456,196608) wout_cat
// (128 rows x 384), [196608,212992) w1, [212992,229376) w2
__device__ __half g_wh [229376];

// ---------------------------------------------------------------------------
// helpers
// ---------------------------------------------------------------------------
__device__ __forceinline__ void cpa16_s(unsigned d, const void* s) {
    asm volatile("cp.async.cg.shared.global [%0], [%1], 16;" :: "r"(d), "l"(s));
}
#define CP_COMMIT() asm volatile("cp.async.commit_group;")
#define CP_WAIT1()  asm volatile("cp.async.wait_group 1;")
#define CP_WAIT0()  asm volatile("cp.async.wait_group 0;")

#define LDSM4(r, addr) \
    asm volatile("ldmatrix.sync.aligned.m8n8.x4.shared.b16 {%0,%1,%2,%3}, [%4];" \
        : "=r"((r)[0]), "=r"((r)[1]), "=r"((r)[2]), "=r"((r)[3]) : "r"(addr))

#define LDSM4T(r, addr) \
    asm volatile("ldmatrix.sync.aligned.m8n8.x4.trans.shared.b16 {%0,%1,%2,%3}, [%4];" \
        : "=r"((r)[0]), "=r"((r)[1]), "=r"((r)[2]), "=r"((r)[3]) : "r"(addr))

#define MMA16(d, a, b0, b1) \
    asm volatile("mma.sync.aligned.m16n8k16.row.col.f32.f16.f16.f32 " \
        "{%0,%1,%2,%3}, {%4,%5,%6,%7}, {%8,%9}, {%0,%1,%2,%3};" \
        : "+f"((d)[0]), "+f"((d)[1]), "+f"((d)[2]), "+f"((d)[3]) \
        : "r"((a)[0]), "r"((a)[1]), "r"((a)[2]), "r"((a)[3]), \
          "r"(b0), "r"(b1))

__device__ __forceinline__ unsigned h2u(float x, float y) {
    __half2 h = __floats2half2_rn(x, y);
    return *(unsigned*)&h;
}

// ---------------------------------------------------------------------------
// weight convert: fp32 -> fp16 buffer, one-time layout
// ---------------------------------------------------------------------------
struct WP {
    const float* wq[3]; const float* wkv[3]; const float* wout[3];
    const float* w1; const float* w2;
};
__global__ __launch_bounds__(256) void wconv_kernel(WP p)
{
    int idx = blockIdx.x * 256 + threadIdx.x;
    if (idx >= 229376) return;
    float v;
    if (idx < 147456) {
        int strip = idx >> 14, rem = idx & 16383;
        int a = strip / 3, r = strip - a * 3;
        v = (r == 0) ? p.wq[a][rem] : p.wkv[a][(r - 1) * 16384 + rem];
    } else if (idx < 196608) {
        int rem = idx - 147456;
        int n = rem / 384, k = rem - n * 384;
        v = p.wout[k >> 7][n * 128 + (k & 127)];
    } else if (idx < 212992) v = p.w1[idx - 196608];
    else                     v = p.w2[idx - 212992];
    g_wh[idx] = __float2half(v);
}

// ---------------------------------------------------------------------------
// prep: xe = 2*x + px + py + pz, transpose (B,C,S) -> (token, C), fp16
// ---------------------------------------------------------------------------
__global__ __launch_bounds__(256) void prep_kernel(
    const float* __restrict__ x,  const float* __restrict__ px,
    const float* __restrict__ py, const float* __restrict__ pz)
{
    __shared__ float tile[64][129];
    int base = blockIdx.x * 64;
    int b    = base / SS;
    int sp0  = base % SS;

    for (int e = threadIdx.x; e < 64 * 128; e += 256) {
        int c = e >> 6;
        int s = e & 63;
        int spatial = sp0 + s;
        int zi = spatial % 48;
        int yi = (spatial / 48) % 48;
        int xi = spatial / 2304;
        tile[s][c] = 2.0f * x[(size_t)b * 128 * SS + (size_t)c * SS + spatial]
                   + px[c * 48 + xi] + py[c * 48 + yi] + pz[c * 48 + zi];
    }
    __syncthreads();
    for (int e = threadIdx.x; e < 64 * 128; e += 256) {
        int s = e >> 7;
        int c = e & 127;
        g_xe[(size_t)(base + s) * 128 + c] = __float2half(tile[s][c]);
    }
}

// ---------------------------------------------------------------------------
// fp16 GEMM: C[Mx128] = A[MxK] @ B^T, ldmatrix + m16n8k16, fused epilogues.
// modes: 0=qkv (blockIdx.x=strip, blockIdx.y=mtile), 1=outproj+res+LN1,
// 2=mlp1 relu, 3=mlp2+res+LN2+transposed fp32 store
// ---------------------------------------------------------------------------
struct GP {
    const float *bias0, *bias1, *bias2, *lng, *lnb;
    float* out;
    int mode;
};

#define GEMM_SMEM 68096

__global__ __launch_bounds__(256, 2) void gemm_kernel(GP p)
{
    extern __shared__ __align__(16) char smc[];
    unsigned sA = (unsigned)__cvta_generic_to_shared(smc);
    unsigned sB = sA + 32768;

    int tid = threadIdx.x, w = tid >> 5, lane = tid & 31;
    int mw = w & 3, nw = w >> 2;
    int g = lane >> 2, t = lane & 3;

    long m0; const __half* Ap; const __half* Bp;
    int lda, ldb, NC;
    if (p.mode == 0) {
        m0 = (long)blockIdx.y * 128;
        Ap = g_xe; lda = 128;
        Bp = g_wh + (size_t)blockIdx.x * 16384; ldb = 128; NC = 2;
    } else if (p.mode == 1) {
        m0 = (long)blockIdx.x * 128;
        Ap = g_o; lda = 384;
        Bp = g_wh + 147456; ldb = 384; NC = 6;
    } else if (p.mode == 2) {
        m0 = (long)blockIdx.x * 128;
        Ap = g_ln; lda = 128;
        Bp = g_wh + 196608; ldb = 128; NC = 2;
    } else {
        m0 = (long)blockIdx.x * 128;
        Ap = g_h; lda = 128;
        Bp = g_wh + 212992; ldb = 128; NC = 2;
    }

#define STAGE(c, buf) do {                                                    \
        int k0_ = (c) * 64;                                                   \
        _Pragma("unroll")                                                     \
        for (int i_ = 0; i_ < 4; i_++) {                                      \
            int idx_ = tid + 256 * i_;                                        \
            int row_ = idx_ >> 3, seg_ = idx_ & 7;                            \
            unsigned dcol_ = (unsigned)((seg_ * 16) ^ ((row_ & 7) << 4));     \
            cpa16_s(sA + (buf) * 16384 + row_ * 128 + dcol_,                  \
                    Ap + (m0 + row_) * (size_t)lda + k0_ + seg_ * 8);         \
            cpa16_s(sB + (buf) * 16384 + row_ * 128 + dcol_,                  \
                    Bp + (size_t)row_ * ldb + k0_ + seg_ * 8);                \
        }                                                                     \
    } while (0)

    float acc[2][8][4];
#pragma unroll
    for (int mt = 0; mt < 2; mt++)
#pragma unroll
        for (int nt = 0; nt < 8; nt++)
#pragma unroll
            for (int i = 0; i < 4; i++) acc[mt][nt][i] = 0.f;

    STAGE(0, 0); CP_COMMIT();

    int rowA  = mw * 32 + (lane & 15);
    int rowB0 = nw * 64 + ((lane & 16) >> 1) + (lane & 7);
    unsigned hiA = (unsigned)((lane >> 4) << 4);
    unsigned hiB = (unsigned)(((lane >> 3) & 1) << 4);
    unsigned xA = (unsigned)((rowA & 7) << 4);
    unsigned xB = (unsigned)((rowB0 & 7) << 4);

    for (int c = 0; c < NC; c++) {
        if (c + 1 < NC) { STAGE(c + 1, (c + 1) & 1); CP_COMMIT(); CP_WAIT1(); }
        else            { CP_WAIT0(); }
        __syncthreads();
        unsigned baseA = sA + (c & 1) * 16384;
        unsigned baseB = sB + (c & 1) * 16384;
#pragma unroll
        for (int kt = 0; kt < 4; kt++) {
            unsigned a[2][4];
#pragma unroll
            for (int mt = 0; mt < 2; mt++) {
                unsigned adr = baseA + (rowA + mt * 16) * 128
                             + (((unsigned)(kt * 32) + hiA) ^ xA);
                LDSM4(a[mt], adr);
            }
#pragma unroll
            for (int np = 0; np < 4; np++) {
                unsigned adr = baseB + (rowB0 + np * 16) * 128
                             + (((unsigned)(kt * 32) + hiB) ^ xB);
                unsigned b[4];
                LDSM4(b, adr);
                MMA16(acc[0][2 * np],     a[0], b[0], b[1]);
                MMA16(acc[1][2 * np],     a[1], b[0], b[1]);
                MMA16(acc[0][2 * np + 1], a[0], b[2], b[3]);
                MMA16(acc[1][2 * np + 1], a[1], b[2], b[3]);
            }
        }
        __syncthreads();
    }
#undef STAGE

    // ---- epilogues ----
    if (p.mode == 0) {
        size_t ocol = (size_t)blockIdx.x * 128;
#pragma unroll
        for (int mt = 0; mt < 2; mt++)
#pragma unroll
            for (int nt = 0; nt < 8; nt++) {
                size_t tok = m0 + mw * 32 + mt * 16 + g;
                int cc = nw * 64 + nt * 8 + 2 * t;
                *(__half2*)(g_qkv + tok * QKVW + ocol + cc) =
                    __floats2half2_rn(acc[mt][nt][0], acc[mt][nt][1]);
                *(__half2*)(g_qkv + (tok + 8) * QKVW + ocol + cc) =
                    __floats2half2_rn(acc[mt][nt][2], acc[mt][nt][3]);
            }
        return;
    }
    if (p.mode == 2) {
#pragma unroll
        for (int mt = 0; mt < 2; mt++)
#pragma unroll
            for (int nt = 0; nt < 8; nt++) {
                size_t tok = m0 + mw * 32 + mt * 16 + g;
                int cc = nw * 64 + nt * 8 + 2 * t;
                float b0 = p.bias0[cc], b1 = p.bias0[cc + 1];
                *(__half2*)(g_h + tok * 128 + cc) =
                    __floats2half2_rn(fmaxf(acc[mt][nt][0] + b0, 0.f),
                                      fmaxf(acc[mt][nt][1] + b1, 0.f));
                *(__half2*)(g_h + (tok + 8) * 128 + cc) =
                    __floats2half2_rn(fmaxf(acc[mt][nt][2] + b0, 0.f),
                                      fmaxf(acc[mt][nt][3] + b1, 0.f));
            }
        return;
    }

    // modes 1/3: residual add in fp32 Ct (reuses smem), LN rows, store
    const int CS = (p.mode == 3) ? 133 : 132;
    float* Ct = (float*)smc;
    const __half* res = (p.mode == 1) ? g_xe : g_ln;
#pragma unroll
    for (int mt = 0; mt < 2; mt++)
#pragma unroll
        for (int nt = 0; nt < 8; nt++) {
            int rl = mw * 32 + mt * 16 + g;
            int cc = nw * 64 + nt * 8 + 2 * t;
            size_t tok = m0 + rl;
            float b0, b1;
            if (p.mode == 1) {
                b0 = p.bias0[cc] + p.bias1[cc] + p.bias2[cc];
                b1 = p.bias0[cc + 1] + p.bias1[cc + 1] + p.bias2[cc + 1];
            } else {
                b0 = p.bias0[cc]; b1 = p.bias0[cc + 1];
            }
            Ct[rl * CS + cc]     = acc[mt][nt][0] + b0 + __half2float(res[tok * 128 + cc]);
            Ct[rl * CS + cc + 1] = acc[mt][nt][1] + b1 + __half2float(res[tok * 128 + cc + 1]);
            Ct[(rl + 8) * CS + cc]     = acc[mt][nt][2] + b0 + __half2float(res[(tok + 8) * 128 + cc]);
            Ct[(rl + 8) * CS + cc + 1] = acc[mt][nt][3] + b1 + __half2float(res[(tok + 8) * 128 + cc + 1]);
        }
    __syncthreads();

    for (int r = w; r < 128; r += 8) {
        float v[4], s = 0.f, s2 = 0.f;
#pragma unroll
        for (int k = 0; k < 4; k++) {
            v[k] = Ct[r * CS + lane + 32 * k];
            s += v[k]; s2 += v[k] * v[k];
        }
        for (int off = 16; off; off >>= 1) {
            s  += __shfl_xor_sync(0xffffffffu, s,  off);
            s2 += __shfl_xor_sync(0xffffffffu, s2, off);
        }
        float m   = s * (1.f / 128.f);
        float var = s2 * (1.f / 128.f) - m * m;
        float inv = rsqrtf(var + 1e-5f);
#pragma unroll
        for (int k = 0; k < 4; k++) {
            int cc = lane + 32 * k;
            float y = (v[k] - m) * inv * p.lng[cc] + p.lnb[cc];
            if (p.mode == 1) g_ln[(m0 + r) * 128 + cc] = __float2half(y);
            else             Ct[r * CS + cc] = y;
        }
    }
    if (p.mode == 3) {
        __syncthreads();
        int  bi  = (int)(m0 / SS);
        long sp0 = m0 % SS;
        float* outp = p.out + (size_t)bi * 128 * SS + sp0;
        for (int e = tid; e < 128 * 128; e += 256) {
            int cc = e >> 7, ss = e & 127;
            outp[(size_t)cc * SS + ss] = Ct[ss * 133 + cc];
        }
    }
}

// ---------------------------------------------------------------------------
// attention v3: grid (4608, 3); warp = head.
// Coalesced CTA staging, ldmatrix fragments, max-free exp2 softmax with
// normalization deferred to the O accumulators, smem-staged coalesced O write.
// ---------------------------------------------------------------------------
#define ATTN_SMEM 56064
#define EXP2_SCALE 0.36067376022224085f   // 0.25 * log2(e)

__global__ __launch_bounds__(256, 2) void attn_kernel()
{
    extern __shared__ __align__(16) __half smh[];
    unsigned sbase = (unsigned)__cvta_generic_to_shared(smh);
    int tid = threadIdx.x, w = tid >> 5, lane = tid & 31;
    int g = lane >> 2, t = lane & 3, h = w;

    int axis = blockIdx.y, seq = blockIdx.x;
    int b = seq / 2304, rr = seq % 2304;
    int o1 = rr / 48, o2 = rr % 48;
    long base; int stride;
    if (axis == 0)      { base = (long)b * SS + o1 * 48 + o2;        stride = 2304; }
    else if (axis == 1) { base = (long)b * SS + o1 * 2304 + o2;      stride = 48;   }
    else                { base = (long)b * SS + o1 * 2304 + o2 * 48; stride = 1;    }

    // ---- cooperative staging: 48 rows x 48 chunks of 16B ----
#pragma unroll
    for (int it = 0; it < 9; it++) {
        int idx  = tid + it * 256;
        int row  = idx / 48;
        int c    = idx - row * 48;
        int kind = c >> 4;
        int hh   = (c >> 1) & 7;
        int lo   = c & 1;
        unsigned dst = sbase + (unsigned)(kind * 9344 + hh * 1168 + row * 24 + lo * 8) * 2;
        const __half* src = g_qkv + (size_t)(base + (long)row * stride) * QKVW
                          + axis * 384 + c * 8;
        cpa16_s(dst, src);
    }
    CP_COMMIT(); CP_WAIT0();
    __syncthreads();

    unsigned Qb = sbase + (unsigned)(h * 1168) * 2;
    unsigned Kb = Qb + 9344u * 2;
    unsigned Vb = Qb + 18688u * 2;

    // ---- scores S = Q @ K^T : M=48, N=48, K=16 ----
    float s[3][6][4];
#pragma unroll
    for (int mt = 0; mt < 3; mt++)
#pragma unroll
        for (int nt = 0; nt < 6; nt++)
#pragma unroll
            for (int i = 0; i < 4; i++) s[mt][nt][i] = 0.f;

    {
        unsigned a[3][4];
#pragma unroll
        for (int mt = 0; mt < 3; mt++)
            LDSM4(a[mt], Qb + (unsigned)((mt * 16 + (lane & 15)) * 24
                                         + ((lane >> 4) << 3)) * 2);
#pragma unroll
        for (int nt2 = 0; nt2 < 3; nt2++) {
            unsigned bb[4];
            LDSM4(bb, Kb + (unsigned)((nt2 * 16 + ((lane & 16) >> 1) + (lane & 7)) * 24
                                      + (((lane >> 3) & 1) << 3)) * 2);
#pragma unroll
            for (int mt = 0; mt < 3; mt++) {
                MMA16(s[mt][2 * nt2],     a[mt], bb[0], bb[1]);
                MMA16(s[mt][2 * nt2 + 1], a[mt], bb[2], bb[3]);
            }
        }
    }

    // ---- max-free softmax: e = exp2(s * 0.25*log2e); norm deferred to O ----
    float inv[3][2];
#pragma unroll
    for (int mt = 0; mt < 3; mt++)
#pragma unroll
        for (int hi = 0; hi < 2; hi++) {
            float sum = 0.f;
#pragma unroll
            for (int nt = 0; nt < 6; nt++)
#pragma unroll
                for (int lo = 0; lo < 2; lo++) {
                    float e = exp2f(s[mt][nt][hi * 2 + lo] * EXP2_SCALE);
                    s[mt][nt][hi * 2 + lo] = e;
                    sum += e;
                }
            sum += __shfl_xor_sync(0xffffffffu, sum, 1);
            sum += __shfl_xor_sync(0xffffffffu, sum, 2);
            inv[mt][hi] = 1.f / sum;
        }

    // ---- O = P_unnorm @ V : M=48, N=16, K=48; V B-frags via ldmatrix.trans --
    float o[3][2][4];
#pragma unroll
    for (int mt = 0; mt < 3; mt++)
#pragma unroll
        for (int nt = 0; nt < 2; nt++)
#pragma unroll
            for (int i = 0; i < 4; i++) o[mt][nt][i] = 0.f;

#pragma unroll
    for (int kt = 0; kt < 3; kt++) {
        unsigned vb[4];
        LDSM4T(vb, Vb + (unsigned)((kt * 16 + (lane & 15)) * 24
                                   + ((lane >> 4) << 3)) * 2);
        unsigned pa[3][4];
#pragma unroll
        for (int mt = 0; mt < 3; mt++) {
            pa[mt][0] = h2u(s[mt][2 * kt][0],     s[mt][2 * kt][1]);
            pa[mt][1] = h2u(s[mt][2 * kt][2],     s[mt][2 * kt][3]);
            pa[mt][2] = h2u(s[mt][2 * kt + 1][0], s[mt][2 * kt + 1][1]);
            pa[mt][3] = h2u(s[mt][2 * kt + 1][2], s[mt][2 * kt + 1][3]);
        }
#pragma unroll
        for (int mt = 0; mt < 3; mt++) {
            MMA16(o[mt][0], pa[mt], vb[0], vb[1]);
            MMA16(o[mt][1], pa[mt], vb[2], vb[3]);
        }
    }

    // ---- normalize O, stage in smem (aliases q/k), coalesced store ----
    __syncthreads();
#pragma unroll
    for (int mt = 0; mt < 3; mt++)
#pragma unroll
        for (int nt = 0; nt < 2; nt++) {
            int col = h * 16 + nt * 8 + 2 * t;
            int r0 = mt * 16 + g;
            *(__half2*)(smh + r0 * 136 + col) =
                __floats2half2_rn(o[mt][nt][0] * inv[mt][0],
                                  o[mt][nt][1] * inv[mt][0]);
            *(__half2*)(smh + (r0 + 8) * 136 + col) =
                __floats2half2_rn(o[mt][nt][2] * inv[mt][1],
                                  o[mt][nt][3] * inv[mt][1]);
        }
    __syncthreads();

#pragma unroll
    for (int it = 0; it < 3; it++) {
        int idx = tid + it * 256;
        int row = idx >> 4, c = idx & 15;
        *(uint4*)(g_o + (size_t)(base + (long)row * stride) * 384
                  + axis * 128 + c * 8) = *(const uint4*)(smh + row * 136 + c * 8);
    }
}

// ---------------------------------------------------------------------------
// launch
// ---------------------------------------------------------------------------
extern "C" void kernel_launch(void* const* d_in, const int* in_sizes, int n_in,
                              void* d_out, int out_size)
{
    (void)in_sizes; (void)n_in; (void)out_size;
    const float* x    = (const float*)d_in[0];
    const float* px   = (const float*)d_in[1];
    const float* py   = (const float*)d_in[2];
    const float* pz   = (const float*)d_in[3];
    const float* ln_g = (const float*)d_in[16];
    const float* ln_b = (const float*)d_in[17];
    const float* b1   = (const float*)d_in[19];
    const float* b2   = (const float*)d_in[21];

    cudaFuncSetAttribute((const void*)gemm_kernel,
                         cudaFuncAttributeMaxDynamicSharedMemorySize, GEMM_SMEM);
    cudaFuncSetAttribute((const void*)attn_kernel,
                         cudaFuncAttributeMaxDynamicSharedMemorySize, ATTN_SMEM);

    WP wp;
    for (int a = 0; a < 3; a++) {
        wp.wq[a]   = (const float*)d_in[4 + 4 * a];
        wp.wkv[a]  = (const float*)d_in[5 + 4 * a];
        wp.wout[a] = (const float*)d_in[6 + 4 * a];
    }
    wp.w1 = (const float*)d_in[18];
    wp.w2 = (const float*)d_in[20];
    wconv_kernel<<<896, 256>>>(wp);

    prep_kernel<<<NT / 64, 256>>>(x, px, py, pz);

    GP q = {}; q.mode = 0;
    gemm_kernel<<<dim3(9, NT / 128), 256, GEMM_SMEM>>>(q);

    attn_kernel<<<dim3(4608, 3), 256, ATTN_SMEM>>>();

    GP op = {}; op.mode = 1;
    op.bias0 = (const float*)d_in[7];
    op.bias1 = (const float*)d_in[11];
    op.bias2 = (const float*)d_in[15];
    op.lng = ln_g; op.lnb = ln_b;
    gemm_kernel<<<NT / 128, 256, GEMM_SMEM>>>(op);

    GP m1 = {}; m1.mode = 2; m1.bias0 = b1;
    gemm_kernel<<<NT / 128, 256, GEMM_SMEM>>>(m1);

    GP m2 = {}; m2.mode = 3; m2.bias0 = b2;
    m2.lng = ln_g; m2.lnb = ln_b; m2.out = (float*)d_out;
    gemm_kernel<<<NT / 128, 256, GEMM_SMEM>>>(m2);
}

// round 7
// speedup vs baseline: 10.8443x; 1.1407x over previous
#include <cuda_runtime.h>
#include <cuda_fp16.h>

// Problem constants
#define SS   110592          // 48^3
#define NT   221184          // NB*SS tokens
#define QKVW 1152            // 3 axes * (q,k,v) * 128

// Scratch (device globals; no allocation allowed) — all intermediates fp16
__device__ __half g_xe [NT * 128];            // pos-embedded input (residual 1)
__device__ __half g_qkv[(size_t)NT * QKVW];   // q/k/v, 3 axes
__device__ __half g_o  [(size_t)NT * 384];    // attention outputs, 3 axes
// fp16 weights: [0,147456) qkv strips (9 x 128x128), [147456,196608) wout_cat
// (128 rows x 384), [196608,212992) w1, [212992,229376) w2
__device__ __half g_wh [229376];

// ---------------------------------------------------------------------------
// helpers
// ---------------------------------------------------------------------------
__device__ __forceinline__ void cpa16_s(unsigned d, const void* s) {
    asm volatile("cp.async.cg.shared.global [%0], [%1], 16;" :: "r"(d), "l"(s));
}
#define CP_COMMIT() asm volatile("cp.async.commit_group;")
#define CP_WAIT1()  asm volatile("cp.async.wait_group 1;")
#define CP_WAIT0()  asm volatile("cp.async.wait_group 0;")

#define LDSM4(r, addr) \
    asm volatile("ldmatrix.sync.aligned.m8n8.x4.shared.b16 {%0,%1,%2,%3}, [%4];" \
        : "=r"((r)[0]), "=r"((r)[1]), "=r"((r)[2]), "=r"((r)[3]) : "r"(addr))

#define LDSM4T(r, addr) \
    asm volatile("ldmatrix.sync.aligned.m8n8.x4.trans.shared.b16 {%0,%1,%2,%3}, [%4];" \
        : "=r"((r)[0]), "=r"((r)[1]), "=r"((r)[2]), "=r"((r)[3]) : "r"(addr))

#define MMA16(d, a, b0, b1) \
    asm volatile("mma.sync.aligned.m16n8k16.row.col.f32.f16.f16.f32 " \
        "{%0,%1,%2,%3}, {%4,%5,%6,%7}, {%8,%9}, {%0,%1,%2,%3};" \
        : "+f"((d)[0]), "+f"((d)[1]), "+f"((d)[2]), "+f"((d)[3]) \
        : "r"((a)[0]), "r"((a)[1]), "r"((a)[2]), "r"((a)[3]), \
          "r"(b0), "r"(b1))

__device__ __forceinline__ unsigned h2u(float x, float y) {
    __half2 h = __floats2half2_rn(x, y);
    return *(unsigned*)&h;
}

// ---------------------------------------------------------------------------
// weight convert: fp32 -> fp16 buffer, one-time layout
// ---------------------------------------------------------------------------
struct WP {
    const float* wq[3]; const float* wkv[3]; const float* wout[3];
    const float* w1; const float* w2;
};
__global__ __launch_bounds__(256) void wconv_kernel(WP p)
{
    int idx = blockIdx.x * 256 + threadIdx.x;
    if (idx >= 229376) return;
    float v;
    if (idx < 147456) {
        int strip = idx >> 14, rem = idx & 16383;
        int a = strip / 3, r = strip - a * 3;
        v = (r == 0) ? p.wq[a][rem] : p.wkv[a][(r - 1) * 16384 + rem];
    } else if (idx < 196608) {
        int rem = idx - 147456;
        int n = rem / 384, k = rem - n * 384;
        v = p.wout[k >> 7][n * 128 + (k & 127)];
    } else if (idx < 212992) v = p.w1[idx - 196608];
    else                     v = p.w2[idx - 212992];
    g_wh[idx] = __float2half(v);
}

// ---------------------------------------------------------------------------
// prep: xe = 2*x + px + py + pz, transpose (B,C,S) -> (token, C), fp16
// ---------------------------------------------------------------------------
__global__ __launch_bounds__(256) void prep_kernel(
    const float* __restrict__ x,  const float* __restrict__ px,
    const float* __restrict__ py, const float* __restrict__ pz)
{
    __shared__ float tile[64][129];
    int base = blockIdx.x * 64;
    int b    = base / SS;
    int sp0  = base % SS;

    for (int e = threadIdx.x; e < 64 * 128; e += 256) {
        int c = e >> 6;
        int s = e & 63;
        int spatial = sp0 + s;
        int zi = spatial % 48;
        int yi = (spatial / 48) % 48;
        int xi = spatial / 2304;
        tile[s][c] = 2.0f * x[(size_t)b * 128 * SS + (size_t)c * SS + spatial]
                   + px[c * 48 + xi] + py[c * 48 + yi] + pz[c * 48 + zi];
    }
    __syncthreads();
    for (int e = threadIdx.x; e < 64 * 128; e += 256) {
        int s = e >> 7;
        int c = e & 127;
        g_xe[(size_t)(base + s) * 128 + c] = __float2half(tile[s][c]);
    }
}

// ---------------------------------------------------------------------------
// qkv GEMM: g_qkv[:, strip*128:+128] = g_xe @ Wstrip^T
// grid (9 strips, NT/128 mtiles); x-fastest => A tile L2 reuse across strips
// ---------------------------------------------------------------------------
#define GEMM_SMEM 65536

__global__ __launch_bounds__(256, 2) void qkv_kernel()
{
    extern __shared__ __align__(16) char smc[];
    unsigned sA = (unsigned)__cvta_generic_to_shared(smc);
    unsigned sB = sA + 32768;

    int tid = threadIdx.x, w = tid >> 5, lane = tid & 31;
    int mw = w & 3, nw = w >> 2;
    int g = lane >> 2, t = lane & 3;

    long m0 = (long)blockIdx.y * 128;
    const __half* Ap = g_xe;
    const __half* Bp = g_wh + (size_t)blockIdx.x * 16384;

#define STAGEQ(c, buf) do {                                                   \
        int k0_ = (c) * 64;                                                   \
        _Pragma("unroll")                                                     \
        for (int i_ = 0; i_ < 4; i_++) {                                      \
            int idx_ = tid + 256 * i_;                                        \
            int row_ = idx_ >> 3, seg_ = idx_ & 7;                            \
            unsigned dcol_ = (unsigned)((seg_ * 16) ^ ((row_ & 7) << 4));     \
            cpa16_s(sA + (buf) * 16384 + row_ * 128 + dcol_,                  \
                    Ap + (m0 + row_) * 128 + k0_ + seg_ * 8);                 \
            cpa16_s(sB + (buf) * 16384 + row_ * 128 + dcol_,                  \
                    Bp + (size_t)row_ * 128 + k0_ + seg_ * 8);                \
        }                                                                     \
    } while (0)

    float acc[2][8][4];
#pragma unroll
    for (int mt = 0; mt < 2; mt++)
#pragma unroll
        for (int nt = 0; nt < 8; nt++)
#pragma unroll
            for (int i = 0; i < 4; i++) acc[mt][nt][i] = 0.f;

    STAGEQ(0, 0); CP_COMMIT();

    int rowA  = mw * 32 + (lane & 15);
    int rowB0 = nw * 64 + ((lane & 16) >> 1) + (lane & 7);
    unsigned hiA = (unsigned)((lane >> 4) << 4);
    unsigned hiB = (unsigned)(((lane >> 3) & 1) << 4);
    unsigned xA = (unsigned)((rowA & 7) << 4);
    unsigned xB = (unsigned)((rowB0 & 7) << 4);

    for (int c = 0; c < 2; c++) {
        if (c == 0) { STAGEQ(1, 1); CP_COMMIT(); CP_WAIT1(); }
        else        { CP_WAIT0(); }
        __syncthreads();
        unsigned baseA = sA + c * 16384;
        unsigned baseB = sB + c * 16384;
#pragma unroll
        for (int kt = 0; kt < 4; kt++) {
            unsigned a[2][4];
#pragma unroll
            for (int mt = 0; mt < 2; mt++)
                LDSM4(a[mt], baseA + (rowA + mt * 16) * 128
                             + (((unsigned)(kt * 32) + hiA) ^ xA));
#pragma unroll
            for (int np = 0; np < 4; np++) {
                unsigned b[4];
                LDSM4(b, baseB + (rowB0 + np * 16) * 128
                         + (((unsigned)(kt * 32) + hiB) ^ xB));
                MMA16(acc[0][2 * np],     a[0], b[0], b[1]);
                MMA16(acc[1][2 * np],     a[1], b[0], b[1]);
                MMA16(acc[0][2 * np + 1], a[0], b[2], b[3]);
                MMA16(acc[1][2 * np + 1], a[1], b[2], b[3]);
            }
        }
        __syncthreads();
    }
#undef STAGEQ

    size_t ocol = (size_t)blockIdx.x * 128;
#pragma unroll
    for (int mt = 0; mt < 2; mt++)
#pragma unroll
        for (int nt = 0; nt < 8; nt++) {
            size_t tok = m0 + mw * 32 + mt * 16 + g;
            int cc = nw * 64 + nt * 8 + 2 * t;
            *(__half2*)(g_qkv + tok * QKVW + ocol + cc) =
                __floats2half2_rn(acc[mt][nt][0], acc[mt][nt][1]);
            *(__half2*)(g_qkv + (tok + 8) * QKVW + ocol + cc) =
                __floats2half2_rn(acc[mt][nt][2], acc[mt][nt][3]);
        }
}

// ---------------------------------------------------------------------------
// attention v4: grid (2304, 3); 2 sequences per CTA, software pipelined.
// Per-seq smem buf 56064B: kind k at +k*18688B, head h at +h*2336B,
// token row 48B. O staging aliases each buf. exp2 max-free softmax,
// normalization deferred to O.
// ---------------------------------------------------------------------------
#define ATTN_SMEM 112128
#define EXP2_SCALE 0.36067376022224085f   // 0.25 * log2(e)

__global__ __launch_bounds__(256, 2) void attn_kernel()
{
    extern __shared__ __align__(16) __half smh[];
    unsigned sbase = (unsigned)__cvta_generic_to_shared(smh);
    int tid = threadIdx.x, w = tid >> 5, lane = tid & 31;
    int g = lane >> 2, t = lane & 3, h = w;

    int axis = blockIdx.y;
    long baseA[2]; int stride;
#pragma unroll
    for (int sp = 0; sp < 2; sp++) {
        int seq = blockIdx.x * 2 + sp;
        int b = seq / 2304, rr = seq % 2304;
        int o1 = rr / 48, o2 = rr % 48;
        if (axis == 0)      { baseA[sp] = (long)b * SS + o1 * 48 + o2;        stride = 2304; }
        else if (axis == 1) { baseA[sp] = (long)b * SS + o1 * 2304 + o2;      stride = 48;   }
        else                { baseA[sp] = (long)b * SS + o1 * 2304 + o2 * 48; stride = 1;    }
    }

    // ---- stage both sequences up front (one commit group each) ----
#pragma unroll
    for (int sp = 0; sp < 2; sp++) {
#pragma unroll
        for (int it = 0; it < 9; it++) {
            int idx  = tid + it * 256;
            int row  = idx / 48;
            int c    = idx - row * 48;
            int kind = c >> 4;
            int hh   = (c >> 1) & 7;
            int lo   = c & 1;
            unsigned dst = sbase + sp * 56064
                         + (unsigned)(kind * 18688 + hh * 2336 + row * 48 + lo * 16);
            const __half* src = g_qkv + (size_t)(baseA[sp] + (long)row * stride) * QKVW
                              + axis * 384 + c * 8;
            cpa16_s(dst, src);
        }
        CP_COMMIT();
    }

#pragma unroll
    for (int sp = 0; sp < 2; sp++) {
        if (sp == 0) { CP_WAIT1(); } else { CP_WAIT0(); }
        __syncthreads();

        unsigned Qb = sbase + sp * 56064 + (unsigned)(h * 2336);
        unsigned Kb = Qb + 18688u;
        unsigned Vb = Qb + 37376u;

        // scores S = Q @ K^T : M=48, N=48, K=16
        float s[3][6][4];
#pragma unroll
        for (int mt = 0; mt < 3; mt++)
#pragma unroll
            for (int nt = 0; nt < 6; nt++)
#pragma unroll
                for (int i = 0; i < 4; i++) s[mt][nt][i] = 0.f;
        {
            unsigned a[3][4];
#pragma unroll
            for (int mt = 0; mt < 3; mt++)
                LDSM4(a[mt], Qb + (unsigned)((mt * 16 + (lane & 15)) * 48
                                             + ((lane >> 4) << 4)));
#pragma unroll
            for (int nt2 = 0; nt2 < 3; nt2++) {
                unsigned bb[4];
                LDSM4(bb, Kb + (unsigned)((nt2 * 16 + ((lane & 16) >> 1) + (lane & 7)) * 48
                                          + (((lane >> 3) & 1) << 4)));
#pragma unroll
                for (int mt = 0; mt < 3; mt++) {
                    MMA16(s[mt][2 * nt2],     a[mt], bb[0], bb[1]);
                    MMA16(s[mt][2 * nt2 + 1], a[mt], bb[2], bb[3]);
                }
            }
        }

        // max-free softmax: e = exp2(s * 0.25*log2e); norm deferred to O
        float inv[3][2];
#pragma unroll
        for (int mt = 0; mt < 3; mt++)
#pragma unroll
            for (int hi = 0; hi < 2; hi++) {
                float sum = 0.f;
#pragma unroll
                for (int nt = 0; nt < 6; nt++)
#pragma unroll
                    for (int lo = 0; lo < 2; lo++) {
                        float e = exp2f(s[mt][nt][hi * 2 + lo] * EXP2_SCALE);
                        s[mt][nt][hi * 2 + lo] = e;
                        sum += e;
                    }
                sum += __shfl_xor_sync(0xffffffffu, sum, 1);
                sum += __shfl_xor_sync(0xffffffffu, sum, 2);
                inv[mt][hi] = 1.f / sum;
            }

        // O = P_unnorm @ V : M=48, N=16, K=48
        float o[3][2][4];
#pragma unroll
        for (int mt = 0; mt < 3; mt++)
#pragma unroll
            for (int nt = 0; nt < 2; nt++)
#pragma unroll
                for (int i = 0; i < 4; i++) o[mt][nt][i] = 0.f;

#pragma unroll
        for (int kt = 0; kt < 3; kt++) {
            unsigned vb[4];
            LDSM4T(vb, Vb + (unsigned)((kt * 16 + (lane & 15)) * 48
                                       + ((lane >> 4) << 4)));
            unsigned pa[3][4];
#pragma unroll
            for (int mt = 0; mt < 3; mt++) {
                pa[mt][0] = h2u(s[mt][2 * kt][0],     s[mt][2 * kt][1]);
                pa[mt][1] = h2u(s[mt][2 * kt][2],     s[mt][2 * kt][3]);
                pa[mt][2] = h2u(s[mt][2 * kt + 1][0], s[mt][2 * kt + 1][1]);
                pa[mt][3] = h2u(s[mt][2 * kt + 1][2], s[mt][2 * kt + 1][3]);
            }
#pragma unroll
            for (int mt = 0; mt < 3; mt++) {
                MMA16(o[mt][0], pa[mt], vb[0], vb[1]);
                MMA16(o[mt][1], pa[mt], vb[2], vb[3]);
            }
        }

        // normalize O, stage in smem (aliases this seq's buf), coalesced store
        __syncthreads();
        __half* Os = smh + sp * 28032;
#pragma unroll
        for (int mt = 0; mt < 3; mt++)
#pragma unroll
            for (int nt = 0; nt < 2; nt++) {
                int col = h * 16 + nt * 8 + 2 * t;
                int r0 = mt * 16 + g;
                *(__half2*)(Os + r0 * 136 + col) =
                    __floats2half2_rn(o[mt][nt][0] * inv[mt][0],
                                      o[mt][nt][1] * inv[mt][0]);
                *(__half2*)(Os + (r0 + 8) * 136 + col) =
                    __floats2half2_rn(o[mt][nt][2] * inv[mt][1],
                                      o[mt][nt][3] * inv[mt][1]);
            }
        __syncthreads();

#pragma unroll
        for (int it = 0; it < 3; it++) {
            int idx = tid + it * 256;
            int row = idx >> 4, c = idx & 15;
            *(uint4*)(g_o + (size_t)(baseA[sp] + (long)row * stride) * 384
                      + axis * 128 + c * 8) = *(const uint4*)(Os + row * 136 + c * 8);
        }
    }
}

// ---------------------------------------------------------------------------
// fused tail: outproj(+bias3+res(g_xe)) -> LN1 -> mlp1(relu) -> mlp2(+res)
// -> LN2 -> transposed fp32 store. g_ln/g_h never touch DRAM.
// smem: R1 [0,68096) = P1 stage bufs / Ct(128x133 f32) / w1+h / w2
//       xln [68096,100864) = LN1 output, fp16 swizzled, row 256B
// ---------------------------------------------------------------------------
#define FUSE_SMEM 100864

struct FP {
    const float *bo0, *bo1, *bo2, *b1, *b2, *lng, *lnb;
    float* out;
};

__global__ __launch_bounds__(256, 2) void fuse_kernel(FP p)
{
    extern __shared__ __align__(16) char smc[];
    unsigned sR = (unsigned)__cvta_generic_to_shared(smc);
    unsigned sX = sR + 68096;
    float* Ct = (float*)smc;

    int tid = threadIdx.x, w = tid >> 5, lane = tid & 31;
    int mw = w & 3, nw = w >> 2;
    int g = lane >> 2, t = lane & 3;
    long m0 = (long)blockIdx.x * 128;

    int rowA  = mw * 32 + (lane & 15);
    int rowB0 = nw * 64 + ((lane & 16) >> 1) + (lane & 7);
    unsigned hiA = (unsigned)((lane >> 4) << 4);
    unsigned hiB = (unsigned)(((lane >> 3) & 1) << 4);
    unsigned xA = (unsigned)((rowA & 7) << 4);
    unsigned xB = (unsigned)((rowB0 & 7) << 4);

    // ================= P1: outproj, A=g_o (lda 384), B=wout_cat, K=384 ======
    float acc[2][8][4];
#pragma unroll
    for (int mt = 0; mt < 2; mt++)
#pragma unroll
        for (int nt = 0; nt < 8; nt++)
#pragma unroll
            for (int i = 0; i < 4; i++) acc[mt][nt][i] = 0.f;
    {
        unsigned sA = sR, sB = sR + 32768;
        const __half* Ap = g_o;
        const __half* Bp = g_wh + 147456;

#define STAGE1(c, buf) do {                                                   \
        int k0_ = (c) * 64;                                                   \
        _Pragma("unroll")                                                     \
        for (int i_ = 0; i_ < 4; i_++) {                                      \
            int idx_ = tid + 256 * i_;                                        \
            int row_ = idx_ >> 3, seg_ = idx_ & 7;                            \
            unsigned dcol_ = (unsigned)((seg_ * 16) ^ ((row_ & 7) << 4));     \
            cpa16_s(sA + (buf) * 16384 + row_ * 128 + dcol_,                  \
                    Ap + (m0 + row_) * 384 + k0_ + seg_ * 8);                 \
            cpa16_s(sB + (buf) * 16384 + row_ * 128 + dcol_,                  \
                    Bp + (size_t)row_ * 384 + k0_ + seg_ * 8);                \
        }                                                                     \
    } while (0)

        STAGE1(0, 0); CP_COMMIT();
        for (int c = 0; c < 6; c++) {
            if (c + 1 < 6) { STAGE1(c + 1, (c + 1) & 1); CP_COMMIT(); CP_WAIT1(); }
            else           { CP_WAIT0(); }
            __syncthreads();
            unsigned baseA = sA + (c & 1) * 16384;
            unsigned baseB = sB + (c & 1) * 16384;
#pragma unroll
            for (int kt = 0; kt < 4; kt++) {
                unsigned a[2][4];
#pragma unroll
                for (int mt = 0; mt < 2; mt++)
                    LDSM4(a[mt], baseA + (rowA + mt * 16) * 128
                                 + (((unsigned)(kt * 32) + hiA) ^ xA));
#pragma unroll
                for (int np = 0; np < 4; np++) {
                    unsigned b[4];
                    LDSM4(b, baseB + (rowB0 + np * 16) * 128
                             + (((unsigned)(kt * 32) + hiB) ^ xB));
                    MMA16(acc[0][2 * np],     a[0], b[0], b[1]);
                    MMA16(acc[1][2 * np],     a[1], b[0], b[1]);
                    MMA16(acc[0][2 * np + 1], a[0], b[2], b[3]);
                    MMA16(acc[1][2 * np + 1], a[1], b[2], b[3]);
                }
            }
            __syncthreads();
        }
#undef STAGE1
    }

    // epilogue P1: Ct = acc + (bo0+bo1+bo2) + g_xe residual
#pragma unroll
    for (int mt = 0; mt < 2; mt++)
#pragma unroll
        for (int nt = 0; nt < 8; nt++) {
            int rl = mw * 32 + mt * 16 + g;
            int cc = nw * 64 + nt * 8 + 2 * t;
            size_t tok = m0 + rl;
            float b0 = p.bo0[cc] + p.bo1[cc] + p.bo2[cc];
            float b1v = p.bo0[cc + 1] + p.bo1[cc + 1] + p.bo2[cc + 1];
            Ct[rl * 133 + cc]     = acc[mt][nt][0] + b0 + __half2float(g_xe[tok * 128 + cc]);
            Ct[rl * 133 + cc + 1] = acc[mt][nt][1] + b1v + __half2float(g_xe[tok * 128 + cc + 1]);
            Ct[(rl + 8) * 133 + cc]     = acc[mt][nt][2] + b0 + __half2float(g_xe[(tok + 8) * 128 + cc]);
            Ct[(rl + 8) * 133 + cc + 1] = acc[mt][nt][3] + b1v + __half2float(g_xe[(tok + 8) * 128 + cc + 1]);
        }
    __syncthreads();

    // LN1 -> xln (fp16 swizzled tile, row stride 256B)
    for (int r = w; r < 128; r += 8) {
        float v[4], s = 0.f, s2 = 0.f;
#pragma unroll
        for (int k = 0; k < 4; k++) {
            v[k] = Ct[r * 133 + lane + 32 * k];
            s += v[k]; s2 += v[k] * v[k];
        }
        for (int off = 16; off; off >>= 1) {
            s  += __shfl_xor_sync(0xffffffffu, s,  off);
            s2 += __shfl_xor_sync(0xffffffffu, s2, off);
        }
        float m   = s * (1.f / 128.f);
        float var = s2 * (1.f / 128.f) - m * m;
        float rs  = rsqrtf(var + 1e-5f);
        unsigned rxor = (unsigned)((r & 7) << 4);
#pragma unroll
        for (int k = 0; k < 4; k++) {
            int cc = lane + 32 * k;
            float y = (v[k] - m) * rs * p.lng[cc] + p.lnb[cc];
            *(__half*)(smc + 68096 + r * 256 + ((unsigned)(2 * cc) ^ rxor)) =
                __float2half(y);
        }
    }
    __syncthreads();   // xln ready; Ct / R1 free

    // ================= stage w1 -> R1[0,32K), w2 -> R1[32K,64K) =============
    {
        const __half* w1p = g_wh + 196608;
        const __half* w2p = g_wh + 212992;
#pragma unroll
        for (int i = 0; i < 8; i++) {
            int idx = tid + i * 256;
            int row = idx >> 4, seg = idx & 15;
            unsigned dcol = (unsigned)((seg * 16) ^ ((row & 7) << 4));
            cpa16_s(sR + row * 256 + dcol, w1p + row * 128 + seg * 8);
            cpa16_s(sR + 32768 + row * 256 + dcol, w2p + row * 128 + seg * 8);
        }
        CP_COMMIT(); CP_WAIT0();
        __syncthreads();
    }

    // ================= P2: h = relu(xln @ w1^T + b1), K=128 =================
    float acc2[2][8][4];
#pragma unroll
    for (int mt = 0; mt < 2; mt++)
#pragma unroll
        for (int nt = 0; nt < 8; nt++)
#pragma unroll
            for (int i = 0; i < 4; i++) acc2[mt][nt][i] = 0.f;

#pragma unroll
    for (int kt = 0; kt < 8; kt++) {
        unsigned a[2][4];
#pragma unroll
        for (int mt = 0; mt < 2; mt++)
            LDSM4(a[mt], sX + (rowA + mt * 16) * 256
                         + (((unsigned)(kt * 32) + hiA) ^ xA));
#pragma unroll
        for (int np = 0; np < 4; np++) {
            unsigned b[4];
            LDSM4(b, sR + (rowB0 + np * 16) * 256
                     + (((unsigned)(kt * 32) + hiB) ^ xB));
            MMA16(acc2[0][2 * np],     a[0], b[0], b[1]);
            MMA16(acc2[1][2 * np],     a[1], b[0], b[1]);
            MMA16(acc2[0][2 * np + 1], a[0], b[2], b[3]);
            MMA16(acc2[1][2 * np + 1], a[1], b[2], b[3]);
        }
    }
    __syncthreads();   // w1 reads done -> h tile may overwrite [0,32K)

    // h tile (fp16 swizzled, row 256B) at R1[0,32K)
#pragma unroll
    for (int mt = 0; mt < 2; mt++)
#pragma unroll
        for (int nt = 0; nt < 8; nt++) {
            int rl = mw * 32 + mt * 16 + g;
            int cc = nw * 64 + nt * 8 + 2 * t;
            float b0 = p.b1[cc], b1v = p.b1[cc + 1];
            unsigned c2 = (unsigned)(2 * cc);
            *(__half2*)(smc + rl * 256 + (c2 ^ (unsigned)((rl & 7) << 4))) =
                __floats2half2_rn(fmaxf(acc2[mt][nt][0] + b0, 0.f),
                                  fmaxf(acc2[mt][nt][1] + b1v, 0.f));
            *(__half2*)(smc + (rl + 8) * 256 + (c2 ^ (unsigned)(((rl + 8) & 7) << 4))) =
                __floats2half2_rn(fmaxf(acc2[mt][nt][2] + b0, 0.f),
                                  fmaxf(acc2[mt][nt][3] + b1v, 0.f));
        }
    __syncthreads();

    // ================= P3: y = h @ w2^T + b2 + xln, K=128 ===================
    float acc3[2][8][4];
#pragma unroll
    for (int mt = 0; mt < 2; mt++)
#pragma unroll
        for (int nt = 0; nt < 8; nt++)
#pragma unroll
            for (int i = 0; i < 4; i++) acc3[mt][nt][i] = 0.f;

#pragma unroll
    for (int kt = 0; kt < 8; kt++) {
        unsigned a[2][4];
#pragma unroll
        for (int mt = 0; mt < 2; mt++)
            LDSM4(a[mt], sR + (rowA + mt * 16) * 256
                         + (((unsigned)(kt * 32) + hiA) ^ xA));
#pragma unroll
        for (int np = 0; np < 4; np++) {
            unsigned b[4];
            LDSM4(b, sR + 32768 + (rowB0 + np * 16) * 256
                     + (((unsigned)(kt * 32) + hiB) ^ xB));
            MMA16(acc3[0][2 * np],     a[0], b[0], b[1]);
            MMA16(acc3[1][2 * np],     a[1], b[0], b[1]);
            MMA16(acc3[0][2 * np + 1], a[0], b[2], b[3]);
            MMA16(acc3[1][2 * np + 1], a[1], b[2], b[3]);
        }
    }
    __syncthreads();   // h/w2 reads done -> Ct may overwrite

    // epilogue P3: Ct = acc3 + b2 + xln residual (fp16 smem read)
#pragma unroll
    for (int mt = 0; mt < 2; mt++)
#pragma unroll
        for (int nt = 0; nt < 8; nt++) {
            int rl = mw * 32 + mt * 16 + g;
            int cc = nw * 64 + nt * 8 + 2 * t;
            float b0 = p.b2[cc], b1v = p.b2[cc + 1];
            unsigned c2 = (unsigned)(2 * cc);
            __half2 r0 = *(const __half2*)(smc + 68096 + rl * 256
                                           + (c2 ^ (unsigned)((rl & 7) << 4)));
            __half2 r1 = *(const __half2*)(smc + 68096 + (rl + 8) * 256
                                           + (c2 ^ (unsigned)(((rl + 8) & 7) << 4)));
            float2 f0 = __half22float2(r0);
            float2 f1 = __half22float2(r1);
            Ct[rl * 133 + cc]           = acc3[mt][nt][0] + b0 + f0.x;
            Ct[rl * 133 + cc + 1]       = acc3[mt][nt][1] + b1v + f0.y;
            Ct[(rl + 8) * 133 + cc]     = acc3[mt][nt][2] + b0 + f1.x;
            Ct[(rl + 8) * 133 + cc + 1] = acc3[mt][nt][3] + b1v + f1.y;
        }
    __syncthreads();

    // LN2 (in place in Ct)
    for (int r = w; r < 128; r += 8) {
        float v[4], s = 0.f, s2 = 0.f;
#pragma unroll
        for (int k = 0; k < 4; k++) {
            v[k] = Ct[r * 133 + lane + 32 * k];
            s += v[k]; s2 += v[k] * v[k];
        }
        for (int off = 16; off; off >>= 1) {
            s  += __shfl_xor_sync(0xffffffffu, s,  off);
            s2 += __shfl_xor_sync(0xffffffffu, s2, off);
        }
        float m   = s * (1.f / 128.f);
        float var = s2 * (1.f / 128.f) - m * m;
        float rs  = rsqrtf(var + 1e-5f);
#pragma unroll
        for (int k = 0; k < 4; k++) {
            int cc = lane + 32 * k;
            Ct[r * 133 + cc] = (v[k] - m) * rs * p.lng[cc] + p.lnb[cc];
        }
    }
    __syncthreads();

    // transposed fp32 store to (B,C,X,Y,Z)
    int  bi  = (int)(m0 / SS);
    long sp0 = m0 % SS;
    float* outp = p.out + (size_t)bi * 128 * SS + sp0;
    for (int e = tid; e < 128 * 128; e += 256) {
        int cc = e >> 7, ss = e & 127;
        outp[(size_t)cc * SS + ss] = Ct[ss * 133 + cc];
    }
}

// ---------------------------------------------------------------------------
// launch
// ---------------------------------------------------------------------------
extern "C" void kernel_launch(void* const* d_in, const int* in_sizes, int n_in,
                              void* d_out, int out_size)
{
    (void)in_sizes; (void)n_in; (void)out_size;
    const float* x    = (const float*)d_in[0];
    const float* px   = (const float*)d_in[1];
    const float* py   = (const float*)d_in[2];
    const float* pz   = (const float*)d_in[3];

    cudaFuncSetAttribute((const void*)qkv_kernel,
                         cudaFuncAttributeMaxDynamicSharedMemorySize, GEMM_SMEM);
    cudaFuncSetAttribute((const void*)attn_kernel,
                         cudaFuncAttributeMaxDynamicSharedMemorySize, ATTN_SMEM);
    cudaFuncSetAttribute((const void*)fuse_kernel,
                         cudaFuncAttributeMaxDynamicSharedMemorySize, FUSE_SMEM);

    WP wp;
    for (int a = 0; a < 3; a++) {
        wp.wq[a]   = (const float*)d_in[4 + 4 * a];
        wp.wkv[a]  = (const float*)d_in[5 + 4 * a];
        wp.wout[a] = (const float*)d_in[6 + 4 * a];
    }
    wp.w1 = (const float*)d_in[18];
    wp.w2 = (const float*)d_in[20];
    wconv_kernel<<<896, 256>>>(wp);

    prep_kernel<<<NT / 64, 256>>>(x, px, py, pz);

    qkv_kernel<<<dim3(9, NT / 128), 256, GEMM_SMEM>>>();

    attn_kernel<<<dim3(2304, 3), 256, ATTN_SMEM>>>();

    FP fp;
    fp.bo0 = (const float*)d_in[7];
    fp.bo1 = (const float*)d_in[11];
    fp.bo2 = (const float*)d_in[15];
    fp.b1  = (const float*)d_in[19];
    fp.b2  = (const float*)d_in[21];
    fp.lng = (const float*)d_in[16];
    fp.lnb = (const float*)d_in[17];
    fp.out = (float*)d_out;
    fuse_kernel<<<NT / 128, 256, FUSE_SMEM>>>(fp);
}

// round 8
// speedup vs baseline: 14.1855x; 1.3081x over previous
#include <cuda_runtime.h>
#include <cuda_fp16.h>

// Problem constants
#define SS   110592          // 48^3
#define NT   221184          // NB*SS tokens

// Scratch (device globals; no allocation allowed) — all intermediates fp16
__device__ __half g_xe [NT * 128];            // pos-embedded input (residual 1)
__device__ __half g_o  [(size_t)NT * 384];    // attention outputs, 3 axes
// fp16 weights: [0,147456) qkv blocks (3 axes x [384][128]), [147456,196608)
// wout_cat (128 rows x 384), [196608,212992) w1, [212992,229376) w2
__device__ __half g_wh [229376];

// ---------------------------------------------------------------------------
// helpers
// ---------------------------------------------------------------------------
__device__ __forceinline__ void cpa16_s(unsigned d, const void* s) {
    asm volatile("cp.async.cg.shared.global [%0], [%1], 16;" :: "r"(d), "l"(s));
}
#define CP_COMMIT() asm volatile("cp.async.commit_group;")
#define CP_WAIT1()  asm volatile("cp.async.wait_group 1;")
#define CP_WAIT0()  asm volatile("cp.async.wait_group 0;")

#define LDSM4(r, addr) \
    asm volatile("ldmatrix.sync.aligned.m8n8.x4.shared.b16 {%0,%1,%2,%3}, [%4];" \
        : "=r"((r)[0]), "=r"((r)[1]), "=r"((r)[2]), "=r"((r)[3]) : "r"(addr))

#define LDSM4T(r, addr) \
    asm volatile("ldmatrix.sync.aligned.m8n8.x4.trans.shared.b16 {%0,%1,%2,%3}, [%4];" \
        : "=r"((r)[0]), "=r"((r)[1]), "=r"((r)[2]), "=r"((r)[3]) : "r"(addr))

#define MMA16(d, a, b0, b1) \
    asm volatile("mma.sync.aligned.m16n8k16.row.col.f32.f16.f16.f32 " \
        "{%0,%1,%2,%3}, {%4,%5,%6,%7}, {%8,%9}, {%0,%1,%2,%3};" \
        : "+f"((d)[0]), "+f"((d)[1]), "+f"((d)[2]), "+f"((d)[3]) \
        : "r"((a)[0]), "r"((a)[1]), "r"((a)[2]), "r"((a)[3]), \
          "r"(b0), "r"(b1))

__device__ __forceinline__ unsigned h2u(float x, float y) {
    __half2 h = __floats2half2_rn(x, y);
    return *(unsigned*)&h;
}

// ---------------------------------------------------------------------------
// weight convert: fp32 -> fp16 buffer, one-time layout
// ---------------------------------------------------------------------------
struct WP {
    const float* wq[3]; const float* wkv[3]; const float* wout[3];
    const float* w1; const float* w2;
};
__global__ __launch_bounds__(256) void wconv_kernel(WP p)
{
    int idx = blockIdx.x * 256 + threadIdx.x;
    if (idx >= 229376) return;
    float v;
    if (idx < 147456) {
        int strip = idx >> 14, rem = idx & 16383;
        int a = strip / 3, r = strip - a * 3;
        v = (r == 0) ? p.wq[a][rem] : p.wkv[a][(r - 1) * 16384 + rem];
    } else if (idx < 196608) {
        int rem = idx - 147456;
        int n = rem / 384, k = rem - n * 384;
        v = p.wout[k >> 7][n * 128 + (k & 127)];
    } else if (idx < 212992) v = p.w1[idx - 196608];
    else                     v = p.w2[idx - 212992];
    g_wh[idx] = __float2half(v);
}

// ---------------------------------------------------------------------------
// prep: xe = 2*x + px + py + pz, transpose (B,C,S) -> (token, C), fp16
// ---------------------------------------------------------------------------
__global__ __launch_bounds__(256) void prep_kernel(
    const float* __restrict__ x,  const float* __restrict__ px,
    const float* __restrict__ py, const float* __restrict__ pz)
{
    __shared__ float tile[64][129];
    int base = blockIdx.x * 64;
    int b    = base / SS;
    int sp0  = base % SS;

    for (int e = threadIdx.x; e < 64 * 128; e += 256) {
        int c = e >> 6;
        int s = e & 63;
        int spatial = sp0 + s;
        int zi = spatial % 48;
        int yi = (spatial / 48) % 48;
        int xi = spatial / 2304;
        tile[s][c] = 2.0f * x[(size_t)b * 128 * SS + (size_t)c * SS + spatial]
                   + px[c * 48 + xi] + py[c * 48 + yi] + pz[c * 48 + zi];
    }
    __syncthreads();
    for (int e = threadIdx.x; e < 64 * 128; e += 256) {
        int s = e >> 7;
        int c = e & 127;
        g_xe[(size_t)(base + s) * 128 + c] = __float2half(tile[s][c]);
    }
}

// ---------------------------------------------------------------------------
// fused QKV + attention: grid (576, 3 axes); 8 seqs per CTA, 8 warps.
// smem: W [0,98304) = axis's wq|wk|wv as [384][128], row 256B swizzled;
//       A [98304,122880) = 2 x (48x128 xe tile, row 256B swizzled);
//       QKV [122880,178944) = attention layout: kind*18688 + head*2336
//       + row*48B (+ O staging alias).
// Per seq: GEMM M=48,N=384,K=128 (warp = 48-col slice) -> epilogue writes
// q/k/v to smem -> per-head mma attention (exp2 max-free softmax, norm
// deferred to O) -> coalesced O store. A double-buffered across seq loop.
// ---------------------------------------------------------------------------
#define ATTN2_SMEM 178944
#define SEQ_PER_CTA 8
#define EXP2_SCALE 0.36067376022224085f   // 0.25 * log2(e)

__global__ __launch_bounds__(256, 1) void attn2_kernel()
{
    extern __shared__ __align__(16) char smc[];
    unsigned sbase = (unsigned)__cvta_generic_to_shared(smc);
    const unsigned sW = sbase;
    const unsigned sA = sbase + 98304;
    const unsigned sQ = sbase + 122880;
    char*   QKVc = smc + 122880;
    __half* Os   = (__half*)(smc + 122880);

    int tid = threadIdx.x, w = tid >> 5, lane = tid & 31;
    int g = lane >> 2, t = lane & 3, h = w;
    int axis = blockIdx.y;
    int stride = (axis == 0) ? 2304 : (axis == 1 ? 48 : 1);

    // ---- stage W (384 rows x 256B, swizzled) ----
    const __half* Wsrc = g_wh + (size_t)axis * 49152;
#pragma unroll
    for (int i = 0; i < 24; i++) {
        int idx = tid + i * 256;
        int row = idx >> 4, seg = idx & 15;
        cpa16_s(sW + row * 256 + (unsigned)((seg * 16) ^ ((row & 7) << 4)),
                Wsrc + (size_t)row * 128 + seg * 8);
    }
    CP_COMMIT();

    int seq0 = blockIdx.x * SEQ_PER_CTA;

#define BASE_OF(sq, bs) do {                                                  \
        int b_ = (sq) / 2304, rr_ = (sq) % 2304;                              \
        int o1_ = rr_ / 48, o2_ = rr_ % 48;                                   \
        if (axis == 0)      bs = (long)b_ * SS + o1_ * 48 + o2_;              \
        else if (axis == 1) bs = (long)b_ * SS + o1_ * 2304 + o2_;            \
        else                bs = (long)b_ * SS + o1_ * 2304 + (long)o2_ * 48; \
    } while (0)

#define STAGE_A(bs, buf) do {                                                 \
        _Pragma("unroll")                                                     \
        for (int it_ = 0; it_ < 3; it_++) {                                   \
            int idx_ = tid + it_ * 256;                                       \
            int row_ = idx_ >> 4, seg_ = idx_ & 15;                           \
            cpa16_s(sA + (buf) * 12288 + row_ * 256                           \
                    + (unsigned)((seg_ * 16) ^ ((row_ & 7) << 4)),            \
                    g_xe + (size_t)((bs) + (long)row_ * stride) * 128         \
                    + seg_ * 8);                                              \
        }                                                                     \
    } while (0)

    { long bs0; BASE_OF(seq0, bs0); STAGE_A(bs0, 0); CP_COMMIT(); }

    // fragment addressing
    int ra = lane & 15;
    unsigned hiA = (unsigned)((lane >> 4) << 4);
    unsigned xA  = (unsigned)((ra & 7) << 4);
    int rb = w * 48 + ((lane & 16) >> 1) + (lane & 7);
    unsigned hiB = (unsigned)(((lane >> 3) & 1) << 4);
    unsigned xB  = (unsigned)((rb & 7) << 4);

    for (int i = 0; i < SEQ_PER_CTA; i++) {
        long bs; BASE_OF(seq0 + i, bs);
        if (i + 1 < SEQ_PER_CTA) {
            long bn; BASE_OF(seq0 + i + 1, bn);
            STAGE_A(bn, (i + 1) & 1);
            CP_COMMIT(); CP_WAIT1();
        } else {
            CP_WAIT0();
        }
        __syncthreads();

        // ---- GEMM: qkv[48x384] = A[48x128] @ W^T ----
        unsigned sAc = sA + (i & 1) * 12288;
        float acc[3][6][4];
#pragma unroll
        for (int mt = 0; mt < 3; mt++)
#pragma unroll
            for (int nt = 0; nt < 6; nt++)
#pragma unroll
                for (int q = 0; q < 4; q++) acc[mt][nt][q] = 0.f;

#pragma unroll
        for (int kt = 0; kt < 8; kt++) {
            unsigned a[3][4];
#pragma unroll
            for (int mt = 0; mt < 3; mt++)
                LDSM4(a[mt], sAc + (unsigned)((mt * 16 + ra) * 256)
                             + (((unsigned)(kt * 32) + hiA) ^ xA));
#pragma unroll
            for (int np = 0; np < 3; np++) {
                unsigned b[4];
                LDSM4(b, sW + (unsigned)((rb + np * 16) * 256)
                         + (((unsigned)(kt * 32) + hiB) ^ xB));
#pragma unroll
                for (int mt = 0; mt < 3; mt++) {
                    MMA16(acc[mt][2 * np],     a[mt], b[0], b[1]);
                    MMA16(acc[mt][2 * np + 1], a[mt], b[2], b[3]);
                }
            }
        }

        // ---- epilogue: q/k/v -> smem attention layout ----
#pragma unroll
        for (int mt = 0; mt < 3; mt++)
#pragma unroll
            for (int nt = 0; nt < 6; nt++) {
                int col = w * 48 + nt * 8 + 2 * t;
                int kind = col >> 7, rem = col & 127;
                unsigned off = (unsigned)(kind * 18688 + (rem >> 4) * 2336
                                          + (rem & 15) * 2);
                int r0 = mt * 16 + g;
                *(__half2*)(QKVc + off + r0 * 48) =
                    __floats2half2_rn(acc[mt][nt][0], acc[mt][nt][1]);
                *(__half2*)(QKVc + off + (r0 + 8) * 48) =
                    __floats2half2_rn(acc[mt][nt][2], acc[mt][nt][3]);
            }
        __syncthreads();

        // ---- attention (warp = head) ----
        unsigned Qb = sQ + (unsigned)(h * 2336);
        unsigned Kb = Qb + 18688u;
        unsigned Vb = Qb + 37376u;

        float s[3][6][4];
#pragma unroll
        for (int mt = 0; mt < 3; mt++)
#pragma unroll
            for (int nt = 0; nt < 6; nt++)
#pragma unroll
                for (int q = 0; q < 4; q++) s[mt][nt][q] = 0.f;
        {
            unsigned a[3][4];
#pragma unroll
            for (int mt = 0; mt < 3; mt++)
                LDSM4(a[mt], Qb + (unsigned)((mt * 16 + (lane & 15)) * 48
                                             + ((lane >> 4) << 4)));
#pragma unroll
            for (int nt2 = 0; nt2 < 3; nt2++) {
                unsigned bb[4];
                LDSM4(bb, Kb + (unsigned)((nt2 * 16 + ((lane & 16) >> 1) + (lane & 7)) * 48
                                          + (((lane >> 3) & 1) << 4)));
#pragma unroll
                for (int mt = 0; mt < 3; mt++) {
                    MMA16(s[mt][2 * nt2],     a[mt], bb[0], bb[1]);
                    MMA16(s[mt][2 * nt2 + 1], a[mt], bb[2], bb[3]);
                }
            }
        }

        float inv[3][2];
#pragma unroll
        for (int mt = 0; mt < 3; mt++)
#pragma unroll
            for (int hi = 0; hi < 2; hi++) {
                float sum = 0.f;
#pragma unroll
                for (int nt = 0; nt < 6; nt++)
#pragma unroll
                    for (int lo = 0; lo < 2; lo++) {
                        float e = exp2f(s[mt][nt][hi * 2 + lo] * EXP2_SCALE);
                        s[mt][nt][hi * 2 + lo] = e;
                        sum += e;
                    }
                sum += __shfl_xor_sync(0xffffffffu, sum, 1);
                sum += __shfl_xor_sync(0xffffffffu, sum, 2);
                inv[mt][hi] = 1.f / sum;
            }

        float o[3][2][4];
#pragma unroll
        for (int mt = 0; mt < 3; mt++)
#pragma unroll
            for (int nt = 0; nt < 2; nt++)
#pragma unroll
                for (int q = 0; q < 4; q++) o[mt][nt][q] = 0.f;

#pragma unroll
        for (int kt = 0; kt < 3; kt++) {
            unsigned vb[4];
            LDSM4T(vb, Vb + (unsigned)((kt * 16 + (lane & 15)) * 48
                                       + ((lane >> 4) << 4)));
            unsigned pa[3][4];
#pragma unroll
            for (int mt = 0; mt < 3; mt++) {
                pa[mt][0] = h2u(s[mt][2 * kt][0],     s[mt][2 * kt][1]);
                pa[mt][1] = h2u(s[mt][2 * kt][2],     s[mt][2 * kt][3]);
                pa[mt][2] = h2u(s[mt][2 * kt + 1][0], s[mt][2 * kt + 1][1]);
                pa[mt][3] = h2u(s[mt][2 * kt + 1][2], s[mt][2 * kt + 1][3]);
            }
#pragma unroll
            for (int mt = 0; mt < 3; mt++) {
                MMA16(o[mt][0], pa[mt], vb[0], vb[1]);
                MMA16(o[mt][1], pa[mt], vb[2], vb[3]);
            }
        }

        // ---- normalize O, stage (aliases QKV buf), coalesced store ----
        __syncthreads();
#pragma unroll
        for (int mt = 0; mt < 3; mt++)
#pragma unroll
            for (int nt = 0; nt < 2; nt++) {
                int col = h * 16 + nt * 8 + 2 * t;
                int r0 = mt * 16 + g;
                *(__half2*)(Os + r0 * 136 + col) =
                    __floats2half2_rn(o[mt][nt][0] * inv[mt][0],
                                      o[mt][nt][1] * inv[mt][0]);
                *(__half2*)(Os + (r0 + 8) * 136 + col) =
                    __floats2half2_rn(o[mt][nt][2] * inv[mt][1],
                                      o[mt][nt][3] * inv[mt][1]);
            }
        __syncthreads();

#pragma unroll
        for (int it = 0; it < 3; it++) {
            int idx = tid + it * 256;
            int row = idx >> 4, c = idx & 15;
            *(uint4*)(g_o + (size_t)(bs + (long)row * stride) * 384
                      + axis * 128 + c * 8) = *(const uint4*)(Os + row * 136 + c * 8);
        }
        __syncthreads();   // Os free before next GEMM epilogue overwrites
    }
#undef BASE_OF
#undef STAGE_A
}

// ---------------------------------------------------------------------------
// fused tail: outproj(+bias3+res(g_xe)) -> LN1 -> mlp1(relu) -> mlp2(+res)
// -> LN2 -> transposed fp32 store. Intermediates never touch DRAM.
// ---------------------------------------------------------------------------
#define FUSE_SMEM 100864

struct FP {
    const float *bo0, *bo1, *bo2, *b1, *b2, *lng, *lnb;
    float* out;
};

__global__ __launch_bounds__(256, 2) void fuse_kernel(FP p)
{
    extern __shared__ __align__(16) char smc[];
    unsigned sR = (unsigned)__cvta_generic_to_shared(smc);
    unsigned sX = sR + 68096;
    float* Ct = (float*)smc;

    int tid = threadIdx.x, w = tid >> 5, lane = tid & 31;
    int mw = w & 3, nw = w >> 2;
    int g = lane >> 2, t = lane & 3;
    long m0 = (long)blockIdx.x * 128;

    int rowA  = mw * 32 + (lane & 15);
    int rowB0 = nw * 64 + ((lane & 16) >> 1) + (lane & 7);
    unsigned hiA = (unsigned)((lane >> 4) << 4);
    unsigned hiB = (unsigned)(((lane >> 3) & 1) << 4);
    unsigned xA = (unsigned)((rowA & 7) << 4);
    unsigned xB = (unsigned)((rowB0 & 7) << 4);

    // ================= P1: outproj, A=g_o (lda 384), B=wout_cat, K=384 ======
    float acc[2][8][4];
#pragma unroll
    for (int mt = 0; mt < 2; mt++)
#pragma unroll
        for (int nt = 0; nt < 8; nt++)
#pragma unroll
            for (int i = 0; i < 4; i++) acc[mt][nt][i] = 0.f;
    {
        unsigned sA = sR, sB = sR + 32768;
        const __half* Ap = g_o;
        const __half* Bp = g_wh + 147456;

#define STAGE1(c, buf) do {                                                   \
        int k0_ = (c) * 64;                                                   \
        _Pragma("unroll")                                                     \
        for (int i_ = 0; i_ < 4; i_++) {                                      \
            int idx_ = tid + 256 * i_;                                        \
            int row_ = idx_ >> 3, seg_ = idx_ & 7;                            \
            unsigned dcol_ = (unsigned)((seg_ * 16) ^ ((row_ & 7) << 4));     \
            cpa16_s(sA + (buf) * 16384 + row_ * 128 + dcol_,                  \
                    Ap + (m0 + row_) * 384 + k0_ + seg_ * 8);                 \
            cpa16_s(sB + (buf) * 16384 + row_ * 128 + dcol_,                  \
                    Bp + (size_t)row_ * 384 + k0_ + seg_ * 8);                \
        }                                                                     \
    } while (0)

        STAGE1(0, 0); CP_COMMIT();
        for (int c = 0; c < 6; c++) {
            if (c + 1 < 6) { STAGE1(c + 1, (c + 1) & 1); CP_COMMIT(); CP_WAIT1(); }
            else           { CP_WAIT0(); }
            __syncthreads();
            unsigned baseA = sA + (c & 1) * 16384;
            unsigned baseB = sB + (c & 1) * 16384;
#pragma unroll
            for (int kt = 0; kt < 4; kt++) {
                unsigned a[2][4];
#pragma unroll
                for (int mt = 0; mt < 2; mt++)
                    LDSM4(a[mt], baseA + (rowA + mt * 16) * 128
                                 + (((unsigned)(kt * 32) + hiA) ^ xA));
#pragma unroll
                for (int np = 0; np < 4; np++) {
                    unsigned b[4];
                    LDSM4(b, baseB + (rowB0 + np * 16) * 128
                             + (((unsigned)(kt * 32) + hiB) ^ xB));
                    MMA16(acc[0][2 * np],     a[0], b[0], b[1]);
                    MMA16(acc[1][2 * np],     a[1], b[0], b[1]);
                    MMA16(acc[0][2 * np + 1], a[0], b[2], b[3]);
                    MMA16(acc[1][2 * np + 1], a[1], b[2], b[3]);
                }
            }
            __syncthreads();
        }
#undef STAGE1
    }

    // epilogue P1: Ct = acc + (bo0+bo1+bo2) + g_xe residual
#pragma unroll
    for (int mt = 0; mt < 2; mt++)
#pragma unroll
        for (int nt = 0; nt < 8; nt++) {
            int rl = mw * 32 + mt * 16 + g;
            int cc = nw * 64 + nt * 8 + 2 * t;
            size_t tok = m0 + rl;
            float b0 = p.bo0[cc] + p.bo1[cc] + p.bo2[cc];
            float b1v = p.bo0[cc + 1] + p.bo1[cc + 1] + p.bo2[cc + 1];
            Ct[rl * 133 + cc]     = acc[mt][nt][0] + b0 + __half2float(g_xe[tok * 128 + cc]);
            Ct[rl * 133 + cc + 1] = acc[mt][nt][1] + b1v + __half2float(g_xe[tok * 128 + cc + 1]);
            Ct[(rl + 8) * 133 + cc]     = acc[mt][nt][2] + b0 + __half2float(g_xe[(tok + 8) * 128 + cc]);
            Ct[(rl + 8) * 133 + cc + 1] = acc[mt][nt][3] + b1v + __half2float(g_xe[(tok + 8) * 128 + cc + 1]);
        }
    __syncthreads();

    // LN1 -> xln (fp16 swizzled tile, row stride 256B)
    for (int r = w; r < 128; r += 8) {
        float v[4], s = 0.f, s2 = 0.f;
#pragma unroll
        for (int k = 0; k < 4; k++) {
            v[k] = Ct[r * 133 + lane + 32 * k];
            s += v[k]; s2 += v[k] * v[k];
        }
        for (int off = 16; off; off >>= 1) {
            s  += __shfl_xor_sync(0xffffffffu, s,  off);
            s2 += __shfl_xor_sync(0xffffffffu, s2, off);
        }
        float m   = s * (1.f / 128.f);
        float var = s2 * (1.f / 128.f) - m * m;
        float rs  = rsqrtf(var + 1e-5f);
        unsigned rxor = (unsigned)((r & 7) << 4);
#pragma unroll
        for (int k = 0; k < 4; k++) {
            int cc = lane + 32 * k;
            float y = (v[k] - m) * rs * p.lng[cc] + p.lnb[cc];
            *(__half*)(smc + 68096 + r * 256 + ((unsigned)(2 * cc) ^ rxor)) =
                __float2half(y);
        }
    }
    __syncthreads();

    // ================= stage w1 -> R1[0,32K), w2 -> R1[32K,64K) =============
    {
        const __half* w1p = g_wh + 196608;
        const __half* w2p = g_wh + 212992;
#pragma unroll
        for (int i = 0; i < 8; i++) {
            int idx = tid + i * 256;
            int row = idx >> 4, seg = idx & 15;
            unsigned dcol = (unsigned)((seg * 16) ^ ((row & 7) << 4));
            cpa16_s(sR + row * 256 + dcol, w1p + row * 128 + seg * 8);
            cpa16_s(sR + 32768 + row * 256 + dcol, w2p + row * 128 + seg * 8);
        }
        CP_COMMIT(); CP_WAIT0();
        __syncthreads();
    }

    // ================= P2: h = relu(xln @ w1^T + b1), K=128 =================
    float acc2[2][8][4];
#pragma unroll
    for (int mt = 0; mt < 2; mt++)
#pragma unroll
        for (int nt = 0; nt < 8; nt++)
#pragma unroll
            for (int i = 0; i < 4; i++) acc2[mt][nt][i] = 0.f;

#pragma unroll
    for (int kt = 0; kt < 8; kt++) {
        unsigned a[2][4];
#pragma unroll
        for (int mt = 0; mt < 2; mt++)
            LDSM4(a[mt], sX + (rowA + mt * 16) * 256
                         + (((unsigned)(kt * 32) + hiA) ^ xA));
#pragma unroll
        for (int np = 0; np < 4; np++) {
            unsigned b[4];
            LDSM4(b, sR + (rowB0 + np * 16) * 256
                     + (((unsigned)(kt * 32) + hiB) ^ xB));
            MMA16(acc2[0][2 * np],     a[0], b[0], b[1]);
            MMA16(acc2[1][2 * np],     a[1], b[0], b[1]);
            MMA16(acc2[0][2 * np + 1], a[0], b[2], b[3]);
            MMA16(acc2[1][2 * np + 1], a[1], b[2], b[3]);
        }
    }
    __syncthreads();

    // h tile (fp16 swizzled, row 256B) at R1[0,32K)
#pragma unroll
    for (int mt = 0; mt < 2; mt++)
#pragma unroll
        for (int nt = 0; nt < 8; nt++) {
            int rl = mw * 32 + mt * 16 + g;
            int cc = nw * 64 + nt * 8 + 2 * t;
            float b0 = p.b1[cc], b1v = p.b1[cc + 1];
            unsigned c2 = (unsigned)(2 * cc);
            *(__half2*)(smc + rl * 256 + (c2 ^ (unsigned)((rl & 7) << 4))) =
                __floats2half2_rn(fmaxf(acc2[mt][nt][0] + b0, 0.f),
                                  fmaxf(acc2[mt][nt][1] + b1v, 0.f));
            *(__half2*)(smc + (rl + 8) * 256 + (c2 ^ (unsigned)(((rl + 8) & 7) << 4))) =
                __floats2half2_rn(fmaxf(acc2[mt][nt][2] + b0, 0.f),
                                  fmaxf(acc2[mt][nt][3] + b1v, 0.f));
        }
    __syncthreads();

    // ================= P3: y = h @ w2^T + b2 + xln, K=128 ===================
    float acc3[2][8][4];
#pragma unroll
    for (int mt = 0; mt < 2; mt++)
#pragma unroll
        for (int nt = 0; nt < 8; nt++)
#pragma unroll
            for (int i = 0; i < 4; i++) acc3[mt][nt][i] = 0.f;

#pragma unroll
    for (int kt = 0; kt < 8; kt++) {
        unsigned a[2][4];
#pragma unroll
        for (int mt = 0; mt < 2; mt++)
            LDSM4(a[mt], sR + (rowA + mt * 16) * 256
                         + (((unsigned)(kt * 32) + hiA) ^ xA));
#pragma unroll
        for (int np = 0; np < 4; np++) {
            unsigned b[4];
            LDSM4(b, sR + 32768 + (rowB0 + np * 16) * 256
                     + (((unsigned)(kt * 32) + hiB) ^ xB));
            MMA16(acc3[0][2 * np],     a[0], b[0], b[1]);
            MMA16(acc3[1][2 * np],     a[1], b[0], b[1]);
            MMA16(acc3[0][2 * np + 1], a[0], b[2], b[3]);
            MMA16(acc3[1][2 * np + 1], a[1], b[2], b[3]);
        }
    }
    __syncthreads();

    // epilogue P3: Ct = acc3 + b2 + xln residual
#pragma unroll
    for (int mt = 0; mt < 2; mt++)
#pragma unroll
        for (int nt = 0; nt < 8; nt++) {
            int rl = mw * 32 + mt * 16 + g;
            int cc = nw * 64 + nt * 8 + 2 * t;
            float b0 = p.b2[cc], b1v = p.b2[cc + 1];
            unsigned c2 = (unsigned)(2 * cc);
            __half2 r0 = *(const __half2*)(smc + 68096 + rl * 256
                                           + (c2 ^ (unsigned)((rl & 7) << 4)));
            __half2 r1 = *(const __half2*)(smc + 68096 + (rl + 8) * 256
                                           + (c2 ^ (unsigned)(((rl + 8) & 7) << 4)));
            float2 f0 = __half22float2(r0);
            float2 f1 = __half22float2(r1);
            Ct[rl * 133 + cc]           = acc3[mt][nt][0] + b0 + f0.x;
            Ct[rl * 133 + cc + 1]       = acc3[mt][nt][1] + b1v + f0.y;
            Ct[(rl + 8) * 133 + cc]     = acc3[mt][nt][2] + b0 + f1.x;
            Ct[(rl + 8) * 133 + cc + 1] = acc3[mt][nt][3] + b1v + f1.y;
        }
    __syncthreads();

    // LN2 (in place in Ct)
    for (int r = w; r < 128; r += 8) {
        float v[4], s = 0.f, s2 = 0.f;
#pragma unroll
        for (int k = 0; k < 4; k++) {
            v[k] = Ct[r * 133 + lane + 32 * k];
            s += v[k]; s2 += v[k] * v[k];
        }
        for (int off = 16; off; off >>= 1) {
            s  += __shfl_xor_sync(0xffffffffu, s,  off);
            s2 += __shfl_xor_sync(0xffffffffu, s2, off);
        }
        float m   = s * (1.f / 128.f);
        float var = s2 * (1.f / 128.f) - m * m;
        float rs  = rsqrtf(var + 1e-5f);
#pragma unroll
        for (int k = 0; k < 4; k++) {
            int cc = lane + 32 * k;
            Ct[r * 133 + cc] = (v[k] - m) * rs * p.lng[cc] + p.lnb[cc];
        }
    }
    __syncthreads();

    // transposed fp32 store to (B,C,X,Y,Z)
    int  bi  = (int)(m0 / SS);
    long sp0 = m0 % SS;
    float* outp = p.out + (size_t)bi * 128 * SS + sp0;
    for (int e = tid; e < 128 * 128; e += 256) {
        int cc = e >> 7, ss = e & 127;
        outp[(size_t)cc * SS + ss] = Ct[ss * 133 + cc];
    }
}

// ---------------------------------------------------------------------------
// launch
// ---------------------------------------------------------------------------
extern "C" void kernel_launch(void* const* d_in, const int* in_sizes, int n_in,
                              void* d_out, int out_size)
{
    (void)in_sizes; (void)n_in; (void)out_size;
    const float* x    = (const float*)d_in[0];
    const float* px   = (const float*)d_in[1];
    const float* py   = (const float*)d_in[2];
    const float* pz   = (const float*)d_in[3];

    cudaFuncSetAttribute((const void*)attn2_kernel,
                         cudaFuncAttributeMaxDynamicSharedMemorySize, ATTN2_SMEM);
    cudaFuncSetAttribute((const void*)fuse_kernel,
                         cudaFuncAttributeMaxDynamicSharedMemorySize, FUSE_SMEM);

    WP wp;
    for (int a = 0; a < 3; a++) {
        wp.wq[a]   = (const float*)d_in[4 + 4 * a];
        wp.wkv[a]  = (const float*)d_in[5 + 4 * a];
        wp.wout[a] = (const float*)d_in[6 + 4 * a];
    }
    wp.w1 = (const float*)d_in[18];
    wp.w2 = (const float*)d_in[20];
    wconv_kernel<<<896, 256>>>(wp);

    prep_kernel<<<NT / 64, 256>>>(x, px, py, pz);

    attn2_kernel<<<dim3(576, 3), 256, ATTN2_SMEM>>>();

    FP fp;
    fp.bo0 = (const float*)d_in[7];
    fp.bo1 = (const float*)d_in[11];
    fp.bo2 = (const float*)d_in[15];
    fp.b1  = (const float*)d_in[19];
    fp.b2  = (const float*)d_in[21];
    fp.lng = (const float*)d_in[16];
    fp.lnb = (const float*)d_in[17];
    fp.out = (float*)d_out;
    fuse_kernel<<<NT / 128, 256, FUSE_SMEM>>>(fp);
}

// round 9
// speedup vs baseline: 15.2324x; 1.0738x over previous
#include <cuda_runtime.h>
#include <cuda_fp16.h>

// Problem constants
#define SS   110592          // 48^3
#define NT   221184          // NB*SS tokens

// Scratch (device globals; no allocation allowed) — all intermediates fp16
__device__ __half g_xe [NT * 128];            // pos-embedded input (residual 1)
__device__ __half g_o  [(size_t)NT * 384];    // attention outputs, 3 axes
// fp16 weights: [0,147456) qkv blocks (3 axes x [384][128]), [147456,196608)
// wout_cat (128 rows x 384), [196608,212992) w1, [212992,229376) w2
__device__ __half g_wh [229376];

// ---------------------------------------------------------------------------
// helpers
// ---------------------------------------------------------------------------
__device__ __forceinline__ void cpa16_s(unsigned d, const void* s) {
    asm volatile("cp.async.cg.shared.global [%0], [%1], 16;" :: "r"(d), "l"(s));
}
#define CP_COMMIT() asm volatile("cp.async.commit_group;")
#define CP_WAIT1()  asm volatile("cp.async.wait_group 1;")
#define CP_WAIT0()  asm volatile("cp.async.wait_group 0;")

#define LDSM4(r, addr) \
    asm volatile("ldmatrix.sync.aligned.m8n8.x4.shared.b16 {%0,%1,%2,%3}, [%4];" \
        : "=r"((r)[0]), "=r"((r)[1]), "=r"((r)[2]), "=r"((r)[3]) : "r"(addr))

#define LDSM4T(r, addr) \
    asm volatile("ldmatrix.sync.aligned.m8n8.x4.trans.shared.b16 {%0,%1,%2,%3}, [%4];" \
        : "=r"((r)[0]), "=r"((r)[1]), "=r"((r)[2]), "=r"((r)[3]) : "r"(addr))

#define MMA16(d, a, b0, b1) \
    asm volatile("mma.sync.aligned.m16n8k16.row.col.f32.f16.f16.f32 " \
        "{%0,%1,%2,%3}, {%4,%5,%6,%7}, {%8,%9}, {%0,%1,%2,%3};" \
        : "+f"((d)[0]), "+f"((d)[1]), "+f"((d)[2]), "+f"((d)[3]) \
        : "r"((a)[0]), "r"((a)[1]), "r"((a)[2]), "r"((a)[3]), \
          "r"(b0), "r"(b1))

#define NBAR(id) asm volatile("bar.sync %0, 256;" :: "r"(id) : "memory")

__device__ __forceinline__ unsigned h2u(float x, float y) {
    __half2 h = __floats2half2_rn(x, y);
    return *(unsigned*)&h;
}

// ---------------------------------------------------------------------------
// weight convert: fp32 -> fp16 buffer, one-time layout
// ---------------------------------------------------------------------------
struct WP {
    const float* wq[3]; const float* wkv[3]; const float* wout[3];
    const float* w1; const float* w2;
};
__global__ __launch_bounds__(256) void wconv_kernel(WP p)
{
    int idx = blockIdx.x * 256 + threadIdx.x;
    if (idx >= 229376) return;
    float v;
    if (idx < 147456) {
        int strip = idx >> 14, rem = idx & 16383;
        int a = strip / 3, r = strip - a * 3;
        v = (r == 0) ? p.wq[a][rem] : p.wkv[a][(r - 1) * 16384 + rem];
    } else if (idx < 196608) {
        int rem = idx - 147456;
        int n = rem / 384, k = rem - n * 384;
        v = p.wout[k >> 7][n * 128 + (k & 127)];
    } else if (idx < 212992) v = p.w1[idx - 196608];
    else                     v = p.w2[idx - 212992];
    g_wh[idx] = __float2half(v);
}

// ---------------------------------------------------------------------------
// prep: xe = 2*x + px + py + pz, transpose (B,C,S) -> (token, C), fp16
// ---------------------------------------------------------------------------
__global__ __launch_bounds__(256) void prep_kernel(
    const float* __restrict__ x,  const float* __restrict__ px,
    const float* __restrict__ py, const float* __restrict__ pz)
{
    __shared__ float tile[64][129];
    int base = blockIdx.x * 64;
    int b    = base / SS;
    int sp0  = base % SS;

    for (int e = threadIdx.x; e < 64 * 128; e += 256) {
        int c = e >> 6;
        int s = e & 63;
        int spatial = sp0 + s;
        int zi = spatial % 48;
        int yi = (spatial / 48) % 48;
        int xi = spatial / 2304;
        tile[s][c] = 2.0f * x[(size_t)b * 128 * SS + (size_t)c * SS + spatial]
                   + px[c * 48 + xi] + py[c * 48 + yi] + pz[c * 48 + zi];
    }
    __syncthreads();
    for (int e = threadIdx.x; e < 64 * 128; e += 256) {
        int s = e >> 7;
        int c = e & 127;
        g_xe[(size_t)(base + s) * 128 + c] = __float2half(tile[s][c]);
    }
}

// ---------------------------------------------------------------------------
// fused QKV + attention v3: grid (288, 3 axes); 512 threads = 2 warp-groups.
// Each group processes 8 interleaved sequences with private A (2x12KB) and
// KV (36KB) buffers; both share the axis weight tile W (96KB). Warp = head:
// warp h computes its head's q/k/v columns; Q stays in registers (C-frag ->
// A-frag repack), K/V go to warp-private smem. Group sync via named barriers.
// ---------------------------------------------------------------------------
#define ATTN3_SMEM 221184
#define EXP2_SCALE 0.36067376022224085f   // 0.25 * log2(e)

__global__ __launch_bounds__(512, 1) void attn3_kernel()
{
    extern __shared__ __align__(16) char smc[];
    unsigned sbase = (unsigned)__cvta_generic_to_shared(smc);
    const unsigned sW = sbase;

    int tid  = threadIdx.x;
    int gid  = tid >> 8;           // warp-group 0/1
    int gtid = tid & 255;
    int lane = tid & 31;
    int h    = (gtid >> 5);        // warp in group = head
    int g    = lane >> 2, t = lane & 3;

    unsigned gA  = sbase + 98304 + (unsigned)gid * 61440;  // 2 x 12288
    unsigned gKV = gA + 24576;                             // 36864 (K,V)
    char*   KVc  = smc + 98304 + gid * 61440 + 24576;
    __half* Os   = (__half*)KVc;                           // aliases KV

    int axis = blockIdx.y;
    int stride = (axis == 0) ? 2304 : (axis == 1 ? 48 : 1);

    // ---- stage W (384 rows x 256B swizzled), all 512 threads ----
    const __half* Wsrc = g_wh + (size_t)axis * 49152;
#pragma unroll
    for (int i = 0; i < 12; i++) {
        int idx = tid + i * 512;
        int row = idx >> 4, seg = idx & 15;
        cpa16_s(sW + row * 256 + (unsigned)((seg * 16) ^ ((row & 7) << 4)),
                Wsrc + (size_t)row * 128 + seg * 8);
    }
    CP_COMMIT();

#define BASE_OF(sq, bs) do {                                                  \
        int b_ = (sq) / 2304, rr_ = (sq) % 2304;                              \
        int o1_ = rr_ / 48, o2_ = rr_ % 48;                                   \
        if (axis == 0)      bs = (long)b_ * SS + o1_ * 48 + o2_;              \
        else if (axis == 1) bs = (long)b_ * SS + o1_ * 2304 + o2_;            \
        else                bs = (long)b_ * SS + o1_ * 2304 + (long)o2_ * 48; \
    } while (0)

#define STAGE_A(bs, buf) do {                                                 \
        _Pragma("unroll")                                                     \
        for (int it_ = 0; it_ < 3; it_++) {                                   \
            int idx_ = gtid + it_ * 256;                                      \
            int row_ = idx_ >> 4, seg_ = idx_ & 15;                           \
            cpa16_s(gA + (buf) * 12288 + row_ * 256                           \
                    + (unsigned)((seg_ * 16) ^ ((row_ & 7) << 4)),            \
                    g_xe + (size_t)((bs) + (long)row_ * stride) * 128         \
                    + seg_ * 8);                                              \
        }                                                                     \
    } while (0)

    int seqbase = blockIdx.x * 16 + gid;     // group's seqs: +2 per step
    { long bs0; BASE_OF(seqbase, bs0); STAGE_A(bs0, 0); }
    CP_COMMIT();
    CP_WAIT1();          // W complete (A0 still in flight)
    __syncthreads();     // W visible CTA-wide

    // fragment addressing constants
    unsigned hiA = (unsigned)((lane >> 4) << 4);
    unsigned xA  = (unsigned)((lane & 7) << 4);
    int raL  = lane & 15;
    int rbL  = ((lane & 16) >> 1) + (lane & 7);
    unsigned hiB = (unsigned)(((lane >> 3) & 1) << 4);
    unsigned xB  = (unsigned)((lane & 7) << 4);
    int barid = gid + 1;

    for (int i = 0; i < 8; i++) {
        long bs; BASE_OF(seqbase + 2 * i, bs);
        if (i + 1 < 8) {
            long bn; BASE_OF(seqbase + 2 * (i + 1), bn);
            STAGE_A(bn, (i + 1) & 1);
            CP_COMMIT(); CP_WAIT1();
        } else {
            CP_WAIT0();
        }
        NBAR(barid);     // A(i) visible group-wide; prior seq fully done

        // ---- GEMM: warp computes its head's q|k|v (48 cols), M=48, K=128 --
        unsigned sAc = gA + (unsigned)((i & 1) * 12288);
        float acc[3][6][4];
#pragma unroll
        for (int mt = 0; mt < 3; mt++)
#pragma unroll
            for (int nt = 0; nt < 6; nt++)
#pragma unroll
                for (int q = 0; q < 4; q++) acc[mt][nt][q] = 0.f;

#pragma unroll
        for (int kt = 0; kt < 8; kt++) {
            unsigned a[3][4];
#pragma unroll
            for (int mt = 0; mt < 3; mt++)
                LDSM4(a[mt], sAc + (unsigned)((mt * 16 + raL) * 256)
                             + (((unsigned)(kt * 32) + hiA) ^ xA));
#pragma unroll
            for (int np = 0; np < 3; np++) {
                int rowb = np * 128 + h * 16 + rbL;
                unsigned b[4];
                LDSM4(b, sW + (unsigned)(rowb * 256)
                         + (((unsigned)(kt * 32) + hiB) ^ xB));
#pragma unroll
                for (int mt = 0; mt < 3; mt++) {
                    MMA16(acc[mt][2 * np],     a[mt], b[0], b[1]);
                    MMA16(acc[mt][2 * np + 1], a[mt], b[2], b[3]);
                }
            }
        }

        // ---- Q: C-frag -> A-frag repack (registers only) ----
        unsigned qf[3][4];
#pragma unroll
        for (int mt = 0; mt < 3; mt++) {
            qf[mt][0] = h2u(acc[mt][0][0], acc[mt][0][1]);
            qf[mt][1] = h2u(acc[mt][0][2], acc[mt][0][3]);
            qf[mt][2] = h2u(acc[mt][1][0], acc[mt][1][1]);
            qf[mt][3] = h2u(acc[mt][1][2], acc[mt][1][3]);
        }
        // ---- K,V -> warp-private smem (48B rows) ----
#pragma unroll
        for (int np = 1; np < 3; np++)
#pragma unroll
            for (int nts = 0; nts < 2; nts++) {
                int nt = np * 2 + nts;
                char* dst = KVc + (np - 1) * 18432 + h * 2304
                          + (nts * 8 + 2 * t) * 2;
#pragma unroll
                for (int mt = 0; mt < 3; mt++) {
                    int r0 = mt * 16 + g;
                    *(__half2*)(dst + r0 * 48) =
                        __floats2half2_rn(acc[mt][nt][0], acc[mt][nt][1]);
                    *(__half2*)(dst + (r0 + 8) * 48) =
                        __floats2half2_rn(acc[mt][nt][2], acc[mt][nt][3]);
                }
            }
        __syncwarp();

        // ---- scores S = Q @ K^T ----
        unsigned Kb = gKV + (unsigned)(h * 2304);
        unsigned Vb = Kb + 18432u;
        float s[3][6][4];
#pragma unroll
        for (int mt = 0; mt < 3; mt++)
#pragma unroll
            for (int nt = 0; nt < 6; nt++)
#pragma unroll
                for (int q = 0; q < 4; q++) s[mt][nt][q] = 0.f;
#pragma unroll
        for (int nt2 = 0; nt2 < 3; nt2++) {
            unsigned bb[4];
            LDSM4(bb, Kb + (unsigned)((nt2 * 16 + rbL) * 48) + hiB);
#pragma unroll
            for (int mt = 0; mt < 3; mt++) {
                MMA16(s[mt][2 * nt2],     qf[mt], bb[0], bb[1]);
                MMA16(s[mt][2 * nt2 + 1], qf[mt], bb[2], bb[3]);
            }
        }

        // ---- max-free softmax, norm deferred to O ----
        float inv[3][2];
#pragma unroll
        for (int mt = 0; mt < 3; mt++)
#pragma unroll
            for (int hi = 0; hi < 2; hi++) {
                float sum = 0.f;
#pragma unroll
                for (int nt = 0; nt < 6; nt++)
#pragma unroll
                    for (int lo = 0; lo < 2; lo++) {
                        float e = exp2f(s[mt][nt][hi * 2 + lo] * EXP2_SCALE);
                        s[mt][nt][hi * 2 + lo] = e;
                        sum += e;
                    }
                sum += __shfl_xor_sync(0xffffffffu, sum, 1);
                sum += __shfl_xor_sync(0xffffffffu, sum, 2);
                inv[mt][hi] = 1.f / sum;
            }

        // ---- O = P_unnorm @ V ----
        float o[3][2][4];
#pragma unroll
        for (int mt = 0; mt < 3; mt++)
#pragma unroll
            for (int nt = 0; nt < 2; nt++)
#pragma unroll
                for (int q = 0; q < 4; q++) o[mt][nt][q] = 0.f;
#pragma unroll
        for (int kt = 0; kt < 3; kt++) {
            unsigned vb[4];
            LDSM4T(vb, Vb + (unsigned)((kt * 16 + raL) * 48) + hiA);
            unsigned pa[3][4];
#pragma unroll
            for (int mt = 0; mt < 3; mt++) {
                pa[mt][0] = h2u(s[mt][2 * kt][0],     s[mt][2 * kt][1]);
                pa[mt][1] = h2u(s[mt][2 * kt][2],     s[mt][2 * kt][3]);
                pa[mt][2] = h2u(s[mt][2 * kt + 1][0], s[mt][2 * kt + 1][1]);
                pa[mt][3] = h2u(s[mt][2 * kt + 1][2], s[mt][2 * kt + 1][3]);
            }
#pragma unroll
            for (int mt = 0; mt < 3; mt++) {
                MMA16(o[mt][0], pa[mt], vb[0], vb[1]);
                MMA16(o[mt][1], pa[mt], vb[2], vb[3]);
            }
        }

        NBAR(barid);   // all group warps done reading K/V (Os aliases KV)

        // ---- normalize O, stage, coalesced group store ----
#pragma unroll
        for (int mt = 0; mt < 3; mt++)
#pragma unroll
            for (int nt = 0; nt < 2; nt++) {
                int col = h * 16 + nt * 8 + 2 * t;
                int r0 = mt * 16 + g;
                *(__half2*)(Os + r0 * 136 + col) =
                    __floats2half2_rn(o[mt][nt][0] * inv[mt][0],
                                      o[mt][nt][1] * inv[mt][0]);
                *(__half2*)(Os + (r0 + 8) * 136 + col) =
                    __floats2half2_rn(o[mt][nt][2] * inv[mt][1],
                                      o[mt][nt][3] * inv[mt][1]);
            }
        NBAR(barid);

#pragma unroll
        for (int it = 0; it < 3; it++) {
            int idx = gtid + it * 256;
            int row = idx >> 4, c = idx & 15;
            *(uint4*)(g_o + (size_t)(bs + (long)row * stride) * 384
                      + axis * 128 + c * 8) = *(const uint4*)(Os + row * 136 + c * 8);
        }
    }
#undef BASE_OF
#undef STAGE_A
}

// ---------------------------------------------------------------------------
// fused tail: outproj(+bias3+res(g_xe)) -> LN1 -> mlp1(relu) -> mlp2(+res)
// -> LN2 -> transposed fp32 store. Intermediates never touch DRAM.
// ---------------------------------------------------------------------------
#define FUSE_SMEM 100864

struct FP {
    const float *bo0, *bo1, *bo2, *b1, *b2, *lng, *lnb;
    float* out;
};

__global__ __launch_bounds__(256, 2) void fuse_kernel(FP p)
{
    extern __shared__ __align__(16) char smc[];
    unsigned sR = (unsigned)__cvta_generic_to_shared(smc);
    unsigned sX = sR + 68096;
    float* Ct = (float*)smc;

    int tid = threadIdx.x, w = tid >> 5, lane = tid & 31;
    int mw = w & 3, nw = w >> 2;
    int g = lane >> 2, t = lane & 3;
    long m0 = (long)blockIdx.x * 128;

    int rowA  = mw * 32 + (lane & 15);
    int rowB0 = nw * 64 + ((lane & 16) >> 1) + (lane & 7);
    unsigned hiA = (unsigned)((lane >> 4) << 4);
    unsigned hiB = (unsigned)(((lane >> 3) & 1) << 4);
    unsigned xA = (unsigned)((rowA & 7) << 4);
    unsigned xB = (unsigned)((rowB0 & 7) << 4);

    // ================= P1: outproj, A=g_o (lda 384), B=wout_cat, K=384 ======
    float acc[2][8][4];
#pragma unroll
    for (int mt = 0; mt < 2; mt++)
#pragma unroll
        for (int nt = 0; nt < 8; nt++)
#pragma unroll
            for (int i = 0; i < 4; i++) acc[mt][nt][i] = 0.f;
    {
        unsigned sA = sR, sB = sR + 32768;
        const __half* Ap = g_o;
        const __half* Bp = g_wh + 147456;

#define STAGE1(c, buf) do {                                                   \
        int k0_ = (c) * 64;                                                   \
        _Pragma("unroll")                                                     \
        for (int i_ = 0; i_ < 4; i_++) {                                      \
            int idx_ = tid + 256 * i_;                                        \
            int row_ = idx_ >> 3, seg_ = idx_ & 7;                            \
            unsigned dcol_ = (unsigned)((seg_ * 16) ^ ((row_ & 7) << 4));     \
            cpa16_s(sA + (buf) * 16384 + row_ * 128 + dcol_,                  \
                    Ap + (m0 + row_) * 384 + k0_ + seg_ * 8);                 \
            cpa16_s(sB + (buf) * 16384 + row_ * 128 + dcol_,                  \
                    Bp + (size_t)row_ * 384 + k0_ + seg_ * 8);                \
        }                                                                     \
    } while (0)

        STAGE1(0, 0); CP_COMMIT();
        for (int c = 0; c < 6; c++) {
            if (c + 1 < 6) { STAGE1(c + 1, (c + 1) & 1); CP_COMMIT(); CP_WAIT1(); }
            else           { CP_WAIT0(); }
            __syncthreads();
            unsigned baseA = sA + (c & 1) * 16384;
            unsigned baseB = sB + (c & 1) * 16384;
#pragma unroll
            for (int kt = 0; kt < 4; kt++) {
                unsigned a[2][4];
#pragma unroll
                for (int mt = 0; mt < 2; mt++)
                    LDSM4(a[mt], baseA + (rowA + mt * 16) * 128
                                 + (((unsigned)(kt * 32) + hiA) ^ xA));
#pragma unroll
                for (int np = 0; np < 4; np++) {
                    unsigned b[4];
                    LDSM4(b, baseB + (rowB0 + np * 16) * 128
                             + (((unsigned)(kt * 32) + hiB) ^ xB));
                    MMA16(acc[0][2 * np],     a[0], b[0], b[1]);
                    MMA16(acc[1][2 * np],     a[1], b[0], b[1]);
                    MMA16(acc[0][2 * np + 1], a[0], b[2], b[3]);
                    MMA16(acc[1][2 * np + 1], a[1], b[2], b[3]);
                }
            }
            __syncthreads();
        }
#undef STAGE1
    }

    // epilogue P1: Ct = acc + (bo0+bo1+bo2) + g_xe residual
#pragma unroll
    for (int mt = 0; mt < 2; mt++)
#pragma unroll
        for (int nt = 0; nt < 8; nt++) {
            int rl = mw * 32 + mt * 16 + g;
            int cc = nw * 64 + nt * 8 + 2 * t;
            size_t tok = m0 + rl;
            float b0 = p.bo0[cc] + p.bo1[cc] + p.bo2[cc];
            float b1v = p.bo0[cc + 1] + p.bo1[cc + 1] + p.bo2[cc + 1];
            Ct[rl * 133 + cc]     = acc[mt][nt][0] + b0 + __half2float(g_xe[tok * 128 + cc]);
            Ct[rl * 133 + cc + 1] = acc[mt][nt][1] + b1v + __half2float(g_xe[tok * 128 + cc + 1]);
            Ct[(rl + 8) * 133 + cc]     = acc[mt][nt][2] + b0 + __half2float(g_xe[(tok + 8) * 128 + cc]);
            Ct[(rl + 8) * 133 + cc + 1] = acc[mt][nt][3] + b1v + __half2float(g_xe[(tok + 8) * 128 + cc + 1]);
        }
    __syncthreads();

    // LN1 -> xln (fp16 swizzled tile, row stride 256B)
    for (int r = w; r < 128; r += 8) {
        float v[4], s = 0.f, s2 = 0.f;
#pragma unroll
        for (int k = 0; k < 4; k++) {
            v[k] = Ct[r * 133 + lane + 32 * k];
            s += v[k]; s2 += v[k] * v[k];
        }
        for (int off = 16; off; off >>= 1) {
            s  += __shfl_xor_sync(0xffffffffu, s,  off);
            s2 += __shfl_xor_sync(0xffffffffu, s2, off);
        }
        float m   = s * (1.f / 128.f);
        float var = s2 * (1.f / 128.f) - m * m;
        float rs  = rsqrtf(var + 1e-5f);
        unsigned rxor = (unsigned)((r & 7) << 4);
#pragma unroll
        for (int k = 0; k < 4; k++) {
            int cc = lane + 32 * k;
            float y = (v[k] - m) * rs * p.lng[cc] + p.lnb[cc];
            *(__half*)(smc + 68096 + r * 256 + ((unsigned)(2 * cc) ^ rxor)) =
                __float2half(y);
        }
    }
    __syncthreads();

    // ================= stage w1 -> R1[0,32K), w2 -> R1[32K,64K) =============
    {
        const __half* w1p = g_wh + 196608;
        const __half* w2p = g_wh + 212992;
#pragma unroll
        for (int i = 0; i < 8; i++) {
            int idx = tid + i * 256;
            int row = idx >> 4, seg = idx & 15;
            unsigned dcol = (unsigned)((seg * 16) ^ ((row & 7) << 4));
            cpa16_s(sR + row * 256 + dcol, w1p + row * 128 + seg * 8);
            cpa16_s(sR + 32768 + row * 256 + dcol, w2p + row * 128 + seg * 8);
        }
        CP_COMMIT(); CP_WAIT0();
        __syncthreads();
    }

    // ================= P2: h = relu(xln @ w1^T + b1), K=128 =================
    float acc2[2][8][4];
#pragma unroll
    for (int mt = 0; mt < 2; mt++)
#pragma unroll
        for (int nt = 0; nt < 8; nt++)
#pragma unroll
            for (int i = 0; i < 4; i++) acc2[mt][nt][i] = 0.f;

#pragma unroll
    for (int kt = 0; kt < 8; kt++) {
        unsigned a[2][4];
#pragma unroll
        for (int mt = 0; mt < 2; mt++)
            LDSM4(a[mt], sX + (rowA + mt * 16) * 256
                         + (((unsigned)(kt * 32) + hiA) ^ xA));
#pragma unroll
        for (int np = 0; np < 4; np++) {
            unsigned b[4];
            LDSM4(b, sR + (rowB0 + np * 16) * 256
                     + (((unsigned)(kt * 32) + hiB) ^ xB));
            MMA16(acc2[0][2 * np],     a[0], b[0], b[1]);
            MMA16(acc2[1][2 * np],     a[1], b[0], b[1]);
            MMA16(acc2[0][2 * np + 1], a[0], b[2], b[3]);
            MMA16(acc2[1][2 * np + 1], a[1], b[2], b[3]);
        }
    }
    __syncthreads();

    // h tile (fp16 swizzled, row 256B) at R1[0,32K)
#pragma unroll
    for (int mt = 0; mt < 2; mt++)
#pragma unroll
        for (int nt = 0; nt < 8; nt++) {
            int rl = mw * 32 + mt * 16 + g;
            int cc = nw * 64 + nt * 8 + 2 * t;
            float b0 = p.b1[cc], b1v = p.b1[cc + 1];
            unsigned c2 = (unsigned)(2 * cc);
            *(__half2*)(smc + rl * 256 + (c2 ^ (unsigned)((rl & 7) << 4))) =
                __floats2half2_rn(fmaxf(acc2[mt][nt][0] + b0, 0.f),
                                  fmaxf(acc2[mt][nt][1] + b1v, 0.f));
            *(__half2*)(smc + (rl + 8) * 256 + (c2 ^ (unsigned)(((rl + 8) & 7) << 4))) =
                __floats2half2_rn(fmaxf(acc2[mt][nt][2] + b0, 0.f),
                                  fmaxf(acc2[mt][nt][3] + b1v, 0.f));
        }
    __syncthreads();

    // ================= P3: y = h @ w2^T + b2 + xln, K=128 ===================
    float acc3[2][8][4];
#pragma unroll
    for (int mt = 0; mt < 2; mt++)
#pragma unroll
        for (int nt = 0; nt < 8; nt++)
#pragma unroll
            for (int i = 0; i < 4; i++) acc3[mt][nt][i] = 0.f;

#pragma unroll
    for (int kt = 0; kt < 8; kt++) {
        unsigned a[2][4];
#pragma unroll
        for (int mt = 0; mt < 2; mt++)
            LDSM4(a[mt], sR + (rowA + mt * 16) * 256
                         + (((unsigned)(kt * 32) + hiA) ^ xA));
#pragma unroll
        for (int np = 0; np < 4; np++) {
            unsigned b[4];
            LDSM4(b, sR + 32768 + (rowB0 + np * 16) * 256
                     + (((unsigned)(kt * 32) + hiB) ^ xB));
            MMA16(acc3[0][2 * np],     a[0], b[0], b[1]);
            MMA16(acc3[1][2 * np],     a[1], b[0], b[1]);
            MMA16(acc3[0][2 * np + 1], a[0], b[2], b[3]);
            MMA16(acc3[1][2 * np + 1], a[1], b[2], b[3]);
        }
    }
    __syncthreads();

    // epilogue P3: Ct = acc3 + b2 + xln residual
#pragma unroll
    for (int mt = 0; mt < 2; mt++)
#pragma unroll
        for (int nt = 0; nt < 8; nt++) {
            int rl = mw * 32 + mt * 16 + g;
            int cc = nw * 64 + nt * 8 + 2 * t;
            float b0 = p.b2[cc], b1v = p.b2[cc + 1];
            unsigned c2 = (unsigned)(2 * cc);
            __half2 r0 = *(const __half2*)(smc + 68096 + rl * 256
                                           + (c2 ^ (unsigned)((rl & 7) << 4)));
            __half2 r1 = *(const __half2*)(smc + 68096 + (rl + 8) * 256
                                           + (c2 ^ (unsigned)(((rl + 8) & 7) << 4)));
            float2 f0 = __half22float2(r0);
            float2 f1 = __half22float2(r1);
            Ct[rl * 133 + cc]           = acc3[mt][nt][0] + b0 + f0.x;
            Ct[rl * 133 + cc + 1]       = acc3[mt][nt][1] + b1v + f0.y;
            Ct[(rl + 8) * 133 + cc]     = acc3[mt][nt][2] + b0 + f1.x;
            Ct[(rl + 8) * 133 + cc + 1] = acc3[mt][nt][3] + b1v + f1.y;
        }
    __syncthreads();

    // LN2 (in place in Ct)
    for (int r = w; r < 128; r += 8) {
        float v[4], s = 0.f, s2 = 0.f;
#pragma unroll
        for (int k = 0; k < 4; k++) {
            v[k] = Ct[r * 133 + lane + 32 * k];
            s += v[k]; s2 += v[k] * v[k];
        }
        for (int off = 16; off; off >>= 1) {
            s  += __shfl_xor_sync(0xffffffffu, s,  off);
            s2 += __shfl_xor_sync(0xffffffffu, s2, off);
        }
        float m   = s * (1.f / 128.f);
        float var = s2 * (1.f / 128.f) - m * m;
        float rs  = rsqrtf(var + 1e-5f);
#pragma unroll
        for (int k = 0; k < 4; k++) {
            int cc = lane + 32 * k;
            Ct[r * 133 + cc] = (v[k] - m) * rs * p.lng[cc] + p.lnb[cc];
        }
    }
    __syncthreads();

    // transposed fp32 store to (B,C,X,Y,Z)
    int  bi  = (int)(m0 / SS);
    long sp0 = m0 % SS;
    float* outp = p.out + (size_t)bi * 128 * SS + sp0;
    for (int e = tid; e < 128 * 128; e += 256) {
        int cc = e >> 7, ss = e & 127;
        outp[(size_t)cc * SS + ss] = Ct[ss * 133 + cc];
    }
}

// ---------------------------------------------------------------------------
// launch
// ---------------------------------------------------------------------------
extern "C" void kernel_launch(void* const* d_in, const int* in_sizes, int n_in,
                              void* d_out, int out_size)
{
    (void)in_sizes; (void)n_in; (void)out_size;
    const float* x    = (const float*)d_in[0];
    const float* px   = (const float*)d_in[1];
    const float* py   = (const float*)d_in[2];
    const float* pz   = (const float*)d_in[3];

    cudaFuncSetAttribute((const void*)attn3_kernel,
                         cudaFuncAttributeMaxDynamicSharedMemorySize, ATTN3_SMEM);
    cudaFuncSetAttribute((const void*)fuse_kernel,
                         cudaFuncAttributeMaxDynamicSharedMemorySize, FUSE_SMEM);

    WP wp;
    for (int a = 0; a < 3; a++) {
        wp.wq[a]   = (const float*)d_in[4 + 4 * a];
        wp.wkv[a]  = (const float*)d_in[5 + 4 * a];
        wp.wout[a] = (const float*)d_in[6 + 4 * a];
    }
    wp.w1 = (const float*)d_in[18];
    wp.w2 = (const float*)d_in[20];
    wconv_kernel<<<896, 256>>>(wp);

    prep_kernel<<<NT / 64, 256>>>(x, px, py, pz);

    attn3_kernel<<<dim3(288, 3), 512, ATTN3_SMEM>>>();

    FP fp;
    fp.bo0 = (const float*)d_in[7];
    fp.bo1 = (const float*)d_in[11];
    fp.bo2 = (const float*)d_in[15];
    fp.b1  = (const float*)d_in[19];
    fp.b2  = (const float*)d_in[21];
    fp.lng = (const float*)d_in[16];
    fp.lnb = (const float*)d_in[17];
    fp.out = (float*)d_out;
    fuse_kernel<<<NT / 128, 256, FUSE_SMEM>>>(fp);
}